// round 11
// baseline (speedup 1.0000x reference)
#include <cuda_runtime.h>
#include <cuda_fp16.h>
#include <math.h>

// Problem constants
#define BB 8
#define TT 10
#define HH 64
#define WW 64
#define HWP 4096           // H*W
#define FF 64
#define NCH 256            // 4*F
#define M_TOTAL (BB*HWP)   // 32768
#define M_BIG   (BB*TT*HWP) // 327680

// Planar halo layout: 2-pixel border on each side
#define HR 68
#define PLANE (HR*HR)      // 4624 per channel plane

// K chunk = 32 fp32 channels -> 64 fp16 cols in A (ah|al), 32 fp16 in B (bh)
#define NC1X 25            // layer1 x-part:  K=800  (25 taps x 32ch) /32
#define NC1H 50            // layer1 h-part:  K=1600 (25 x 64) /32
#define NC2  18            // layer2 x/h:     K=576  (9 x 64) /32

#define SM_BIG   49152     // big GEMM kernel: A[2][16K] + B[2][8K]
#define SM_FUSED 65536     // fused kernel:    A[2][16K] + B[2][16K]

// Scratch (static device globals; no allocation allowed)
// Activation planes are packed u32 = fp16(hi) | fp16(lo)<<16  (hi+lo == fp32 value)
__device__ float    g_zx[(long)M_BIG * NCH];           // precomputed W*x part
__device__ unsigned g_xp[(long)BB * TT * 32 * PLANE];  // x planar+halo, packed hi/lo
__device__ unsigned g_h1[(long)BB * TT * FF * PLANE];  // relu(h) seq layer1, packed
__device__ unsigned g_hA[(long)BB * FF * PLANE];       // hidden state ping
__device__ unsigned g_hB[(long)BB * FF * PLANE];       // hidden state pong
__device__ float    g_c[(long)BB * FF * HWP];          // cell state, planar fp32
__device__ __half g_B1x[(long)2 * NC1X * 4096];        // big-GEMM tiles [nb][kc]
__device__ __half g_B1h[(long)2 * NC1H * 4096];        // fused tiles   [kc][nb]
__device__ __half g_B2x[(long)2 * NC2 * 4096];
__device__ __half g_B2h[(long)2 * NC2 * 4096];

// ---------------------------------------------------------------------------
// Helpers (sm_80-baseline PTX only — harness targets family-generic sm_103)
// ---------------------------------------------------------------------------
__device__ __forceinline__ unsigned smem_u32(const void* p) {
    unsigned r;
    asm("{ .reg .u64 t; cvta.to.shared.u64 t, %1; cvt.u32.u64 %0, t; }"
        : "=r"(r) : "l"(p));
    return r;
}
__device__ __forceinline__ unsigned pack_hl(float f) {
    __half h = __float2half_rn(f);
    float r = f - __half2float(h);
    return (unsigned)__half_as_ushort(h)
         | ((unsigned)__half_as_ushort(__float2half_rn(r)) << 16);
}
__device__ __forceinline__ void ldsm4(unsigned* r, unsigned addr) {
    asm volatile("ldmatrix.sync.aligned.m8n8.x4.shared.b16 {%0,%1,%2,%3}, [%4];"
                 : "=r"(r[0]), "=r"(r[1]), "=r"(r[2]), "=r"(r[3]) : "r"(addr));
}
__device__ __forceinline__ void mma_f16(float* c, const unsigned* a,
                                        unsigned b0, unsigned b1) {
    asm volatile(
        "mma.sync.aligned.m16n8k16.row.col.f32.f16.f16.f32 "
        "{%0,%1,%2,%3}, {%4,%5,%6,%7}, {%8,%9}, {%0,%1,%2,%3};"
        : "+f"(c[0]), "+f"(c[1]), "+f"(c[2]), "+f"(c[3])
        : "r"(a[0]), "r"(a[1]), "r"(a[2]), "r"(a[3]), "r"(b0), "r"(b1));
}
#define CP_ASYNC16(dst, src) \
    asm volatile("cp.async.cg.shared.global [%0], [%1], 16;" \
                 :: "r"(dst), "l"(src))
#define CP_COMMIT() asm volatile("cp.async.commit_group;" ::: "memory")
#define CP_WAIT0()  asm volatile("cp.async.wait_group 0;" ::: "memory")

#define SWZ(off)   ((off) ^ (((off) >> 3) & 0x70))   // 128B-row swizzle (A)
#define SWZ64(off) ((off) ^ (((off) >> 3) & 0x30))   // 64B-row swizzle (B)

__device__ __forceinline__ float hsig(float v)
{
    return fminf(fmaxf(0.2f * v + 0.5f, 0.f), 1.f);
}

// ---------------------------------------------------------------------------
__global__ void zerok(float4* __restrict__ p, long n4)
{
    long stride = (long)gridDim.x * blockDim.x;
    for (long i = blockIdx.x * (long)blockDim.x + threadIdx.x; i < n4; i += stride)
        p[i] = make_float4(0.f, 0.f, 0.f, 0.f);
}
__global__ void zerok2(float4* __restrict__ p, float4* __restrict__ q, long n4)
{
    long stride = (long)gridDim.x * blockDim.x;
    for (long i = blockIdx.x * (long)blockDim.x + threadIdx.x; i < n4; i += stride) {
        p[i] = make_float4(0.f, 0.f, 0.f, 0.f);
        q[i] = make_float4(0.f, 0.f, 0.f, 0.f);
    }
}

// ---------------------------------------------------------------------------
// Prepack weights. W [kh,kw,Cin,256] -> 8KB tiles (128 N-rows x 32 fp16,
// 64B rows, SWZ64). Tile order: big GEMM = [nb][kc]; fused = [kc][nb].
// ---------------------------------------------------------------------------
__device__ __forceinline__ void prepack_one(long idx, const float* __restrict__ W,
                                            __half* __restrict__ Bp, int Cin,
                                            int nch, int fused)
{
    int j = (int)(idx & 31);
    long r = idx >> 5;
    int nrow = (int)(r & 127);
    r >>= 7;
    int kc = (int)(r % nch);
    int nb = (int)(r / nch);
    int k = kc * 32 + j;
    int pos = k / Cin, c = k % Cin;
    int n = nb * 128 + nrow;
    float w = W[((long)pos * Cin + c) * NCH + n];
    int inb = nrow * 64 + j * 2;
    int sw = SWZ64(inb);
    long tile = fused ? (long)(kc * 2 + nb) : (long)(nb * nch + kc);
    Bp[tile * 4096 + (sw >> 1)] = __float2half_rn(w);
}

__global__ void prepack_all(const float* __restrict__ W1, const float* __restrict__ U1,
                            const float* __restrict__ W2, const float* __restrict__ U2,
                            __half* __restrict__ B1x, __half* __restrict__ B1h,
                            __half* __restrict__ B2x, __half* __restrict__ B2h)
{
    long idx = blockIdx.x * 256L + threadIdx.x;
    if (idx < 204800)       prepack_one(idx,          W1, B1x, 32, NC1X, 0);
    else if (idx < 614400)  prepack_one(idx - 204800, U1, B1h, 64, NC1H, 1);
    else if (idx < 761856)  prepack_one(idx - 614400, W2, B2x, 64, NC2, 0);
    else if (idx < 909312)  prepack_one(idx - 761856, U2, B2h, 64, NC2, 1);
}

// ---------------------------------------------------------------------------
// Transpose x [b,t,pix,32] (NHWC fp32) -> xp [b,t,32,PLANE] packed hi/lo planes
// ---------------------------------------------------------------------------
__global__ void transpose_x(const float* __restrict__ x, unsigned* __restrict__ xp)
{
    long idx = blockIdx.x * (long)blockDim.x + threadIdx.x;
    if (idx >= (long)BB * TT * 32 * HWP) return;
    int pix = idx & 4095;
    long rest = idx >> 12;
    int ch = (int)(rest & 31);
    long bt = rest >> 5;
    float v = x[(bt * HWP + pix) * 32 + ch];
    int y = pix >> 6, xx = pix & 63;
    xp[(bt * 32 + ch) * PLANE + (y + 2) * HR + xx + 2] = pack_hl(v);
}

// ---------------------------------------------------------------------------
// Big-GEMM conv (input part, all timesteps at once). 256 threads,
// CTA 128m x 128n, 8 warps x (32m x 64n). fp16x2 split (ah*bh + al*bh).
// ---------------------------------------------------------------------------
template<int CIN, int KH, int NCHUNKS>
__global__ void __launch_bounds__(256, 2)
conv_big(const unsigned* __restrict__ src,
         const __half* __restrict__ Bpack,
         float* __restrict__ zout)
{
    extern __shared__ char smem[];
    const unsigned sb = smem_u32(smem);
    const int tid = threadIdx.x;
    const int lane = tid & 31, wid = tid >> 5;
    const int n_blk = blockIdx.x;          // 0..1
    const int m0 = blockIdx.y * 128;
    const int bt = m0 >> 12;
    const int y0 = (m0 & 4095) >> 6;
    constexpr int pad = KH >> 1;
    constexpr int HOFF = 2 - pad;

    const unsigned sA0 = sb, sB0 = sb + 32768;

    const int pix = tid & 127;
    const int g = tid >> 7;                // 0/1: channels g*16..g*16+15
    const int prow = (y0 + (pix >> 6)) * HR + (pix & 63);

    const int mw = wid & 3, nw = wid >> 2;
    int offA[2], offB[4];
#pragma unroll
    for (int mf = 0; mf < 2; mf++)
        offA[mf] = (mw * 32 + mf * 16 + (lane & 15)) * 128 + (lane >> 4) * 16;
#pragma unroll
    for (int nf2 = 0; nf2 < 4; nf2++)
        offB[nf2] = (nw * 64 + nf2 * 16 + (lane >> 4) * 8 + (lane & 7)) * 64
                  + ((lane >> 3) & 1) * 16;

    float acc[16][4];
#pragma unroll
    for (int i = 0; i < 16; i++)
#pragma unroll
        for (int j = 0; j < 4; j++) acc[i][j] = 0.f;

    unsigned a[16];

    auto prefA = [&](int kc) {
        int k0 = kc * 32;
        int pos = k0 / CIN;
        int cb = k0 - pos * CIN;
        int ky = pos / KH, kx = pos - ky * KH;
        const unsigned* s = src + ((long)bt * CIN + cb + g * 16) * PLANE
                          + prow + (ky + HOFF) * HR + kx + HOFF;
#pragma unroll
        for (int r = 0; r < 16; r++) a[r] = __ldg(s + (long)r * PLANE);
    };

    auto cpB = [&](int kc, int s) {
        const char* gsrc = (const char*)(Bpack + ((long)n_blk * NCHUNKS + kc) * 4096)
                         + tid * 16;
        unsigned dst = sB0 + s * 8192 + tid * 16;
        CP_ASYNC16(dst, gsrc);
        CP_ASYNC16(dst + 4096, gsrc + 4096);
    };

    auto stageA = [&](int s) {
        unsigned hw[8], lw[8];
#pragma unroll
        for (int j = 0; j < 8; j++) {
            hw[j] = __byte_perm(a[2 * j], a[2 * j + 1], 0x5410);
            lw[j] = __byte_perm(a[2 * j], a[2 * j + 1], 0x7632);
        }
        char* Ab = smem + s * 16384;
        int rb = pix * 128 + g * 32;
#pragma unroll
        for (int q = 0; q < 2; q++) {
            *(uint4*)(Ab + SWZ(rb + q * 16)) =
                make_uint4(hw[q * 4], hw[q * 4 + 1], hw[q * 4 + 2], hw[q * 4 + 3]);
            *(uint4*)(Ab + SWZ(rb + 64 + q * 16)) =
                make_uint4(lw[q * 4], lw[q * 4 + 1], lw[q * 4 + 2], lw[q * 4 + 3]);
        }
    };

    prefA(0);
    cpB(0, 0);
    CP_COMMIT();
    stageA(0);
    CP_WAIT0();
    __syncthreads();

    for (int kt = 0; kt < NCHUNKS; kt++) {
        const int cur = kt & 1;
        const bool more = (kt + 1 < NCHUNKS);
        if (more) {
            prefA(kt + 1);
            cpB(kt + 1, cur ^ 1);
            CP_COMMIT();
        }

        const unsigned a_base = sA0 + cur * 16384;
        const unsigned b_base = sB0 + cur * 8192;
#pragma unroll
        for (int ks = 0; ks < 2; ks++) {
            unsigned bf[4][4];
#pragma unroll
            for (int nf2 = 0; nf2 < 4; nf2++)
                ldsm4(bf[nf2], b_base + SWZ64(offB[nf2] + ks * 32));
#pragma unroll
            for (int term = 0; term < 2; term++) {
                unsigned af[2][4];
                ldsm4(af[0], a_base + SWZ(offA[0] + term * 64 + ks * 32));
                ldsm4(af[1], a_base + SWZ(offA[1] + term * 64 + ks * 32));
#pragma unroll
                for (int nf2 = 0; nf2 < 4; nf2++) {
                    mma_f16(acc[nf2 * 2 + 0],     af[0], bf[nf2][0], bf[nf2][1]);
                    mma_f16(acc[nf2 * 2 + 1],     af[0], bf[nf2][2], bf[nf2][3]);
                    mma_f16(acc[8 + nf2 * 2 + 0], af[1], bf[nf2][0], bf[nf2][1]);
                    mma_f16(acc[8 + nf2 * 2 + 1], af[1], bf[nf2][2], bf[nf2][3]);
                }
            }
        }

        if (more) {
            stageA(cur ^ 1);
            CP_WAIT0();
        }
        __syncthreads();
    }

#pragma unroll
    for (int mf = 0; mf < 2; mf++) {
        int ml = mw * 32 + mf * 16 + (lane >> 2);
        long coff = (long)n_blk * 128 + nw * 64 + (lane & 3) * 2;
        float* zr = zout + (long)(m0 + ml) * NCH + coff;
#pragma unroll
        for (int nf = 0; nf < 8; nf++) {
            *(float2*)(zr + nf * 8) =
                make_float2(acc[mf * 8 + nf][0], acc[mf * 8 + nf][1]);
            *(float2*)(zr + nf * 8 + 8 * NCH) =
                make_float2(acc[mf * 8 + nf][2], acc[mf * 8 + nf][3]);
        }
    }
}

// ---------------------------------------------------------------------------
// FUSED recurrent step: U*h conv (all 256 gate channels) + zx + bias + LSTM
// gates, one kernel. 512 threads, CTA 128m x 256n, 16 warps (4m x 4n).
// h is PING-PONGED across steps: reads hin (h_{t-1}), writes hout (h_t) —
// different buffers, so cross-CTA halo reads never race with writes.
// LAYER==1: write packed h + packed relu(h)->h1seq. LAYER==2: h + NHWC out.
// ---------------------------------------------------------------------------
template<int KH, int NCHUNKS, int LAYER>
__global__ void __launch_bounds__(512, 1)
conv_fused(const unsigned* __restrict__ hin,
           const __half* __restrict__ Bpack,
           const float* __restrict__ zx,
           const float* __restrict__ bias,
           float* __restrict__ cst,
           unsigned* __restrict__ hout,
           unsigned* __restrict__ h1seq,
           float* __restrict__ outp, int t)
{
    extern __shared__ char smem[];
    const unsigned sb = smem_u32(smem);
    const int tid = threadIdx.x;
    const int lane = tid & 31, wid = tid >> 5;
    const int m0 = blockIdx.x * 128;
    const int b = m0 >> 12;
    const int y0 = (m0 & 4095) >> 6;
    constexpr int CIN = 64;
    constexpr int pad = KH >> 1;
    constexpr int HOFF = 2 - pad;

    const unsigned sA0 = sb, sB0 = sb + 32768;

    // producer: 512 threads, 128 pix x 4 channel-groups of 8
    const int pix = tid & 127;
    const int g = tid >> 7;                // 0..3
    const int prow = (y0 + (pix >> 6)) * HR + (pix & 63);

    // consumer: warp (mw, nw), tile 32m x 64n
    const int mw = wid & 3, nw = wid >> 2;
    int offA[2], offBhi[4], offBin[4];
#pragma unroll
    for (int mf = 0; mf < 2; mf++)
        offA[mf] = (mw * 32 + mf * 16 + (lane & 15)) * 128 + (lane >> 4) * 16;
#pragma unroll
    for (int nf2 = 0; nf2 < 4; nf2++) {
        int row = nw * 64 + nf2 * 16 + (lane >> 4) * 8 + (lane & 7);
        offBhi[nf2] = (row >> 7) * 8192;
        offBin[nf2] = (row & 127) * 64 + ((lane >> 3) & 1) * 16;
    }

    float acc[16][4];
#pragma unroll
    for (int i = 0; i < 16; i++)
#pragma unroll
        for (int j = 0; j < 4; j++) acc[i][j] = 0.f;

    unsigned a[8];

    auto prefA = [&](int kc) {
        int k0 = kc * 32;
        int pos = k0 / CIN;
        int cb = k0 - pos * CIN;
        int ky = pos / KH, kx = pos - ky * KH;
        const unsigned* s = hin + ((long)b * CIN + cb + g * 8) * PLANE
                          + prow + (ky + HOFF) * HR + kx + HOFF;
#pragma unroll
        for (int r = 0; r < 8; r++) a[r] = __ldg(s + (long)r * PLANE);
    };

    auto cpB = [&](int kc, int s) {
        const char* gsrc = (const char*)(Bpack + (long)kc * 8192) + tid * 16;
        unsigned dst = sB0 + s * 16384 + tid * 16;
        CP_ASYNC16(dst, gsrc);
        CP_ASYNC16(dst + 8192, gsrc + 8192);
    };

    auto stageA = [&](int s) {
        unsigned hw[4], lw[4];
#pragma unroll
        for (int j = 0; j < 4; j++) {
            hw[j] = __byte_perm(a[2 * j], a[2 * j + 1], 0x5410);
            lw[j] = __byte_perm(a[2 * j], a[2 * j + 1], 0x7632);
        }
        char* Ab = smem + s * 16384;
        int rb = pix * 128 + g * 16;
        *(uint4*)(Ab + SWZ(rb)) = make_uint4(hw[0], hw[1], hw[2], hw[3]);
        *(uint4*)(Ab + SWZ(rb + 64)) = make_uint4(lw[0], lw[1], lw[2], lw[3]);
    };

    prefA(0);
    cpB(0, 0);
    CP_COMMIT();
    stageA(0);
    CP_WAIT0();
    __syncthreads();

    for (int kt = 0; kt < NCHUNKS; kt++) {
        const int cur = kt & 1;
        const bool more = (kt + 1 < NCHUNKS);
        if (more) {
            prefA(kt + 1);
            cpB(kt + 1, cur ^ 1);
            CP_COMMIT();
        }

        const unsigned a_base = sA0 + cur * 16384;
        const unsigned b_base = sB0 + cur * 16384;
#pragma unroll
        for (int ks = 0; ks < 2; ks++) {
            unsigned bf[4][4];
#pragma unroll
            for (int nf2 = 0; nf2 < 4; nf2++)
                ldsm4(bf[nf2], b_base + offBhi[nf2] + SWZ64(offBin[nf2] + ks * 32));
#pragma unroll
            for (int term = 0; term < 2; term++) {
                unsigned af[2][4];
                ldsm4(af[0], a_base + SWZ(offA[0] + term * 64 + ks * 32));
                ldsm4(af[1], a_base + SWZ(offA[1] + term * 64 + ks * 32));
#pragma unroll
                for (int nf2 = 0; nf2 < 4; nf2++) {
                    mma_f16(acc[nf2 * 2 + 0],     af[0], bf[nf2][0], bf[nf2][1]);
                    mma_f16(acc[nf2 * 2 + 1],     af[0], bf[nf2][2], bf[nf2][3]);
                    mma_f16(acc[8 + nf2 * 2 + 0], af[1], bf[nf2][0], bf[nf2][1]);
                    mma_f16(acc[8 + nf2 * 2 + 1], af[1], bf[nf2][2], bf[nf2][3]);
                }
            }
        }

        if (more) {
            stageA(cur ^ 1);
            CP_WAIT0();
        }
        __syncthreads();
    }

    // ================= fused gate epilogue =================
    const float* za = zx + (((long)b * TT + t) * HWP + (m0 & 4095)) * NCH;
    float* zs = (float*)smem;                       // [32][257]
    float* hs = (float*)(smem + 33024);             // [32][65] (LAYER 2)

#pragma unroll 1
    for (int pass = 0; pass < 4; pass++) {
        __syncthreads();                            // zs free
        if (mw == pass) {
            // stage acc + zx + bias into zs[32][257]
#pragma unroll
            for (int mf = 0; mf < 2; mf++) {
                int r0 = mf * 16 + (lane >> 2);     // local row in [0,32)
                long mrow = (long)(pass * 32 + r0);
#pragma unroll
                for (int nf = 0; nf < 8; nf++) {
                    int n = nw * 64 + nf * 8 + (lane & 3) * 2;
                    float b0 = __ldg(bias + n), b1 = __ldg(bias + n + 1);
                    float2 w0 = *(const float2*)(za + mrow * NCH + n);
                    float2 w1 = *(const float2*)(za + (mrow + 8) * NCH + n);
                    float* p0 = zs + r0 * 257 + n;
                    p0[0] = acc[mf * 8 + nf][0] + w0.x + b0;
                    p0[1] = acc[mf * 8 + nf][1] + w0.y + b1;
                    float* p1 = zs + (r0 + 8) * 257 + n;
                    p1[0] = acc[mf * 8 + nf][2] + w1.x + b0;
                    p1[1] = acc[mf * 8 + nf][3] + w1.y + b1;
                }
            }
        }
        __syncthreads();

        // gate compute: lane = pixel, warp id selects 4 f values
        {
            int pixg = (m0 & 4095) + pass * 32 + lane;
            int y = pixg >> 6, xx = pixg & 63;
            int hoffpix = (y + 2) * HR + xx + 2;
#pragma unroll
            for (int i = 0; i < 4; i++) {
                int f = (wid << 2) + i;             // 0..63
                float zi = zs[lane * 257 + f];
                float zf = zs[lane * 257 + 64 + f];
                float zc = zs[lane * 257 + 128 + f];
                float zo = zs[lane * 257 + 192 + f];
                long cidx = ((long)b * FF + f) * HWP + pixg;
                float cn = hsig(zf) * cst[cidx] + hsig(zi) * tanhf(zc);
                float hn = hsig(zo) * tanhf(cn);
                cst[cidx] = cn;
                hout[((long)b * FF + f) * PLANE + hoffpix] = pack_hl(hn);
                if (LAYER == 1)
                    h1seq[((long)(b * TT + t) * FF + f) * PLANE + hoffpix] =
                        pack_hl(fmaxf(hn, 0.f));
                else
                    hs[lane * 65 + f] = fmaxf(hn, 0.f);
            }
        }
        if (LAYER == 2) {
            __syncthreads();
            int f = tid & 63;
            int pq = tid >> 6;                      // 0..7
            float* ob = outp + ((long)(b * TT + t) * HWP + (m0 & 4095) + pass * 32) * FF;
#pragma unroll
            for (int i = 0; i < 4; i++) {
                int px = pq * 4 + i;
                ob[(long)px * FF + f] = hs[px * 65 + f];
            }
        }
    }
}

// ---------------------------------------------------------------------------
extern "C" void kernel_launch(void* const* d_in, const int* in_sizes, int n_in,
                              void* d_out, int out_size)
{
    const float* x   = (const float*)d_in[0];
    const float* Wk1 = (const float*)d_in[1];
    const float* Uk1 = (const float*)d_in[2];
    const float* b1  = (const float*)d_in[3];
    const float* Wk2 = (const float*)d_in[4];
    const float* Uk2 = (const float*)d_in[5];
    const float* b2  = (const float*)d_in[6];
    float* out = (float*)d_out;

    float *zx, *c;
    unsigned *xp, *h1, *hA, *hB;
    __half *B1x, *B1h, *B2x, *B2h;
    cudaGetSymbolAddress((void**)&zx, g_zx);
    cudaGetSymbolAddress((void**)&xp, g_xp);
    cudaGetSymbolAddress((void**)&h1, g_h1);
    cudaGetSymbolAddress((void**)&hA, g_hA);
    cudaGetSymbolAddress((void**)&hB, g_hB);
    cudaGetSymbolAddress((void**)&c,  g_c);
    cudaGetSymbolAddress((void**)&B1x, g_B1x);
    cudaGetSymbolAddress((void**)&B1h, g_B1h);
    cudaGetSymbolAddress((void**)&B2x, g_B2x);
    cudaGetSymbolAddress((void**)&B2h, g_B2h);

    static int smem_set = 0;
    if (!smem_set) {
        cudaFuncSetAttribute(conv_big<32, 5, NC1X>,
                             cudaFuncAttributeMaxDynamicSharedMemorySize, SM_BIG);
        cudaFuncSetAttribute(conv_big<64, 3, NC2>,
                             cudaFuncAttributeMaxDynamicSharedMemorySize, SM_BIG);
        cudaFuncSetAttribute(conv_fused<5, NC1H, 1>,
                             cudaFuncAttributeMaxDynamicSharedMemorySize, SM_FUSED);
        cudaFuncSetAttribute(conv_fused<3, NC2, 2>,
                             cudaFuncAttributeMaxDynamicSharedMemorySize, SM_FUSED);
        smem_set = 1;
    }

    const dim3 gridBig(2, M_BIG / 128);   // (2, 2560)
    const int gridRec = M_TOTAL / 128;    // 256
    const long hN4 = (long)BB * FF * PLANE / 4;

    // Launch order is deliberate: index 3 = layer-1 big GEMM (ncu captures it).
    prepack_all<<<(909312 + 255) / 256, 256>>>(Wk1, Uk1, Wk2, Uk2, B1x, B1h, B2x, B2h);
    zerok<<<1024, 256>>>((float4*)xp, (long)BB * TT * 32 * PLANE / 4);
    {
        long totx = (long)BB * TT * 32 * HWP;
        transpose_x<<<(int)((totx + 255) / 256), 256>>>(x, xp);
    }
    // [3] zx = W1 * x for all timesteps  <-- PROFILED
    conv_big<32, 5, NC1X><<<gridBig, 256, SM_BIG>>>(xp, B1x, zx);
    zerok2<<<1024, 256>>>((float4*)hA, (float4*)hB, hN4);
    zerok<<<1024, 256>>>((float4*)c, (long)BB * FF * HWP / 4);
    zerok<<<1024, 256>>>((float4*)h1, (long)BB * TT * FF * PLANE / 4);

    // ---- Layer 1 recurrence (fused conv+gates, ping-pong h) ----
    for (int t = 0; t < TT; t++) {
        unsigned* hin  = (t & 1) ? hB : hA;
        unsigned* hout = (t & 1) ? hA : hB;
        conv_fused<5, NC1H, 1><<<gridRec, 512, SM_FUSED>>>(
            hin, B1h, zx, b1, c, hout, h1, nullptr, t);
    }

    // ---- Layer 2 ----
    conv_big<64, 3, NC2><<<gridBig, 256, SM_BIG>>>(h1, B2x, zx);
    zerok2<<<1024, 256>>>((float4*)hA, (float4*)hB, hN4);
    zerok<<<1024, 256>>>((float4*)c, (long)BB * FF * HWP / 4);
    for (int t = 0; t < TT; t++) {
        unsigned* hin  = (t & 1) ? hB : hA;
        unsigned* hout = (t & 1) ? hA : hB;
        conv_fused<3, NC2, 2><<<gridRec, 512, SM_FUSED>>>(
            hin, B2h, zx, b2, c, hout, nullptr, out, t);
    }
}

// round 12
// speedup vs baseline: 1.1091x; 1.1091x over previous
#include <cuda_runtime.h>
#include <cuda_fp16.h>
#include <math.h>

// Problem constants
#define BB 8
#define TT 10
#define HH 64
#define WW 64
#define HWP 4096           // H*W
#define FF 64
#define NCH 256            // 4*F
#define M_TOTAL (BB*HWP)   // 32768
#define M_BIG   (BB*TT*HWP) // 327680

// Planar halo layout: 2-pixel border on each side
#define HR 68
#define PLANE (HR*HR)      // 4624 per channel plane

// K chunk = 32 fp32 channels -> 64 fp16 cols in A (ah|al), 32 fp16 in B (bh)
#define NC1X 25            // layer1 x-part:  K=800  (25 taps x 32ch) /32
#define NC1H 50            // layer1 h-part:  K=1600 (25 x 64) /32
#define NC2  18            // layer2 x/h:     K=576  (9 x 64) /32

#define SM_BIG   49152     // big GEMM kernel: A[2][16K] + B[2][8K]
#define SM_FUSED 65536     // fused kernel:    A[2][16K] + B[2][16K]

// N-column permutation: GEMM column n' carries f = n'>>2, gate = n'&3.
// Original weight column = gate*64 + f. zx, B tiles, fused epilogue all use n'.

// Scratch (static device globals; no allocation allowed)
// Activation planes are packed u32 = fp16(hi) | fp16(lo)<<16  (hi+lo == fp32 value)
__device__ float    g_zx[(long)M_BIG * NCH];           // W*x + bias, permuted cols
__device__ unsigned g_xp[(long)BB * TT * 32 * PLANE];  // x planar+halo, packed hi/lo
__device__ unsigned g_h1[(long)BB * TT * FF * PLANE];  // relu(h) seq layer1, packed
__device__ unsigned g_hA[(long)BB * FF * PLANE];       // hidden state ping
__device__ unsigned g_hB[(long)BB * FF * PLANE];       // hidden state pong
__device__ float    g_c[(long)BB * FF * HWP];          // cell state, planar fp32
__device__ __half g_B1x[(long)2 * NC1X * 4096];        // big-GEMM tiles [nb][kc]
__device__ __half g_B1h[(long)2 * NC1H * 4096];        // fused tiles   [kc][nb]
__device__ __half g_B2x[(long)2 * NC2 * 4096];
__device__ __half g_B2h[(long)2 * NC2 * 4096];

// ---------------------------------------------------------------------------
// Helpers (sm_80-baseline PTX only — harness targets family-generic sm_103)
// ---------------------------------------------------------------------------
__device__ __forceinline__ unsigned smem_u32(const void* p) {
    unsigned r;
    asm("{ .reg .u64 t; cvta.to.shared.u64 t, %1; cvt.u32.u64 %0, t; }"
        : "=r"(r) : "l"(p));
    return r;
}
__device__ __forceinline__ unsigned pack_hl(float f) {
    __half h = __float2half_rn(f);
    float r = f - __half2float(h);
    return (unsigned)__half_as_ushort(h)
         | ((unsigned)__half_as_ushort(__float2half_rn(r)) << 16);
}
__device__ __forceinline__ void ldsm4(unsigned* r, unsigned addr) {
    asm volatile("ldmatrix.sync.aligned.m8n8.x4.shared.b16 {%0,%1,%2,%3}, [%4];"
                 : "=r"(r[0]), "=r"(r[1]), "=r"(r[2]), "=r"(r[3]) : "r"(addr));
}
__device__ __forceinline__ void mma_f16(float* c, const unsigned* a,
                                        unsigned b0, unsigned b1) {
    asm volatile(
        "mma.sync.aligned.m16n8k16.row.col.f32.f16.f16.f32 "
        "{%0,%1,%2,%3}, {%4,%5,%6,%7}, {%8,%9}, {%0,%1,%2,%3};"
        : "+f"(c[0]), "+f"(c[1]), "+f"(c[2]), "+f"(c[3])
        : "r"(a[0]), "r"(a[1]), "r"(a[2]), "r"(a[3]), "r"(b0), "r"(b1));
}
#define CP_ASYNC16(dst, src) \
    asm volatile("cp.async.cg.shared.global [%0], [%1], 16;" \
                 :: "r"(dst), "l"(src))
#define CP_COMMIT() asm volatile("cp.async.commit_group;" ::: "memory")
#define CP_WAIT0()  asm volatile("cp.async.wait_group 0;" ::: "memory")

#define SWZ(off)   ((off) ^ (((off) >> 3) & 0x70))   // 128B-row swizzle (A)
#define SWZ64(off) ((off) ^ (((off) >> 3) & 0x30))   // 64B-row swizzle (B)

__device__ __forceinline__ float hsig(float v)
{
    return fminf(fmaxf(0.2f * v + 0.5f, 0.f), 1.f);
}

// ---------------------------------------------------------------------------
__global__ void zerok(float4* __restrict__ p, long n4)
{
    long stride = (long)gridDim.x * blockDim.x;
    for (long i = blockIdx.x * (long)blockDim.x + threadIdx.x; i < n4; i += stride)
        p[i] = make_float4(0.f, 0.f, 0.f, 0.f);
}
__global__ void zerok2(float4* __restrict__ p, float4* __restrict__ q, long n4)
{
    long stride = (long)gridDim.x * blockDim.x;
    for (long i = blockIdx.x * (long)blockDim.x + threadIdx.x; i < n4; i += stride) {
        p[i] = make_float4(0.f, 0.f, 0.f, 0.f);
        q[i] = make_float4(0.f, 0.f, 0.f, 0.f);
    }
}

// ---------------------------------------------------------------------------
// Prepack weights into permuted-N 8KB tiles (128 N-rows x 32 fp16, 64B rows,
// SWZ64). GEMM col n' reads original weight col (n'&3)*64 + (n'>>2).
// Tile order: big GEMM = [nb][kc]; fused = [kc][nb].
// ---------------------------------------------------------------------------
__device__ __forceinline__ void prepack_one(long idx, const float* __restrict__ W,
                                            __half* __restrict__ Bp, int Cin,
                                            int nch, int fused)
{
    int j = (int)(idx & 31);
    long r = idx >> 5;
    int nrow = (int)(r & 127);
    r >>= 7;
    int kc = (int)(r % nch);
    int nb = (int)(r / nch);
    int k = kc * 32 + j;
    int pos = k / Cin, c = k % Cin;
    int n = nb * 128 + nrow;                    // permuted column index
    int worig = ((n & 3) << 6) + (n >> 2);      // gate*64 + f
    float w = W[((long)pos * Cin + c) * NCH + worig];
    int inb = nrow * 64 + j * 2;
    int sw = SWZ64(inb);
    long tile = fused ? (long)(kc * 2 + nb) : (long)(nb * nch + kc);
    Bp[tile * 4096 + (sw >> 1)] = __float2half_rn(w);
}

__global__ void prepack_all(const float* __restrict__ W1, const float* __restrict__ U1,
                            const float* __restrict__ W2, const float* __restrict__ U2,
                            __half* __restrict__ B1x, __half* __restrict__ B1h,
                            __half* __restrict__ B2x, __half* __restrict__ B2h)
{
    long idx = blockIdx.x * 256L + threadIdx.x;
    if (idx < 204800)       prepack_one(idx,          W1, B1x, 32, NC1X, 0);
    else if (idx < 614400)  prepack_one(idx - 204800, U1, B1h, 64, NC1H, 1);
    else if (idx < 761856)  prepack_one(idx - 614400, W2, B2x, 64, NC2, 0);
    else if (idx < 909312)  prepack_one(idx - 761856, U2, B2h, 64, NC2, 1);
}

// ---------------------------------------------------------------------------
// Transpose x [b,t,pix,32] (NHWC fp32) -> xp [b,t,32,PLANE] packed hi/lo planes
// ---------------------------------------------------------------------------
__global__ void transpose_x(const float* __restrict__ x, unsigned* __restrict__ xp)
{
    long idx = blockIdx.x * (long)blockDim.x + threadIdx.x;
    if (idx >= (long)BB * TT * 32 * HWP) return;
    int pix = idx & 4095;
    long rest = idx >> 12;
    int ch = (int)(rest & 31);
    long bt = rest >> 5;
    float v = x[(bt * HWP + pix) * 32 + ch];
    int y = pix >> 6, xx = pix & 63;
    xp[(bt * 32 + ch) * PLANE + (y + 2) * HR + xx + 2] = pack_hl(v);
}

// ---------------------------------------------------------------------------
// Big-GEMM conv (input part, all timesteps). 256 threads, CTA 128m x 128n,
// 8 warps x (32m x 64n). fp16x2 split (ah*bh + al*bh). Epilogue folds bias
// (permuted cols) into zout.
// ---------------------------------------------------------------------------
template<int CIN, int KH, int NCHUNKS>
__global__ void __launch_bounds__(256, 2)
conv_big(const unsigned* __restrict__ src,
         const __half* __restrict__ Bpack,
         const float* __restrict__ bias,
         float* __restrict__ zout)
{
    extern __shared__ char smem[];
    const unsigned sb = smem_u32(smem);
    const int tid = threadIdx.x;
    const int lane = tid & 31, wid = tid >> 5;
    const int n_blk = blockIdx.x;          // 0..1
    const int m0 = blockIdx.y * 128;
    const int bt = m0 >> 12;
    const int y0 = (m0 & 4095) >> 6;
    constexpr int pad = KH >> 1;
    constexpr int HOFF = 2 - pad;

    const unsigned sA0 = sb, sB0 = sb + 32768;

    const int pix = tid & 127;
    const int g = tid >> 7;                // 0/1: channels g*16..g*16+15
    const int prow = (y0 + (pix >> 6)) * HR + (pix & 63);

    const int mw = wid & 3, nw = wid >> 2;
    int offA[2], offB[4];
#pragma unroll
    for (int mf = 0; mf < 2; mf++)
        offA[mf] = (mw * 32 + mf * 16 + (lane & 15)) * 128 + (lane >> 4) * 16;
#pragma unroll
    for (int nf2 = 0; nf2 < 4; nf2++)
        offB[nf2] = (nw * 64 + nf2 * 16 + (lane >> 4) * 8 + (lane & 7)) * 64
                  + ((lane >> 3) & 1) * 16;

    float acc[16][4];
#pragma unroll
    for (int i = 0; i < 16; i++)
#pragma unroll
        for (int j = 0; j < 4; j++) acc[i][j] = 0.f;

    unsigned a[16];

    auto prefA = [&](int kc) {
        int k0 = kc * 32;
        int pos = k0 / CIN;
        int cb = k0 - pos * CIN;
        int ky = pos / KH, kx = pos - ky * KH;
        const unsigned* s = src + ((long)bt * CIN + cb + g * 16) * PLANE
                          + prow + (ky + HOFF) * HR + kx + HOFF;
#pragma unroll
        for (int r = 0; r < 16; r++) a[r] = __ldg(s + (long)r * PLANE);
    };

    auto cpB = [&](int kc, int s) {
        const char* gsrc = (const char*)(Bpack + ((long)n_blk * NCHUNKS + kc) * 4096)
                         + tid * 16;
        unsigned dst = sB0 + s * 8192 + tid * 16;
        CP_ASYNC16(dst, gsrc);
        CP_ASYNC16(dst + 4096, gsrc + 4096);
    };

    auto stageA = [&](int s) {
        unsigned hw[8], lw[8];
#pragma unroll
        for (int j = 0; j < 8; j++) {
            hw[j] = __byte_perm(a[2 * j], a[2 * j + 1], 0x5410);
            lw[j] = __byte_perm(a[2 * j], a[2 * j + 1], 0x7632);
        }
        char* Ab = smem + s * 16384;
        int rb = pix * 128 + g * 32;
#pragma unroll
        for (int q = 0; q < 2; q++) {
            *(uint4*)(Ab + SWZ(rb + q * 16)) =
                make_uint4(hw[q * 4], hw[q * 4 + 1], hw[q * 4 + 2], hw[q * 4 + 3]);
            *(uint4*)(Ab + SWZ(rb + 64 + q * 16)) =
                make_uint4(lw[q * 4], lw[q * 4 + 1], lw[q * 4 + 2], lw[q * 4 + 3]);
        }
    };

    prefA(0);
    cpB(0, 0);
    CP_COMMIT();
    stageA(0);
    CP_WAIT0();
    __syncthreads();

    for (int kt = 0; kt < NCHUNKS; kt++) {
        const int cur = kt & 1;
        const bool more = (kt + 1 < NCHUNKS);
        if (more) {
            prefA(kt + 1);
            cpB(kt + 1, cur ^ 1);
            CP_COMMIT();
        }

        const unsigned a_base = sA0 + cur * 16384;
        const unsigned b_base = sB0 + cur * 8192;
#pragma unroll
        for (int ks = 0; ks < 2; ks++) {
            unsigned bf[4][4];
#pragma unroll
            for (int nf2 = 0; nf2 < 4; nf2++)
                ldsm4(bf[nf2], b_base + SWZ64(offB[nf2] + ks * 32));
#pragma unroll
            for (int term = 0; term < 2; term++) {
                unsigned af[2][4];
                ldsm4(af[0], a_base + SWZ(offA[0] + term * 64 + ks * 32));
                ldsm4(af[1], a_base + SWZ(offA[1] + term * 64 + ks * 32));
#pragma unroll
                for (int nf2 = 0; nf2 < 4; nf2++) {
                    mma_f16(acc[nf2 * 2 + 0],     af[0], bf[nf2][0], bf[nf2][1]);
                    mma_f16(acc[nf2 * 2 + 1],     af[0], bf[nf2][2], bf[nf2][3]);
                    mma_f16(acc[8 + nf2 * 2 + 0], af[1], bf[nf2][0], bf[nf2][1]);
                    mma_f16(acc[8 + nf2 * 2 + 1], af[1], bf[nf2][2], bf[nf2][3]);
                }
            }
        }

        if (more) {
            stageA(cur ^ 1);
            CP_WAIT0();
        }
        __syncthreads();
    }

    // epilogue: + bias (permuted cols), write zout
    const long coff = (long)n_blk * 128 + nw * 64 + (lane & 3) * 2;
    float bb0[8], bb1[8];
#pragma unroll
    for (int nf = 0; nf < 8; nf++) {
        int col = (int)coff + nf * 8;
        bb0[nf] = __ldg(bias + ((col & 3) << 6) + (col >> 2));
        bb1[nf] = __ldg(bias + (((col + 1) & 3) << 6) + ((col + 1) >> 2));
    }
#pragma unroll
    for (int mf = 0; mf < 2; mf++) {
        int ml = mw * 32 + mf * 16 + (lane >> 2);
        float* zr = zout + (long)(m0 + ml) * NCH + coff;
#pragma unroll
        for (int nf = 0; nf < 8; nf++) {
            *(float2*)(zr + nf * 8) = make_float2(
                acc[mf * 8 + nf][0] + bb0[nf], acc[mf * 8 + nf][1] + bb1[nf]);
            *(float2*)(zr + nf * 8 + 8 * NCH) = make_float2(
                acc[mf * 8 + nf][2] + bb0[nf], acc[mf * 8 + nf][3] + bb1[nf]);
        }
    }
}

// ---------------------------------------------------------------------------
// FUSED recurrent step: U*h conv (all 256 permuted gate channels) + zx + LSTM
// gates, one kernel. 512 threads, CTA 128m x 256n, 16 warps (4m x 4n).
// h ping-pongs across steps (no cross-CTA halo race). Register-gate epilogue:
// permuted cols put all 4 gates of one f in adjacent columns, so a lane and
// its xor-1 partner hold the full gate set -> one shfl exchange, no smem
// staging, no epilogue syncs (LAYER 2 adds one sync for the NHWC transpose).
// ---------------------------------------------------------------------------
template<int KH, int NCHUNKS, int LAYER>
__global__ void __launch_bounds__(512, 1)
conv_fused(const unsigned* __restrict__ hin,
           const __half* __restrict__ Bpack,
           const float* __restrict__ zx,
           float* __restrict__ cst,
           unsigned* __restrict__ hout,
           unsigned* __restrict__ h1seq,
           float* __restrict__ outp, int t)
{
    extern __shared__ char smem[];
    const unsigned sb = smem_u32(smem);
    const int tid = threadIdx.x;
    const int lane = tid & 31, wid = tid >> 5;
    const int m0 = blockIdx.x * 128;
    const int b = m0 >> 12;
    const int y0 = (m0 & 4095) >> 6;
    constexpr int CIN = 64;
    constexpr int pad = KH >> 1;
    constexpr int HOFF = 2 - pad;

    const unsigned sA0 = sb, sB0 = sb + 32768;

    // producer: 512 threads, 128 pix x 4 channel-groups of 8
    const int pix = tid & 127;
    const int g = tid >> 7;                // 0..3
    const int prow = (y0 + (pix >> 6)) * HR + (pix & 63);

    // consumer: warp (mw, nw), tile 32m x 64n
    const int mw = wid & 3, nw = wid >> 2;
    int offA[2], offBhi[4], offBin[4];
#pragma unroll
    for (int mf = 0; mf < 2; mf++)
        offA[mf] = (mw * 32 + mf * 16 + (lane & 15)) * 128 + (lane >> 4) * 16;
#pragma unroll
    for (int nf2 = 0; nf2 < 4; nf2++) {
        int row = nw * 64 + nf2 * 16 + (lane >> 4) * 8 + (lane & 7);
        offBhi[nf2] = (row >> 7) * 8192;
        offBin[nf2] = (row & 127) * 64 + ((lane >> 3) & 1) * 16;
    }

    float acc[16][4];
#pragma unroll
    for (int i = 0; i < 16; i++)
#pragma unroll
        for (int j = 0; j < 4; j++) acc[i][j] = 0.f;

    unsigned a[8];

    auto prefA = [&](int kc) {
        int k0 = kc * 32;
        int pos = k0 / CIN;
        int cb = k0 - pos * CIN;
        int ky = pos / KH, kx = pos - ky * KH;
        const unsigned* s = hin + ((long)b * CIN + cb + g * 8) * PLANE
                          + prow + (ky + HOFF) * HR + kx + HOFF;
#pragma unroll
        for (int r = 0; r < 8; r++) a[r] = __ldg(s + (long)r * PLANE);
    };

    auto cpB = [&](int kc, int s) {
        const char* gsrc = (const char*)(Bpack + (long)kc * 8192) + tid * 16;
        unsigned dst = sB0 + s * 16384 + tid * 16;
        CP_ASYNC16(dst, gsrc);
        CP_ASYNC16(dst + 8192, gsrc + 8192);
    };

    auto stageA = [&](int s) {
        unsigned hw[4], lw[4];
#pragma unroll
        for (int j = 0; j < 4; j++) {
            hw[j] = __byte_perm(a[2 * j], a[2 * j + 1], 0x5410);
            lw[j] = __byte_perm(a[2 * j], a[2 * j + 1], 0x7632);
        }
        char* Ab = smem + s * 16384;
        int rb = pix * 128 + g * 16;
        *(uint4*)(Ab + SWZ(rb)) = make_uint4(hw[0], hw[1], hw[2], hw[3]);
        *(uint4*)(Ab + SWZ(rb + 64)) = make_uint4(lw[0], lw[1], lw[2], lw[3]);
    };

    prefA(0);
    cpB(0, 0);
    CP_COMMIT();
    stageA(0);
    CP_WAIT0();
    __syncthreads();

    for (int kt = 0; kt < NCHUNKS; kt++) {
        const int cur = kt & 1;
        const bool more = (kt + 1 < NCHUNKS);
        if (more) {
            prefA(kt + 1);
            cpB(kt + 1, cur ^ 1);
            CP_COMMIT();
        }

        const unsigned a_base = sA0 + cur * 16384;
        const unsigned b_base = sB0 + cur * 16384;
#pragma unroll
        for (int ks = 0; ks < 2; ks++) {
            unsigned bf[4][4];
#pragma unroll
            for (int nf2 = 0; nf2 < 4; nf2++)
                ldsm4(bf[nf2], b_base + offBhi[nf2] + SWZ64(offBin[nf2] + ks * 32));
#pragma unroll
            for (int term = 0; term < 2; term++) {
                unsigned af[2][4];
                ldsm4(af[0], a_base + SWZ(offA[0] + term * 64 + ks * 32));
                ldsm4(af[1], a_base + SWZ(offA[1] + term * 64 + ks * 32));
#pragma unroll
                for (int nf2 = 0; nf2 < 4; nf2++) {
                    mma_f16(acc[nf2 * 2 + 0],     af[0], bf[nf2][0], bf[nf2][1]);
                    mma_f16(acc[nf2 * 2 + 1],     af[0], bf[nf2][2], bf[nf2][3]);
                    mma_f16(acc[8 + nf2 * 2 + 0], af[1], bf[nf2][0], bf[nf2][1]);
                    mma_f16(acc[8 + nf2 * 2 + 1], af[1], bf[nf2][2], bf[nf2][3]);
                }
            }
        }

        if (more) {
            stageA(cur ^ 1);
            CP_WAIT0();
        }
        __syncthreads();
    }

    // ================= register-gate epilogue =================
    // acc[mf*8+nf][0..3] = rows (r, r+8) x cols (n', n'+1),
    // n' = nw*64 + nf*8 + q*2, q = lane&3. q even -> gates (i,f); q odd ->
    // gates (c,o) of the same f = n'>>2. xor-1 partner holds the other pair.
    const float* za = zx + (((long)b * TT + t) * HWP + (m0 & 4095)) * NCH;
    float* hs = (float*)smem;              // LAYER 2: [128][65] relu(h) staging
    const int q = lane & 3;
    const int rq = lane >> 2;
    const bool odd = (q & 1);
#pragma unroll
    for (int mf = 0; mf < 2; mf++) {
        const int rloc = mw * 32 + mf * 16 + rq;
#pragma unroll
        for (int nf = 0; nf < 8; nf++) {
            int col = nw * 64 + nf * 8 + q * 2;
            float2 w0 = *(const float2*)(za + (long)rloc * NCH + col);
            float2 w1 = *(const float2*)(za + (long)(rloc + 8) * NCH + col);
            float z0 = acc[mf * 8 + nf][0] + w0.x;
            float z1 = acc[mf * 8 + nf][1] + w0.y;
            float z2 = acc[mf * 8 + nf][2] + w1.x;
            float z3 = acc[mf * 8 + nf][3] + w1.y;
            float e0 = __shfl_xor_sync(0xFFFFFFFFu, z0, 1);
            float e1 = __shfl_xor_sync(0xFFFFFFFFu, z1, 1);
            float e2 = __shfl_xor_sync(0xFFFFFFFFu, z2, 1);
            float e3 = __shfl_xor_sync(0xFFFFFFFFu, z3, 1);
            float zi = odd ? e2 : z0;
            float zf = odd ? e3 : z1;
            float zc = odd ? z2 : e0;
            float zo = odd ? z3 : e1;
            int pixl = rloc + (odd ? 8 : 0);
            int f = nw * 16 + nf * 2 + (q >> 1);
            int pixg = (m0 & 4095) + pixl;
            long cidx = ((long)b * FF + f) * HWP + pixg;
            float cn = hsig(zf) * cst[cidx] + hsig(zi) * tanhf(zc);
            float hn = hsig(zo) * tanhf(cn);
            cst[cidx] = cn;
            int y = pixg >> 6, xx = pixg & 63;
            int hoffpix = (y + 2) * HR + xx + 2;
            hout[((long)b * FF + f) * PLANE + hoffpix] = pack_hl(hn);
            if (LAYER == 1)
                h1seq[((long)(b * TT + t) * FF + f) * PLANE + hoffpix] =
                    pack_hl(fmaxf(hn, 0.f));
            else
                hs[pixl * 65 + f] = fmaxf(hn, 0.f);
        }
    }
    if (LAYER == 2) {
        __syncthreads();
        float* ob = outp + ((long)(b * TT + t) * HWP + (m0 & 4095)) * FF;
#pragma unroll
        for (int i = 0; i < 16; i++) {
            int e = i * 512 + tid;
            int pixl = e >> 6, f = e & 63;
            ob[(long)pixl * FF + f] = hs[pixl * 65 + f];
        }
    }
}

// ---------------------------------------------------------------------------
extern "C" void kernel_launch(void* const* d_in, const int* in_sizes, int n_in,
                              void* d_out, int out_size)
{
    const float* x   = (const float*)d_in[0];
    const float* Wk1 = (const float*)d_in[1];
    const float* Uk1 = (const float*)d_in[2];
    const float* b1  = (const float*)d_in[3];
    const float* Wk2 = (const float*)d_in[4];
    const float* Uk2 = (const float*)d_in[5];
    const float* b2  = (const float*)d_in[6];
    float* out = (float*)d_out;

    float *zx, *c;
    unsigned *xp, *h1, *hA, *hB;
    __half *B1x, *B1h, *B2x, *B2h;
    cudaGetSymbolAddress((void**)&zx, g_zx);
    cudaGetSymbolAddress((void**)&xp, g_xp);
    cudaGetSymbolAddress((void**)&h1, g_h1);
    cudaGetSymbolAddress((void**)&hA, g_hA);
    cudaGetSymbolAddress((void**)&hB, g_hB);
    cudaGetSymbolAddress((void**)&c,  g_c);
    cudaGetSymbolAddress((void**)&B1x, g_B1x);
    cudaGetSymbolAddress((void**)&B1h, g_B1h);
    cudaGetSymbolAddress((void**)&B2x, g_B2x);
    cudaGetSymbolAddress((void**)&B2h, g_B2h);

    static int smem_set = 0;
    if (!smem_set) {
        cudaFuncSetAttribute(conv_big<32, 5, NC1X>,
                             cudaFuncAttributeMaxDynamicSharedMemorySize, SM_BIG);
        cudaFuncSetAttribute(conv_big<64, 3, NC2>,
                             cudaFuncAttributeMaxDynamicSharedMemorySize, SM_BIG);
        cudaFuncSetAttribute(conv_fused<5, NC1H, 1>,
                             cudaFuncAttributeMaxDynamicSharedMemorySize, SM_FUSED);
        cudaFuncSetAttribute(conv_fused<3, NC2, 2>,
                             cudaFuncAttributeMaxDynamicSharedMemorySize, SM_FUSED);
        smem_set = 1;
    }

    const dim3 gridBig(2, M_BIG / 128);   // (2, 2560)
    const int gridRec = M_TOTAL / 128;    // 256
    const long hN4 = (long)BB * FF * PLANE / 4;

    // Launch order is deliberate: index 3 = layer-1 big GEMM (ncu captures it).
    prepack_all<<<(909312 + 255) / 256, 256>>>(Wk1, Uk1, Wk2, Uk2, B1x, B1h, B2x, B2h);
    zerok<<<1024, 256>>>((float4*)xp, (long)BB * TT * 32 * PLANE / 4);
    {
        long totx = (long)BB * TT * 32 * HWP;
        transpose_x<<<(int)((totx + 255) / 256), 256>>>(x, xp);
    }
    // [3] zx = W1 * x + b1 for all timesteps  <-- PROFILED
    conv_big<32, 5, NC1X><<<gridBig, 256, SM_BIG>>>(xp, B1x, b1, zx);
    zerok2<<<1024, 256>>>((float4*)hA, (float4*)hB, hN4);
    zerok<<<1024, 256>>>((float4*)c, (long)BB * FF * HWP / 4);
    zerok<<<1024, 256>>>((float4*)h1, (long)BB * TT * FF * PLANE / 4);

    // ---- Layer 1 recurrence (fused conv+gates, ping-pong h) ----
    for (int t = 0; t < TT; t++) {
        unsigned* hin  = (t & 1) ? hB : hA;
        unsigned* hout = (t & 1) ? hA : hB;
        conv_fused<5, NC1H, 1><<<gridRec, 512, SM_FUSED>>>(
            hin, B1h, zx, c, hout, h1, nullptr, t);
    }

    // ---- Layer 2 ----
    conv_big<64, 3, NC2><<<gridBig, 256, SM_BIG>>>(h1, B2x, b2, zx);
    zerok2<<<1024, 256>>>((float4*)hA, (float4*)hB, hN4);
    zerok<<<1024, 256>>>((float4*)c, (long)BB * FF * HWP / 4);
    for (int t = 0; t < TT; t++) {
        unsigned* hin  = (t & 1) ? hB : hA;
        unsigned* hout = (t & 1) ? hA : hB;
        conv_fused<3, NC2, 2><<<gridRec, 512, SM_FUSED>>>(
            hin, B2h, zx, c, hout, nullptr, out, t);
    }
}

// round 13
// speedup vs baseline: 1.2211x; 1.1011x over previous
#include <cuda_runtime.h>
#include <cuda_fp16.h>
#include <math.h>

// Problem constants
#define BB 8
#define TT 10
#define HH 64
#define WW 64
#define HWP 4096           // H*W
#define FF 64
#define NCH 256            // 4*F
#define M_TOTAL (BB*HWP)   // 32768
#define M_BIG   (BB*TT*HWP) // 327680

// Planar halo layout: 2-pixel border on each side
#define HR 68
#define PLANE (HR*HR)      // 4624 per channel plane

// K chunk = 32 fp32 channels -> 64 fp16 cols in A (ah|al), 32 fp16 in B (bh)
#define NC1X 25            // layer1 x-part:  K=800  (25 taps x 32ch) /32
#define NC1H 50            // layer1 h-part:  K=1600 (25 x 64) /32
#define NC2  18            // layer2 x/h:     K=576  (9 x 64) /32

#define SM_BIG 49152       // A[2][16K] + B[2][8K] (both GEMM kernels)

// N-column permutation: GEMM column n' carries f = n'>>2, gate = n'&3.
// Original weight column = gate*64 + f. zx, B tiles, epilogues all use n'.

// Scratch (static device globals; no allocation allowed)
// Activation planes are packed u32 = fp16(hi) | fp16(lo)<<16  (hi+lo == fp32 value)
__device__ float    g_zx[(long)M_BIG * NCH];           // W*x + bias, permuted cols
__device__ unsigned g_xp[(long)BB * TT * 32 * PLANE];  // x planar+halo, packed hi/lo
__device__ unsigned g_h1[(long)BB * TT * FF * PLANE];  // relu(h) seq layer1, packed
__device__ unsigned g_hA[(long)BB * FF * PLANE];       // hidden state ping
__device__ unsigned g_hB[(long)BB * FF * PLANE];       // hidden state pong
__device__ float    g_c[(long)BB * FF * HWP];          // cell state (t0 skips read)
__device__ __half g_B1x[(long)2 * NC1X * 4096];        // big-GEMM tiles [nb][kc]
__device__ __half g_B1h[(long)2 * NC1H * 4096];        // fused tiles   [kc][nb]
__device__ __half g_B2x[(long)2 * NC2 * 4096];
__device__ __half g_B2h[(long)2 * NC2 * 4096];

// ---------------------------------------------------------------------------
// Helpers (sm_80-baseline PTX only — harness targets family-generic sm_103)
// ---------------------------------------------------------------------------
__device__ __forceinline__ unsigned smem_u32(const void* p) {
    unsigned r;
    asm("{ .reg .u64 t; cvta.to.shared.u64 t, %1; cvt.u32.u64 %0, t; }"
        : "=r"(r) : "l"(p));
    return r;
}
__device__ __forceinline__ unsigned pack_hl(float f) {
    __half h = __float2half_rn(f);
    float r = f - __half2float(h);
    return (unsigned)__half_as_ushort(h)
         | ((unsigned)__half_as_ushort(__float2half_rn(r)) << 16);
}
__device__ __forceinline__ void ldsm4(unsigned* r, unsigned addr) {
    asm volatile("ldmatrix.sync.aligned.m8n8.x4.shared.b16 {%0,%1,%2,%3}, [%4];"
                 : "=r"(r[0]), "=r"(r[1]), "=r"(r[2]), "=r"(r[3]) : "r"(addr));
}
__device__ __forceinline__ void mma_f16(float* c, const unsigned* a,
                                        unsigned b0, unsigned b1) {
    asm volatile(
        "mma.sync.aligned.m16n8k16.row.col.f32.f16.f16.f32 "
        "{%0,%1,%2,%3}, {%4,%5,%6,%7}, {%8,%9}, {%0,%1,%2,%3};"
        : "+f"(c[0]), "+f"(c[1]), "+f"(c[2]), "+f"(c[3])
        : "r"(a[0]), "r"(a[1]), "r"(a[2]), "r"(a[3]), "r"(b0), "r"(b1));
}
#define CP_ASYNC16(dst, src) \
    asm volatile("cp.async.cg.shared.global [%0], [%1], 16;" \
                 :: "r"(dst), "l"(src))
#define CP_COMMIT() asm volatile("cp.async.commit_group;" ::: "memory")
#define CP_WAIT0()  asm volatile("cp.async.wait_group 0;" ::: "memory")

#define SWZ(off)   ((off) ^ (((off) >> 3) & 0x70))   // 128B-row swizzle (A)
#define SWZ64(off) ((off) ^ (((off) >> 3) & 0x30))   // 64B-row swizzle (B)

__device__ __forceinline__ float hsig(float v)
{
    return fminf(fmaxf(0.2f * v + 0.5f, 0.f), 1.f);
}

// ---------------------------------------------------------------------------
// Prepack weights into permuted-N 8KB tiles (128 N-rows x 32 fp16, 64B rows,
// SWZ64). GEMM col n' reads original weight col (n'&3)*64 + (n'>>2).
// Tile order: big GEMM = [nb][kc]; fused = [kc][nb].
// ---------------------------------------------------------------------------
__device__ __forceinline__ void prepack_one(long idx, const float* __restrict__ W,
                                            __half* __restrict__ Bp, int Cin,
                                            int nch, int fused)
{
    int j = (int)(idx & 31);
    long r = idx >> 5;
    int nrow = (int)(r & 127);
    r >>= 7;
    int kc = (int)(r % nch);
    int nb = (int)(r / nch);
    int k = kc * 32 + j;
    int pos = k / Cin, c = k % Cin;
    int n = nb * 128 + nrow;                    // permuted column index
    int worig = ((n & 3) << 6) + (n >> 2);      // gate*64 + f
    float w = W[((long)pos * Cin + c) * NCH + worig];
    int inb = nrow * 64 + j * 2;
    int sw = SWZ64(inb);
    long tile = fused ? (long)(kc * 2 + nb) : (long)(nb * nch + kc);
    Bp[tile * 4096 + (sw >> 1)] = __float2half_rn(w);
}

// ---------------------------------------------------------------------------
// mega_setup: ONE kernel for prepack + x transpose (with halo zero-fill) +
// zeroing h1 / hA / hB. Grid-stride over concatenated work segments.
// ---------------------------------------------------------------------------
#define MS_P0 909312L                 // prepack items
#define MS_P1 12746752L               // + xp full-plane items (11,837,440)
#define MS_P2 18665472L               // + h1 uint4 zeros (5,918,720)
#define MS_P3 19257344L               // + hA uint4 zeros (591,872)
#define MS_P4 19849216L               // + hB uint4 zeros (591,872)

__global__ void mega_setup(const float* __restrict__ x,
                           const float* __restrict__ W1, const float* __restrict__ U1,
                           const float* __restrict__ W2, const float* __restrict__ U2,
                           __half* __restrict__ B1x, __half* __restrict__ B1h,
                           __half* __restrict__ B2x, __half* __restrict__ B2h,
                           unsigned* __restrict__ xp,
                           uint4* __restrict__ zh1,
                           uint4* __restrict__ zhA,
                           uint4* __restrict__ zhB)
{
    long stride = (long)gridDim.x * blockDim.x;
    for (long idx = blockIdx.x * (long)blockDim.x + threadIdx.x; idx < MS_P4;
         idx += stride) {
        if (idx < MS_P0) {
            long i = idx;
            if (i < 204800)       prepack_one(i,          W1, B1x, 32, NC1X, 0);
            else if (i < 614400)  prepack_one(i - 204800, U1, B1h, 64, NC1H, 1);
            else if (i < 761856)  prepack_one(i - 614400, W2, B2x, 64, NC2, 0);
            else                  prepack_one(i - 761856, U2, B2h, 64, NC2, 1);
        } else if (idx < MS_P1) {
            long i = idx - MS_P0;
            int plane = (int)(i % PLANE);
            long cb = i / PLANE;               // bt*32 + ch
            int ch = (int)(cb & 31);
            long bt = cb >> 5;
            int y = plane / HR, xx = plane - y * HR;
            unsigned v = 0u;
            if (y >= 2 && y < 66 && xx >= 2 && xx < 66) {
                float f = x[(bt * HWP + (y - 2) * 64 + (xx - 2)) * 32 + ch];
                v = pack_hl(f);
            }
            xp[cb * PLANE + plane] = v;
        } else if (idx < MS_P2) {
            zh1[idx - MS_P1] = make_uint4(0u, 0u, 0u, 0u);
        } else if (idx < MS_P3) {
            zhA[idx - MS_P2] = make_uint4(0u, 0u, 0u, 0u);
        } else {
            zhB[idx - MS_P3] = make_uint4(0u, 0u, 0u, 0u);
        }
    }
}

// ---------------------------------------------------------------------------
// Big-GEMM conv (input part, all timesteps). 256 threads, CTA 128m x 128n,
// 8 warps x (32m x 64n). fp16x2 split (ah*bh + al*bh). Folds bias into zout.
// ---------------------------------------------------------------------------
template<int CIN, int KH, int NCHUNKS>
__global__ void __launch_bounds__(256, 2)
conv_big(const unsigned* __restrict__ src,
         const __half* __restrict__ Bpack,
         const float* __restrict__ bias,
         float* __restrict__ zout)
{
    extern __shared__ char smem[];
    const unsigned sb = smem_u32(smem);
    const int tid = threadIdx.x;
    const int lane = tid & 31, wid = tid >> 5;
    const int n_blk = blockIdx.x;          // 0..1
    const int m0 = blockIdx.y * 128;
    const int bt = m0 >> 12;
    const int y0 = (m0 & 4095) >> 6;
    constexpr int pad = KH >> 1;
    constexpr int HOFF = 2 - pad;

    const unsigned sA0 = sb, sB0 = sb + 32768;

    const int pix = tid & 127;
    const int g = tid >> 7;                // 0/1: channels g*16..g*16+15
    const int prow = (y0 + (pix >> 6)) * HR + (pix & 63);

    const int mw = wid & 3, nw = wid >> 2;
    int offA[2], offB[4];
#pragma unroll
    for (int mf = 0; mf < 2; mf++)
        offA[mf] = (mw * 32 + mf * 16 + (lane & 15)) * 128 + (lane >> 4) * 16;
#pragma unroll
    for (int nf2 = 0; nf2 < 4; nf2++)
        offB[nf2] = (nw * 64 + nf2 * 16 + (lane >> 4) * 8 + (lane & 7)) * 64
                  + ((lane >> 3) & 1) * 16;

    float acc[16][4];
#pragma unroll
    for (int i = 0; i < 16; i++)
#pragma unroll
        for (int j = 0; j < 4; j++) acc[i][j] = 0.f;

    unsigned a[16];

    auto prefA = [&](int kc) {
        int k0 = kc * 32;
        int pos = k0 / CIN;
        int cb = k0 - pos * CIN;
        int ky = pos / KH, kx = pos - ky * KH;
        const unsigned* s = src + ((long)bt * CIN + cb + g * 16) * PLANE
                          + prow + (ky + HOFF) * HR + kx + HOFF;
#pragma unroll
        for (int r = 0; r < 16; r++) a[r] = __ldg(s + (long)r * PLANE);
    };

    auto cpB = [&](int kc, int s) {
        const char* gsrc = (const char*)(Bpack + ((long)n_blk * NCHUNKS + kc) * 4096)
                         + tid * 16;
        unsigned dst = sB0 + s * 8192 + tid * 16;
        CP_ASYNC16(dst, gsrc);
        CP_ASYNC16(dst + 4096, gsrc + 4096);
    };

    auto stageA = [&](int s) {
        unsigned hw[8], lw[8];
#pragma unroll
        for (int j = 0; j < 8; j++) {
            hw[j] = __byte_perm(a[2 * j], a[2 * j + 1], 0x5410);
            lw[j] = __byte_perm(a[2 * j], a[2 * j + 1], 0x7632);
        }
        char* Ab = smem + s * 16384;
        int rb = pix * 128 + g * 32;
#pragma unroll
        for (int q = 0; q < 2; q++) {
            *(uint4*)(Ab + SWZ(rb + q * 16)) =
                make_uint4(hw[q * 4], hw[q * 4 + 1], hw[q * 4 + 2], hw[q * 4 + 3]);
            *(uint4*)(Ab + SWZ(rb + 64 + q * 16)) =
                make_uint4(lw[q * 4], lw[q * 4 + 1], lw[q * 4 + 2], lw[q * 4 + 3]);
        }
    };

    prefA(0);
    cpB(0, 0);
    CP_COMMIT();
    stageA(0);
    CP_WAIT0();
    __syncthreads();

    for (int kt = 0; kt < NCHUNKS; kt++) {
        const int cur = kt & 1;
        const bool more = (kt + 1 < NCHUNKS);
        if (more) {
            prefA(kt + 1);
            cpB(kt + 1, cur ^ 1);
            CP_COMMIT();
        }

        const unsigned a_base = sA0 + cur * 16384;
        const unsigned b_base = sB0 + cur * 8192;
#pragma unroll
        for (int ks = 0; ks < 2; ks++) {
            unsigned bf[4][4];
#pragma unroll
            for (int nf2 = 0; nf2 < 4; nf2++)
                ldsm4(bf[nf2], b_base + SWZ64(offB[nf2] + ks * 32));
#pragma unroll
            for (int term = 0; term < 2; term++) {
                unsigned af[2][4];
                ldsm4(af[0], a_base + SWZ(offA[0] + term * 64 + ks * 32));
                ldsm4(af[1], a_base + SWZ(offA[1] + term * 64 + ks * 32));
#pragma unroll
                for (int nf2 = 0; nf2 < 4; nf2++) {
                    mma_f16(acc[nf2 * 2 + 0],     af[0], bf[nf2][0], bf[nf2][1]);
                    mma_f16(acc[nf2 * 2 + 1],     af[0], bf[nf2][2], bf[nf2][3]);
                    mma_f16(acc[8 + nf2 * 2 + 0], af[1], bf[nf2][0], bf[nf2][1]);
                    mma_f16(acc[8 + nf2 * 2 + 1], af[1], bf[nf2][2], bf[nf2][3]);
                }
            }
        }

        if (more) {
            stageA(cur ^ 1);
            CP_WAIT0();
        }
        __syncthreads();
    }

    // epilogue: + bias (permuted cols), write zout
    const long coff = (long)n_blk * 128 + nw * 64 + (lane & 3) * 2;
    float bb0[8], bb1[8];
#pragma unroll
    for (int nf = 0; nf < 8; nf++) {
        int col = (int)coff + nf * 8;
        bb0[nf] = __ldg(bias + ((col & 3) << 6) + (col >> 2));
        bb1[nf] = __ldg(bias + (((col + 1) & 3) << 6) + ((col + 1) >> 2));
    }
#pragma unroll
    for (int mf = 0; mf < 2; mf++) {
        int ml = mw * 32 + mf * 16 + (lane >> 2);
        float* zr = zout + (long)(m0 + ml) * NCH + coff;
#pragma unroll
        for (int nf = 0; nf < 8; nf++) {
            *(float2*)(zr + nf * 8) = make_float2(
                acc[mf * 8 + nf][0] + bb0[nf], acc[mf * 8 + nf][1] + bb1[nf]);
            *(float2*)(zr + nf * 8 + 8 * NCH) = make_float2(
                acc[mf * 8 + nf][2] + bb0[nf], acc[mf * 8 + nf][3] + bb1[nf]);
        }
    }
}

// ---------------------------------------------------------------------------
// FUSED recurrent step: U*h conv + zx + LSTM gates. 256 threads, occ 2,
// CTA 128m x 128n (grid (2, 256)), 8 warps x (32m x 64n) — same proven
// mainloop shape as conv_big. h ping-pongs across steps. Register-gate
// epilogue via shfl-xor under the permuted-N layout.
// t0 != 0: h_{t-1} == 0 -> skip the GEMM entirely and treat c as 0.
// LAYER==1: write packed h + packed relu(h)->h1seq. LAYER==2: h + NHWC out.
// ---------------------------------------------------------------------------
template<int KH, int NCHUNKS, int LAYER>
__global__ void __launch_bounds__(256, 2)
conv_fused(const unsigned* __restrict__ hin,
           const __half* __restrict__ Bpack,
           const float* __restrict__ zx,
           float* __restrict__ cst,
           unsigned* __restrict__ hout,
           unsigned* __restrict__ h1seq,
           float* __restrict__ outp, int t, int t0)
{
    extern __shared__ char smem[];
    const unsigned sb = smem_u32(smem);
    const int tid = threadIdx.x;
    const int lane = tid & 31, wid = tid >> 5;
    const int n_blk = blockIdx.x;          // 0..1
    const int m0 = blockIdx.y * 128;
    const int b = m0 >> 12;
    const int y0 = (m0 & 4095) >> 6;
    constexpr int CIN = 64;
    constexpr int pad = KH >> 1;
    constexpr int HOFF = 2 - pad;

    const unsigned sA0 = sb, sB0 = sb + 32768;

    const int mw = wid & 3, nw = wid >> 2;

    float acc[16][4];
#pragma unroll
    for (int i = 0; i < 16; i++)
#pragma unroll
        for (int j = 0; j < 4; j++) acc[i][j] = 0.f;

    if (!t0) {
        const int pix = tid & 127;
        const int g = tid >> 7;
        const int prow = (y0 + (pix >> 6)) * HR + (pix & 63);

        int offA[2], offB[4];
#pragma unroll
        for (int mf = 0; mf < 2; mf++)
            offA[mf] = (mw * 32 + mf * 16 + (lane & 15)) * 128 + (lane >> 4) * 16;
#pragma unroll
        for (int nf2 = 0; nf2 < 4; nf2++)
            offB[nf2] = (nw * 64 + nf2 * 16 + (lane >> 4) * 8 + (lane & 7)) * 64
                      + ((lane >> 3) & 1) * 16;

        unsigned a[16];

        auto prefA = [&](int kc) {
            int k0 = kc * 32;
            int pos = k0 / CIN;
            int cb = k0 - pos * CIN;
            int ky = pos / KH, kx = pos - ky * KH;
            const unsigned* s = hin + ((long)b * CIN + cb + g * 16) * PLANE
                              + prow + (ky + HOFF) * HR + kx + HOFF;
#pragma unroll
            for (int r = 0; r < 16; r++) a[r] = __ldg(s + (long)r * PLANE);
        };

        auto cpB = [&](int kc, int s) {
            const char* gsrc = (const char*)(Bpack + ((long)kc * 2 + n_blk) * 4096)
                             + tid * 16;
            unsigned dst = sB0 + s * 8192 + tid * 16;
            CP_ASYNC16(dst, gsrc);
            CP_ASYNC16(dst + 4096, gsrc + 4096);
        };

        auto stageA = [&](int s) {
            unsigned hw[8], lw[8];
#pragma unroll
            for (int j = 0; j < 8; j++) {
                hw[j] = __byte_perm(a[2 * j], a[2 * j + 1], 0x5410);
                lw[j] = __byte_perm(a[2 * j], a[2 * j + 1], 0x7632);
            }
            char* Ab = smem + s * 16384;
            int rb = pix * 128 + g * 32;
#pragma unroll
            for (int q = 0; q < 2; q++) {
                *(uint4*)(Ab + SWZ(rb + q * 16)) =
                    make_uint4(hw[q * 4], hw[q * 4 + 1], hw[q * 4 + 2], hw[q * 4 + 3]);
                *(uint4*)(Ab + SWZ(rb + 64 + q * 16)) =
                    make_uint4(lw[q * 4], lw[q * 4 + 1], lw[q * 4 + 2], lw[q * 4 + 3]);
            }
        };

        prefA(0);
        cpB(0, 0);
        CP_COMMIT();
        stageA(0);
        CP_WAIT0();
        __syncthreads();

        for (int kt = 0; kt < NCHUNKS; kt++) {
            const int cur = kt & 1;
            const bool more = (kt + 1 < NCHUNKS);
            if (more) {
                prefA(kt + 1);
                cpB(kt + 1, cur ^ 1);
                CP_COMMIT();
            }

            const unsigned a_base = sA0 + cur * 16384;
            const unsigned b_base = sB0 + cur * 8192;
#pragma unroll
            for (int ks = 0; ks < 2; ks++) {
                unsigned bf[4][4];
#pragma unroll
                for (int nf2 = 0; nf2 < 4; nf2++)
                    ldsm4(bf[nf2], b_base + SWZ64(offB[nf2] + ks * 32));
#pragma unroll
                for (int term = 0; term < 2; term++) {
                    unsigned af[2][4];
                    ldsm4(af[0], a_base + SWZ(offA[0] + term * 64 + ks * 32));
                    ldsm4(af[1], a_base + SWZ(offA[1] + term * 64 + ks * 32));
#pragma unroll
                    for (int nf2 = 0; nf2 < 4; nf2++) {
                        mma_f16(acc[nf2 * 2 + 0],     af[0], bf[nf2][0], bf[nf2][1]);
                        mma_f16(acc[nf2 * 2 + 1],     af[0], bf[nf2][2], bf[nf2][3]);
                        mma_f16(acc[8 + nf2 * 2 + 0], af[1], bf[nf2][0], bf[nf2][1]);
                        mma_f16(acc[8 + nf2 * 2 + 1], af[1], bf[nf2][2], bf[nf2][3]);
                    }
                }
            }

            if (more) {
                stageA(cur ^ 1);
                CP_WAIT0();
            }
            __syncthreads();
        }
    }

    // ================= register-gate epilogue =================
    // acc[mf*8+nf][0..3] = rows (r, r+8) x cols (col, col+1),
    // col = n_blk*128 + nw*64 + nf*8 + q*2, q = lane&3. q even -> gates (i,f);
    // q odd -> gates (c,o) of the same f. xor-1 partner holds the other pair.
    const float* za = zx + (((long)b * TT + t) * HWP + (m0 & 4095)) * NCH;
    float* hs = (float*)smem;              // LAYER 2: [128][33] relu(h) staging
    const int q = lane & 3;
    const int rq = lane >> 2;
    const bool odd = (q & 1);
#pragma unroll
    for (int mf = 0; mf < 2; mf++) {
        const int rloc = mw * 32 + mf * 16 + rq;
#pragma unroll
        for (int nf = 0; nf < 8; nf++) {
            int coll = nw * 64 + nf * 8 + q * 2;
            int col = n_blk * 128 + coll;
            float2 w0 = *(const float2*)(za + (long)rloc * NCH + col);
            float2 w1 = *(const float2*)(za + (long)(rloc + 8) * NCH + col);
            float z0 = acc[mf * 8 + nf][0] + w0.x;
            float z1 = acc[mf * 8 + nf][1] + w0.y;
            float z2 = acc[mf * 8 + nf][2] + w1.x;
            float z3 = acc[mf * 8 + nf][3] + w1.y;
            float e0 = __shfl_xor_sync(0xFFFFFFFFu, z0, 1);
            float e1 = __shfl_xor_sync(0xFFFFFFFFu, z1, 1);
            float e2 = __shfl_xor_sync(0xFFFFFFFFu, z2, 1);
            float e3 = __shfl_xor_sync(0xFFFFFFFFu, z3, 1);
            float zi = odd ? e2 : z0;
            float zf = odd ? e3 : z1;
            float zc = odd ? z2 : e0;
            float zo = odd ? z3 : e1;
            int pixl = rloc + (odd ? 8 : 0);
            int f = col >> 2;
            int pixg = (m0 & 4095) + pixl;
            long cidx = ((long)b * FF + f) * HWP + pixg;
            float cold = t0 ? 0.f : cst[cidx];
            float cn = hsig(zf) * cold + hsig(zi) * tanhf(zc);
            float hn = hsig(zo) * tanhf(cn);
            cst[cidx] = cn;
            int y = pixg >> 6, xx = pixg & 63;
            int hoffpix = (y + 2) * HR + xx + 2;
            hout[((long)b * FF + f) * PLANE + hoffpix] = pack_hl(hn);
            if (LAYER == 1)
                h1seq[((long)(b * TT + t) * FF + f) * PLANE + hoffpix] =
                    pack_hl(fmaxf(hn, 0.f));
            else
                hs[pixl * 33 + (coll >> 2)] = fmaxf(hn, 0.f);
        }
    }
    if (LAYER == 2) {
        __syncthreads();
        float* ob = outp + ((long)(b * TT + t) * HWP + (m0 & 4095)) * FF
                  + n_blk * 32;
#pragma unroll
        for (int i = 0; i < 16; i++) {
            int e = i * 256 + tid;
            int pixl = e >> 5, fl = e & 31;
            ob[(long)pixl * FF + fl] = hs[pixl * 33 + fl];
        }
    }
}

// ---------------------------------------------------------------------------
extern "C" void kernel_launch(void* const* d_in, const int* in_sizes, int n_in,
                              void* d_out, int out_size)
{
    const float* x   = (const float*)d_in[0];
    const float* Wk1 = (const float*)d_in[1];
    const float* Uk1 = (const float*)d_in[2];
    const float* b1  = (const float*)d_in[3];
    const float* Wk2 = (const float*)d_in[4];
    const float* Uk2 = (const float*)d_in[5];
    const float* b2  = (const float*)d_in[6];
    float* out = (float*)d_out;

    float *zx, *c;
    unsigned *xp, *h1, *hA, *hB;
    __half *B1x, *B1h, *B2x, *B2h;
    cudaGetSymbolAddress((void**)&zx, g_zx);
    cudaGetSymbolAddress((void**)&xp, g_xp);
    cudaGetSymbolAddress((void**)&h1, g_h1);
    cudaGetSymbolAddress((void**)&hA, g_hA);
    cudaGetSymbolAddress((void**)&hB, g_hB);
    cudaGetSymbolAddress((void**)&c,  g_c);
    cudaGetSymbolAddress((void**)&B1x, g_B1x);
    cudaGetSymbolAddress((void**)&B1h, g_B1h);
    cudaGetSymbolAddress((void**)&B2x, g_B2x);
    cudaGetSymbolAddress((void**)&B2h, g_B2h);

    static int smem_set = 0;
    if (!smem_set) {
        cudaFuncSetAttribute(conv_big<32, 5, NC1X>,
                             cudaFuncAttributeMaxDynamicSharedMemorySize, SM_BIG);
        cudaFuncSetAttribute(conv_big<64, 3, NC2>,
                             cudaFuncAttributeMaxDynamicSharedMemorySize, SM_BIG);
        cudaFuncSetAttribute(conv_fused<5, NC1H, 1>,
                             cudaFuncAttributeMaxDynamicSharedMemorySize, SM_BIG);
        cudaFuncSetAttribute(conv_fused<3, NC2, 2>,
                             cudaFuncAttributeMaxDynamicSharedMemorySize, SM_BIG);
        smem_set = 1;
    }

    const dim3 gridBig(2, M_BIG / 128);   // (2, 2560)
    const dim3 gridRec(2, M_TOTAL / 128); // (2, 256)

    // Launch order (ncu captures index 3):
    // [0] mega_setup, [1] conv_big L1, [2] fused L1 t=0 (GEMM skipped),
    // [3] fused L1 t=1  <-- PROFILED (representative recurrent step)
    mega_setup<<<2048, 256>>>(x, Wk1, Uk1, Wk2, Uk2,
                              B1x, B1h, B2x, B2h,
                              xp, (uint4*)h1, (uint4*)hA, (uint4*)hB);
    conv_big<32, 5, NC1X><<<gridBig, 256, SM_BIG>>>(xp, B1x, b1, zx);

    // ---- Layer 1 recurrence (fused conv+gates, ping-pong h) ----
    for (int t = 0; t < TT; t++) {
        unsigned* hin  = (t & 1) ? hB : hA;
        unsigned* hout = (t & 1) ? hA : hB;
        conv_fused<5, NC1H, 1><<<gridRec, 256, SM_BIG>>>(
            hin, B1h, zx, c, hout, h1, nullptr, t, t == 0);
    }

    // ---- Layer 2 ----
    conv_big<64, 3, NC2><<<gridBig, 256, SM_BIG>>>(h1, B2x, b2, zx);
    for (int t = 0; t < TT; t++) {
        unsigned* hin  = (t & 1) ? hB : hA;
        unsigned* hout = (t & 1) ? hA : hB;
        conv_fused<3, NC2, 2><<<gridRec, 256, SM_BIG>>>(
            hin, B2h, zx, c, hout, nullptr, out, t, t == 0);
    }
}

// round 14
// speedup vs baseline: 1.3264x; 1.0862x over previous
#include <cuda_runtime.h>
#include <cuda_fp16.h>
#include <math.h>

// Problem constants
#define BB 8
#define TT 10
#define HH 64
#define WW 64
#define HWP 4096           // H*W
#define FF 64
#define NCH 256            // 4*F
#define M_TOTAL (BB*HWP)   // 32768
#define M_BIG   (BB*TT*HWP) // 327680

// Planar halo layout: 2-pixel border on each side
#define HR 68
#define PLANE (HR*HR)      // 4624 per channel plane

// K chunk = 32 fp32 channels -> 64 fp16 cols in A (ah|al), 32 fp16 in B (bh)
#define NC1X 25            // layer1 x-part:  K=800  (25 taps x 32ch) /32
#define NC1H 50            // layer1 h-part:  K=1600 (25 x 64) /32
#define NC2  18            // layer2 x/h:     K=576  (9 x 64) /32

#define SM_BIG 49152       // A[2][16K] + B[2][8K] (both GEMM kernels)

// N-column permutation: GEMM column n' carries f = n'>>2, gate = n'&3.

// Scratch (static device globals; no allocation allowed)
// Activation planes are packed u32 = fp16(hi) | fp16(lo)<<16  (hi+lo == fp32)
__device__ float    g_zx[(long)M_BIG * NCH];            // L1: W1*x + b1 (all t)
__device__ float    g_zx2[(long)M_TOTAL * NCH];         // L2: W2*h1_t + b2 (per t)
__device__ unsigned g_xp[(long)BB * TT * 32 * PLANE];   // x planar+halo packed
__device__ unsigned g_h1[(long)BB * TT * FF * PLANE];   // relu(h) seq L1, packed
__device__ unsigned g_hA1[(long)BB * FF * PLANE];       // L1 hidden ping
__device__ unsigned g_hB1[(long)BB * FF * PLANE];       // L1 hidden pong
__device__ unsigned g_hA2[(long)BB * FF * PLANE];       // L2 hidden ping
__device__ unsigned g_hB2[(long)BB * FF * PLANE];       // L2 hidden pong
__device__ float    g_c1[(long)BB * FF * HWP];          // L1 cell state
__device__ float    g_c2[(long)BB * FF * HWP];          // L2 cell state
__device__ __half g_B1x[(long)2 * NC1X * 4096];         // big-GEMM tiles [nb][kc]
__device__ __half g_B1h[(long)2 * NC1H * 4096];         // fused tiles   [kc][nb]
__device__ __half g_B2x[(long)2 * NC2 * 4096];          // big-GEMM tiles [nb][kc]
__device__ __half g_B2h[(long)2 * NC2 * 4096];          // fused tiles   [kc][nb]

// ---------------------------------------------------------------------------
// Helpers (sm_80-baseline PTX only — harness targets family-generic sm_103)
// ---------------------------------------------------------------------------
__device__ __forceinline__ unsigned smem_u32(const void* p) {
    unsigned r;
    asm("{ .reg .u64 t; cvta.to.shared.u64 t, %1; cvt.u32.u64 %0, t; }"
        : "=r"(r) : "l"(p));
    return r;
}
__device__ __forceinline__ unsigned pack_hl(float f) {
    __half h = __float2half_rn(f);
    float r = f - __half2float(h);
    return (unsigned)__half_as_ushort(h)
         | ((unsigned)__half_as_ushort(__float2half_rn(r)) << 16);
}
__device__ __forceinline__ void ldsm4(unsigned* r, unsigned addr) {
    asm volatile("ldmatrix.sync.aligned.m8n8.x4.shared.b16 {%0,%1,%2,%3}, [%4];"
                 : "=r"(r[0]), "=r"(r[1]), "=r"(r[2]), "=r"(r[3]) : "r"(addr));
}
__device__ __forceinline__ void mma_f16(float* c, const unsigned* a,
                                        unsigned b0, unsigned b1) {
    asm volatile(
        "mma.sync.aligned.m16n8k16.row.col.f32.f16.f16.f32 "
        "{%0,%1,%2,%3}, {%4,%5,%6,%7}, {%8,%9}, {%0,%1,%2,%3};"
        : "+f"(c[0]), "+f"(c[1]), "+f"(c[2]), "+f"(c[3])
        : "r"(a[0]), "r"(a[1]), "r"(a[2]), "r"(a[3]), "r"(b0), "r"(b1));
}
#define CP_ASYNC16(dst, src) \
    asm volatile("cp.async.cg.shared.global [%0], [%1], 16;" \
                 :: "r"(dst), "l"(src))
#define CP_COMMIT() asm volatile("cp.async.commit_group;" ::: "memory")
#define CP_WAIT0()  asm volatile("cp.async.wait_group 0;" ::: "memory")

#define SWZ(off)   ((off) ^ (((off) >> 3) & 0x70))   // 128B-row swizzle (A)
#define SWZ64(off) ((off) ^ (((off) >> 3) & 0x30))   // 64B-row swizzle (B)

__device__ __forceinline__ float hsig(float v)
{
    return fminf(fmaxf(0.2f * v + 0.5f, 0.f), 1.f);
}

// ---------------------------------------------------------------------------
// Prepack weights into permuted-N 8KB tiles (128 N-rows x 32 fp16, 64B rows,
// SWZ64). GEMM col n' reads original weight col (n'&3)*64 + (n'>>2).
// Tile order: big GEMM = [nb][kc]; fused = [kc][nb].
// ---------------------------------------------------------------------------
__device__ __forceinline__ void prepack_one(long idx, const float* __restrict__ W,
                                            __half* __restrict__ Bp, int Cin,
                                            int nch, int fused)
{
    int j = (int)(idx & 31);
    long r = idx >> 5;
    int nrow = (int)(r & 127);
    r >>= 7;
    int kc = (int)(r % nch);
    int nb = (int)(r / nch);
    int k = kc * 32 + j;
    int pos = k / Cin, c = k % Cin;
    int n = nb * 128 + nrow;                    // permuted column index
    int worig = ((n & 3) << 6) + (n >> 2);      // gate*64 + f
    float w = W[((long)pos * Cin + c) * NCH + worig];
    int inb = nrow * 64 + j * 2;
    int sw = SWZ64(inb);
    long tile = fused ? (long)(kc * 2 + nb) : (long)(nb * nch + kc);
    Bp[tile * 4096 + (sw >> 1)] = __float2half_rn(w);
}

// ---------------------------------------------------------------------------
// mega_setup: prepack + x transpose (halo zero-fill) + zero h1/hA1/hB1/hA2/hB2
// ---------------------------------------------------------------------------
#define MS_P0 909312L
#define MS_P1 12746752L               // + xp items (11,837,440)
#define MS_P2 18665472L               // + h1 uint4 (5,918,720)
#define MS_P3 19257344L               // + hA1 uint4 (591,872)
#define MS_P4 19849216L               // + hB1
#define MS_P5 20441088L               // + hA2
#define MS_P6 21032960L               // + hB2

__global__ void mega_setup(const float* __restrict__ x,
                           const float* __restrict__ W1, const float* __restrict__ U1,
                           const float* __restrict__ W2, const float* __restrict__ U2,
                           __half* __restrict__ B1x, __half* __restrict__ B1h,
                           __half* __restrict__ B2x, __half* __restrict__ B2h,
                           unsigned* __restrict__ xp,
                           uint4* __restrict__ zh1,
                           uint4* __restrict__ zhA1, uint4* __restrict__ zhB1,
                           uint4* __restrict__ zhA2, uint4* __restrict__ zhB2)
{
    long stride = (long)gridDim.x * blockDim.x;
    for (long idx = blockIdx.x * (long)blockDim.x + threadIdx.x; idx < MS_P6;
         idx += stride) {
        if (idx < MS_P0) {
            long i = idx;
            if (i < 204800)       prepack_one(i,          W1, B1x, 32, NC1X, 0);
            else if (i < 614400)  prepack_one(i - 204800, U1, B1h, 64, NC1H, 1);
            else if (i < 761856)  prepack_one(i - 614400, W2, B2x, 64, NC2, 0);
            else                  prepack_one(i - 761856, U2, B2h, 64, NC2, 1);
        } else if (idx < MS_P1) {
            long i = idx - MS_P0;
            int plane = (int)(i % PLANE);
            long cb = i / PLANE;               // bt*32 + ch
            int ch = (int)(cb & 31);
            long bt = cb >> 5;
            int y = plane / HR, xx = plane - y * HR;
            unsigned v = 0u;
            if (y >= 2 && y < 66 && xx >= 2 && xx < 66) {
                float f = x[(bt * HWP + (y - 2) * 64 + (xx - 2)) * 32 + ch];
                v = pack_hl(f);
            }
            xp[cb * PLANE + plane] = v;
        } else if (idx < MS_P2) {
            zh1[idx - MS_P1] = make_uint4(0u, 0u, 0u, 0u);
        } else if (idx < MS_P3) {
            zhA1[idx - MS_P2] = make_uint4(0u, 0u, 0u, 0u);
        } else if (idx < MS_P4) {
            zhB1[idx - MS_P3] = make_uint4(0u, 0u, 0u, 0u);
        } else if (idx < MS_P5) {
            zhA2[idx - MS_P4] = make_uint4(0u, 0u, 0u, 0u);
        } else {
            zhB2[idx - MS_P5] = make_uint4(0u, 0u, 0u, 0u);
        }
    }
}

// ---------------------------------------------------------------------------
// Input-part GEMM conv. 256 threads, CTA 128m x 128n, 8 warps x (32m x 64n).
// fp16x2 split (ah*bh + al*bh). Folds bias into zout.
// STEP=false: m over M_BIG (all timesteps), src plane index bt = m>>12.
// STEP=true : m over M_TOTAL (one timestep t), src bt = (m>>12)*TT + t,
//             zout compact [M_TOTAL x NCH].
// ---------------------------------------------------------------------------
template<int CIN, int KH, int NCHUNKS, bool STEP>
__global__ void __launch_bounds__(256, 2)
conv_big(const unsigned* __restrict__ src,
         const __half* __restrict__ Bpack,
         const float* __restrict__ bias,
         float* __restrict__ zout, int t)
{
    extern __shared__ char smem[];
    const unsigned sb = smem_u32(smem);
    const int tid = threadIdx.x;
    const int lane = tid & 31, wid = tid >> 5;
    const int n_blk = blockIdx.x;          // 0..1
    const int m0 = blockIdx.y * 128;
    const int bt = STEP ? ((m0 >> 12) * TT + t) : (m0 >> 12);
    const int y0 = (m0 & 4095) >> 6;
    constexpr int pad = KH >> 1;
    constexpr int HOFF = 2 - pad;

    const unsigned sA0 = sb, sB0 = sb + 32768;

    const int pix = tid & 127;
    const int g = tid >> 7;                // 0/1: channels g*16..g*16+15
    const int prow = (y0 + (pix >> 6)) * HR + (pix & 63);

    const int mw = wid & 3, nw = wid >> 2;
    int offA[2], offB[4];
#pragma unroll
    for (int mf = 0; mf < 2; mf++)
        offA[mf] = (mw * 32 + mf * 16 + (lane & 15)) * 128 + (lane >> 4) * 16;
#pragma unroll
    for (int nf2 = 0; nf2 < 4; nf2++)
        offB[nf2] = (nw * 64 + nf2 * 16 + (lane >> 4) * 8 + (lane & 7)) * 64
                  + ((lane >> 3) & 1) * 16;

    float acc[16][4];
#pragma unroll
    for (int i = 0; i < 16; i++)
#pragma unroll
        for (int j = 0; j < 4; j++) acc[i][j] = 0.f;

    unsigned a[16];

    auto prefA = [&](int kc) {
        int k0 = kc * 32;
        int pos = k0 / CIN;
        int cb = k0 - pos * CIN;
        int ky = pos / KH, kx = pos - ky * KH;
        const unsigned* s = src + ((long)bt * CIN + cb + g * 16) * PLANE
                          + prow + (ky + HOFF) * HR + kx + HOFF;
#pragma unroll
        for (int r = 0; r < 16; r++) a[r] = __ldg(s + (long)r * PLANE);
    };

    auto cpB = [&](int kc, int s) {
        const char* gsrc = (const char*)(Bpack + ((long)n_blk * NCHUNKS + kc) * 4096)
                         + tid * 16;
        unsigned dst = sB0 + s * 8192 + tid * 16;
        CP_ASYNC16(dst, gsrc);
        CP_ASYNC16(dst + 4096, gsrc + 4096);
    };

    auto stageA = [&](int s) {
        unsigned hw[8], lw[8];
#pragma unroll
        for (int j = 0; j < 8; j++) {
            hw[j] = __byte_perm(a[2 * j], a[2 * j + 1], 0x5410);
            lw[j] = __byte_perm(a[2 * j], a[2 * j + 1], 0x7632);
        }
        char* Ab = smem + s * 16384;
        int rb = pix * 128 + g * 32;
#pragma unroll
        for (int q = 0; q < 2; q++) {
            *(uint4*)(Ab + SWZ(rb + q * 16)) =
                make_uint4(hw[q * 4], hw[q * 4 + 1], hw[q * 4 + 2], hw[q * 4 + 3]);
            *(uint4*)(Ab + SWZ(rb + 64 + q * 16)) =
                make_uint4(lw[q * 4], lw[q * 4 + 1], lw[q * 4 + 2], lw[q * 4 + 3]);
        }
    };

    prefA(0);
    cpB(0, 0);
    CP_COMMIT();
    stageA(0);
    CP_WAIT0();
    __syncthreads();

    for (int kt = 0; kt < NCHUNKS; kt++) {
        const int cur = kt & 1;
        const bool more = (kt + 1 < NCHUNKS);
        if (more) {
            prefA(kt + 1);
            cpB(kt + 1, cur ^ 1);
            CP_COMMIT();
        }

        const unsigned a_base = sA0 + cur * 16384;
        const unsigned b_base = sB0 + cur * 8192;
#pragma unroll
        for (int ks = 0; ks < 2; ks++) {
            unsigned bf[4][4];
#pragma unroll
            for (int nf2 = 0; nf2 < 4; nf2++)
                ldsm4(bf[nf2], b_base + SWZ64(offB[nf2] + ks * 32));
#pragma unroll
            for (int term = 0; term < 2; term++) {
                unsigned af[2][4];
                ldsm4(af[0], a_base + SWZ(offA[0] + term * 64 + ks * 32));
                ldsm4(af[1], a_base + SWZ(offA[1] + term * 64 + ks * 32));
#pragma unroll
                for (int nf2 = 0; nf2 < 4; nf2++) {
                    mma_f16(acc[nf2 * 2 + 0],     af[0], bf[nf2][0], bf[nf2][1]);
                    mma_f16(acc[nf2 * 2 + 1],     af[0], bf[nf2][2], bf[nf2][3]);
                    mma_f16(acc[8 + nf2 * 2 + 0], af[1], bf[nf2][0], bf[nf2][1]);
                    mma_f16(acc[8 + nf2 * 2 + 1], af[1], bf[nf2][2], bf[nf2][3]);
                }
            }
        }

        if (more) {
            stageA(cur ^ 1);
            CP_WAIT0();
        }
        __syncthreads();
    }

    // epilogue: + bias (permuted cols), write zout
    const long coff = (long)n_blk * 128 + nw * 64 + (lane & 3) * 2;
    float bb0[8], bb1[8];
#pragma unroll
    for (int nf = 0; nf < 8; nf++) {
        int col = (int)coff + nf * 8;
        bb0[nf] = __ldg(bias + ((col & 3) << 6) + (col >> 2));
        bb1[nf] = __ldg(bias + (((col + 1) & 3) << 6) + ((col + 1) >> 2));
    }
#pragma unroll
    for (int mf = 0; mf < 2; mf++) {
        int ml = mw * 32 + mf * 16 + (lane >> 2);
        float* zr = zout + (long)(m0 + ml) * NCH + coff;
#pragma unroll
        for (int nf = 0; nf < 8; nf++) {
            *(float2*)(zr + nf * 8) = make_float2(
                acc[mf * 8 + nf][0] + bb0[nf], acc[mf * 8 + nf][1] + bb1[nf]);
            *(float2*)(zr + nf * 8 + 8 * NCH) = make_float2(
                acc[mf * 8 + nf][2] + bb0[nf], acc[mf * 8 + nf][3] + bb1[nf]);
        }
    }
}

// ---------------------------------------------------------------------------
// FUSED recurrent step: U*h conv + z-add + LSTM gates. 256 threads, occ 2,
// CTA 128m x 128n (grid (2, 256)). h ping-pongs across steps. Register-gate
// epilogue via shfl-xor (permuted-N). z-add row = b*zstrb + zoff + pix.
// t0: h_{t-1}==0 -> skip GEMM, treat c as 0.
// ---------------------------------------------------------------------------
template<int KH, int NCHUNKS, int LAYER>
__global__ void __launch_bounds__(256, 2)
conv_fused(const unsigned* __restrict__ hin,
           const __half* __restrict__ Bpack,
           const float* __restrict__ zx, long zstrb, long zoff,
           float* __restrict__ cst,
           unsigned* __restrict__ hout,
           unsigned* __restrict__ h1seq,
           float* __restrict__ outp, int t, int t0)
{
    extern __shared__ char smem[];
    const unsigned sb = smem_u32(smem);
    const int tid = threadIdx.x;
    const int lane = tid & 31, wid = tid >> 5;
    const int n_blk = blockIdx.x;          // 0..1
    const int m0 = blockIdx.y * 128;
    const int b = m0 >> 12;
    const int y0 = (m0 & 4095) >> 6;
    constexpr int CIN = 64;
    constexpr int pad = KH >> 1;
    constexpr int HOFF = 2 - pad;

    const unsigned sA0 = sb, sB0 = sb + 32768;

    const int mw = wid & 3, nw = wid >> 2;

    float acc[16][4];
#pragma unroll
    for (int i = 0; i < 16; i++)
#pragma unroll
        for (int j = 0; j < 4; j++) acc[i][j] = 0.f;

    if (!t0) {
        const int pix = tid & 127;
        const int g = tid >> 7;
        const int prow = (y0 + (pix >> 6)) * HR + (pix & 63);

        int offA[2], offB[4];
#pragma unroll
        for (int mf = 0; mf < 2; mf++)
            offA[mf] = (mw * 32 + mf * 16 + (lane & 15)) * 128 + (lane >> 4) * 16;
#pragma unroll
        for (int nf2 = 0; nf2 < 4; nf2++)
            offB[nf2] = (nw * 64 + nf2 * 16 + (lane >> 4) * 8 + (lane & 7)) * 64
                      + ((lane >> 3) & 1) * 16;

        unsigned a[16];

        auto prefA = [&](int kc) {
            int k0 = kc * 32;
            int pos = k0 / CIN;
            int cb = k0 - pos * CIN;
            int ky = pos / KH, kx = pos - ky * KH;
            const unsigned* s = hin + ((long)b * CIN + cb + g * 16) * PLANE
                              + prow + (ky + HOFF) * HR + kx + HOFF;
#pragma unroll
            for (int r = 0; r < 16; r++) a[r] = __ldg(s + (long)r * PLANE);
        };

        auto cpB = [&](int kc, int s) {
            const char* gsrc = (const char*)(Bpack + ((long)kc * 2 + n_blk) * 4096)
                             + tid * 16;
            unsigned dst = sB0 + s * 8192 + tid * 16;
            CP_ASYNC16(dst, gsrc);
            CP_ASYNC16(dst + 4096, gsrc + 4096);
        };

        auto stageA = [&](int s) {
            unsigned hw[8], lw[8];
#pragma unroll
            for (int j = 0; j < 8; j++) {
                hw[j] = __byte_perm(a[2 * j], a[2 * j + 1], 0x5410);
                lw[j] = __byte_perm(a[2 * j], a[2 * j + 1], 0x7632);
            }
            char* Ab = smem + s * 16384;
            int rb = pix * 128 + g * 32;
#pragma unroll
            for (int q = 0; q < 2; q++) {
                *(uint4*)(Ab + SWZ(rb + q * 16)) =
                    make_uint4(hw[q * 4], hw[q * 4 + 1], hw[q * 4 + 2], hw[q * 4 + 3]);
                *(uint4*)(Ab + SWZ(rb + 64 + q * 16)) =
                    make_uint4(lw[q * 4], lw[q * 4 + 1], lw[q * 4 + 2], lw[q * 4 + 3]);
            }
        };

        prefA(0);
        cpB(0, 0);
        CP_COMMIT();
        stageA(0);
        CP_WAIT0();
        __syncthreads();

        for (int kt = 0; kt < NCHUNKS; kt++) {
            const int cur = kt & 1;
            const bool more = (kt + 1 < NCHUNKS);
            if (more) {
                prefA(kt + 1);
                cpB(kt + 1, cur ^ 1);
                CP_COMMIT();
            }

            const unsigned a_base = sA0 + cur * 16384;
            const unsigned b_base = sB0 + cur * 8192;
#pragma unroll
            for (int ks = 0; ks < 2; ks++) {
                unsigned bf[4][4];
#pragma unroll
                for (int nf2 = 0; nf2 < 4; nf2++)
                    ldsm4(bf[nf2], b_base + SWZ64(offB[nf2] + ks * 32));
#pragma unroll
                for (int term = 0; term < 2; term++) {
                    unsigned af[2][4];
                    ldsm4(af[0], a_base + SWZ(offA[0] + term * 64 + ks * 32));
                    ldsm4(af[1], a_base + SWZ(offA[1] + term * 64 + ks * 32));
#pragma unroll
                    for (int nf2 = 0; nf2 < 4; nf2++) {
                        mma_f16(acc[nf2 * 2 + 0],     af[0], bf[nf2][0], bf[nf2][1]);
                        mma_f16(acc[nf2 * 2 + 1],     af[0], bf[nf2][2], bf[nf2][3]);
                        mma_f16(acc[8 + nf2 * 2 + 0], af[1], bf[nf2][0], bf[nf2][1]);
                        mma_f16(acc[8 + nf2 * 2 + 1], af[1], bf[nf2][2], bf[nf2][3]);
                    }
                }
            }

            if (more) {
                stageA(cur ^ 1);
                CP_WAIT0();
            }
            __syncthreads();
        }
    }

    // ================= register-gate epilogue =================
    const float* za = zx + ((long)b * zstrb + zoff + (m0 & 4095)) * NCH;
    float* hs = (float*)smem;              // LAYER 2: [128][33] relu(h) staging
    const int q = lane & 3;
    const int rq = lane >> 2;
    const bool odd = (q & 1);
#pragma unroll
    for (int mf = 0; mf < 2; mf++) {
        const int rloc = mw * 32 + mf * 16 + rq;
#pragma unroll
        for (int nf = 0; nf < 8; nf++) {
            int coll = nw * 64 + nf * 8 + q * 2;
            int col = n_blk * 128 + coll;
            float2 w0 = *(const float2*)(za + (long)rloc * NCH + col);
            float2 w1 = *(const float2*)(za + (long)(rloc + 8) * NCH + col);
            float z0 = acc[mf * 8 + nf][0] + w0.x;
            float z1 = acc[mf * 8 + nf][1] + w0.y;
            float z2 = acc[mf * 8 + nf][2] + w1.x;
            float z3 = acc[mf * 8 + nf][3] + w1.y;
            float e0 = __shfl_xor_sync(0xFFFFFFFFu, z0, 1);
            float e1 = __shfl_xor_sync(0xFFFFFFFFu, z1, 1);
            float e2 = __shfl_xor_sync(0xFFFFFFFFu, z2, 1);
            float e3 = __shfl_xor_sync(0xFFFFFFFFu, z3, 1);
            float zi = odd ? e2 : z0;
            float zf = odd ? e3 : z1;
            float zc = odd ? z2 : e0;
            float zo = odd ? z3 : e1;
            int pixl = rloc + (odd ? 8 : 0);
            int f = col >> 2;
            int pixg = (m0 & 4095) + pixl;
            long cidx = ((long)b * FF + f) * HWP + pixg;
            float cold = t0 ? 0.f : cst[cidx];
            float cn = hsig(zf) * cold + hsig(zi) * tanhf(zc);
            float hn = hsig(zo) * tanhf(cn);
            cst[cidx] = cn;
            int y = pixg >> 6, xx = pixg & 63;
            int hoffpix = (y + 2) * HR + xx + 2;
            hout[((long)b * FF + f) * PLANE + hoffpix] = pack_hl(hn);
            if (LAYER == 1)
                h1seq[((long)(b * TT + t) * FF + f) * PLANE + hoffpix] =
                    pack_hl(fmaxf(hn, 0.f));
            else
                hs[pixl * 33 + (coll >> 2)] = fmaxf(hn, 0.f);
        }
    }
    if (LAYER == 2) {
        __syncthreads();
        float* ob = outp + ((long)(b * TT + t) * HWP + (m0 & 4095)) * FF
                  + n_blk * 32;
#pragma unroll
        for (int i = 0; i < 16; i++) {
            int e = i * 256 + tid;
            int pixl = e >> 5, fl = e & 31;
            ob[(long)pixl * FF + fl] = hs[pixl * 33 + fl];
        }
    }
}

// ---------------------------------------------------------------------------
extern "C" void kernel_launch(void* const* d_in, const int* in_sizes, int n_in,
                              void* d_out, int out_size)
{
    const float* x   = (const float*)d_in[0];
    const float* Wk1 = (const float*)d_in[1];
    const float* Uk1 = (const float*)d_in[2];
    const float* b1  = (const float*)d_in[3];
    const float* Wk2 = (const float*)d_in[4];
    const float* Uk2 = (const float*)d_in[5];
    const float* b2  = (const float*)d_in[6];
    float* out = (float*)d_out;

    float *zx, *zx2, *c1, *c2;
    unsigned *xp, *h1, *hA1, *hB1, *hA2, *hB2;
    __half *B1x, *B1h, *B2x, *B2h;
    cudaGetSymbolAddress((void**)&zx,  g_zx);
    cudaGetSymbolAddress((void**)&zx2, g_zx2);
    cudaGetSymbolAddress((void**)&xp,  g_xp);
    cudaGetSymbolAddress((void**)&h1,  g_h1);
    cudaGetSymbolAddress((void**)&hA1, g_hA1);
    cudaGetSymbolAddress((void**)&hB1, g_hB1);
    cudaGetSymbolAddress((void**)&hA2, g_hA2);
    cudaGetSymbolAddress((void**)&hB2, g_hB2);
    cudaGetSymbolAddress((void**)&c1,  g_c1);
    cudaGetSymbolAddress((void**)&c2,  g_c2);
    cudaGetSymbolAddress((void**)&B1x, g_B1x);
    cudaGetSymbolAddress((void**)&B1h, g_B1h);
    cudaGetSymbolAddress((void**)&B2x, g_B2x);
    cudaGetSymbolAddress((void**)&B2h, g_B2h);

    static int inited = 0;
    static cudaStream_t s2;
    static cudaEvent_t evL1[TT], evJoin;
    if (!inited) {
        cudaFuncSetAttribute(conv_big<32, 5, NC1X, false>,
                             cudaFuncAttributeMaxDynamicSharedMemorySize, SM_BIG);
        cudaFuncSetAttribute(conv_big<64, 3, NC2, true>,
                             cudaFuncAttributeMaxDynamicSharedMemorySize, SM_BIG);
        cudaFuncSetAttribute(conv_fused<5, NC1H, 1>,
                             cudaFuncAttributeMaxDynamicSharedMemorySize, SM_BIG);
        cudaFuncSetAttribute(conv_fused<3, NC2, 2>,
                             cudaFuncAttributeMaxDynamicSharedMemorySize, SM_BIG);
        cudaStreamCreateWithFlags(&s2, cudaStreamNonBlocking);
        for (int i = 0; i < TT; i++)
            cudaEventCreateWithFlags(&evL1[i], cudaEventDisableTiming);
        cudaEventCreateWithFlags(&evJoin, cudaEventDisableTiming);
        inited = 1;
    }

    const dim3 gridBig(2, M_BIG / 128);   // (2, 2560)
    const dim3 gridRec(2, M_TOTAL / 128); // (2, 256)

    // Stream 0: setup, L1 input GEMM, L1 recurrent chain (events per step).
    // Stream 2: per-step W2*h1_t GEMM + L2 recurrent step, overlapped with L1.
    mega_setup<<<2048, 256>>>(x, Wk1, Uk1, Wk2, Uk2,
                              B1x, B1h, B2x, B2h,
                              xp, (uint4*)h1,
                              (uint4*)hA1, (uint4*)hB1,
                              (uint4*)hA2, (uint4*)hB2);
    conv_big<32, 5, NC1X, false><<<gridBig, 256, SM_BIG>>>(xp, B1x, b1, zx, 0);

    for (int t = 0; t < TT; t++) {
        unsigned* hin1  = (t & 1) ? hB1 : hA1;
        unsigned* hout1 = (t & 1) ? hA1 : hB1;
        conv_fused<5, NC1H, 1><<<gridRec, 256, SM_BIG>>>(
            hin1, B1h, zx, (long)TT * HWP, (long)t * HWP,
            c1, hout1, h1, nullptr, t, t == 0);
        cudaEventRecord(evL1[t], 0);

        cudaStreamWaitEvent(s2, evL1[t], 0);
        conv_big<64, 3, NC2, true><<<gridRec, 256, SM_BIG, s2>>>(
            h1, B2x, b2, zx2, t);
        unsigned* hin2  = (t & 1) ? hB2 : hA2;
        unsigned* hout2 = (t & 1) ? hA2 : hB2;
        conv_fused<3, NC2, 2><<<gridRec, 256, SM_BIG, s2>>>(
            hin2, B2h, zx2, (long)HWP, 0L,
            c2, hout2, nullptr, out, t, t == 0);
    }

    cudaEventRecord(evJoin, s2);
    cudaStreamWaitEvent(0, evJoin, 0);
}

// round 15
// speedup vs baseline: 1.3523x; 1.0195x over previous
#include <cuda_runtime.h>
#include <cuda_fp16.h>
#include <math.h>

// Problem constants
#define BB 8
#define TT 10
#define HH 64
#define WW 64
#define HWP 4096           // H*W
#define FF 64
#define NCH 256            // 4*F
#define M_TOTAL (BB*HWP)   // 32768

// Planar halo layout: 2-pixel border on each side
#define HR 68
#define PLANE (HR*HR)      // 4624 per channel plane

// K chunk = 32 fp32 channels -> 64 fp16 cols in A (ah|al), 32 fp16 in B (bh)
#define NC1X 25            // layer1 x-part:  K=800  (25 taps x 32ch) /32
#define NC1H 50            // layer1 h-part:  K=1600 (25 x 64) /32
#define NC2  18            // layer2 x/h:     K=576  (9 x 64) /32

#define SM_BIG 49152       // A[2][16K] + B[2][8K] (both GEMM kernels)

// N-column permutation: GEMM column n' carries f = n'>>2, gate = n'&3.

// Scratch (static device globals; no allocation allowed)
// Activation planes are packed u32 = fp16(hi) | fp16(lo)<<16  (hi+lo == fp32)
__device__ float    g_zx[(long)BB * TT * HWP * NCH];    // L1: W1*x + b1 (all t)
__device__ float    g_zx2[(long)M_TOTAL * NCH];         // L2: W2*h1_t + b2 (per t)
__device__ unsigned g_xp[(long)BB * TT * 32 * PLANE];   // x planar+halo packed
__device__ unsigned g_h1[(long)BB * TT * FF * PLANE];   // relu(h) seq L1, packed
__device__ unsigned g_hA1[(long)BB * FF * PLANE];       // L1 hidden ping
__device__ unsigned g_hB1[(long)BB * FF * PLANE];       // L1 hidden pong
__device__ unsigned g_hA2[(long)BB * FF * PLANE];       // L2 hidden ping
__device__ unsigned g_hB2[(long)BB * FF * PLANE];       // L2 hidden pong
__device__ float    g_c1[(long)BB * FF * HWP];          // L1 cell state
__device__ float    g_c2[(long)BB * FF * HWP];          // L2 cell state
__device__ __half g_B1x[(long)2 * NC1X * 4096];         // per-step GEMM [nb][kc]
__device__ __half g_B1h[(long)2 * NC1H * 4096];         // fused tiles   [kc][nb]
__device__ __half g_B2x[(long)2 * NC2 * 4096];          // per-step GEMM [nb][kc]
__device__ __half g_B2h[(long)2 * NC2 * 4096];          // fused tiles   [kc][nb]

// ---------------------------------------------------------------------------
// Helpers (sm_80-baseline PTX only — harness targets family-generic sm_103)
// ---------------------------------------------------------------------------
__device__ __forceinline__ unsigned smem_u32(const void* p) {
    unsigned r;
    asm("{ .reg .u64 t; cvta.to.shared.u64 t, %1; cvt.u32.u64 %0, t; }"
        : "=r"(r) : "l"(p));
    return r;
}
__device__ __forceinline__ unsigned pack_hl(float f) {
    __half h = __float2half_rn(f);
    float r = f - __half2float(h);
    return (unsigned)__half_as_ushort(h)
         | ((unsigned)__half_as_ushort(__float2half_rn(r)) << 16);
}
__device__ __forceinline__ void ldsm4(unsigned* r, unsigned addr) {
    asm volatile("ldmatrix.sync.aligned.m8n8.x4.shared.b16 {%0,%1,%2,%3}, [%4];"
                 : "=r"(r[0]), "=r"(r[1]), "=r"(r[2]), "=r"(r[3]) : "r"(addr));
}
__device__ __forceinline__ void mma_f16(float* c, const unsigned* a,
                                        unsigned b0, unsigned b1) {
    asm volatile(
        "mma.sync.aligned.m16n8k16.row.col.f32.f16.f16.f32 "
        "{%0,%1,%2,%3}, {%4,%5,%6,%7}, {%8,%9}, {%0,%1,%2,%3};"
        : "+f"(c[0]), "+f"(c[1]), "+f"(c[2]), "+f"(c[3])
        : "r"(a[0]), "r"(a[1]), "r"(a[2]), "r"(a[3]), "r"(b0), "r"(b1));
}
#define CP_ASYNC16(dst, src) \
    asm volatile("cp.async.cg.shared.global [%0], [%1], 16;" \
                 :: "r"(dst), "l"(src))
#define CP_COMMIT() asm volatile("cp.async.commit_group;" ::: "memory")
#define CP_WAIT0()  asm volatile("cp.async.wait_group 0;" ::: "memory")

#define SWZ(off)   ((off) ^ (((off) >> 3) & 0x70))   // 128B-row swizzle (A)
#define SWZ64(off) ((off) ^ (((off) >> 3) & 0x30))   // 64B-row swizzle (B)

__device__ __forceinline__ float hsig(float v)
{
    return fminf(fmaxf(0.2f * v + 0.5f, 0.f), 1.f);
}

// ---------------------------------------------------------------------------
// Prepack weights into permuted-N 8KB tiles (128 N-rows x 32 fp16, 64B rows,
// SWZ64). GEMM col n' reads original weight col (n'&3)*64 + (n'>>2).
// Tile order: per-step GEMM = [nb][kc]; fused = [kc][nb].
// ---------------------------------------------------------------------------
__device__ __forceinline__ void prepack_one(long idx, const float* __restrict__ W,
                                            __half* __restrict__ Bp, int Cin,
                                            int nch, int fused)
{
    int j = (int)(idx & 31);
    long r = idx >> 5;
    int nrow = (int)(r & 127);
    r >>= 7;
    int kc = (int)(r % nch);
    int nb = (int)(r / nch);
    int k = kc * 32 + j;
    int pos = k / Cin, c = k % Cin;
    int n = nb * 128 + nrow;                    // permuted column index
    int worig = ((n & 3) << 6) + (n >> 2);      // gate*64 + f
    float w = W[((long)pos * Cin + c) * NCH + worig];
    int inb = nrow * 64 + j * 2;
    int sw = SWZ64(inb);
    long tile = fused ? (long)(kc * 2 + nb) : (long)(nb * nch + kc);
    Bp[tile * 4096 + (sw >> 1)] = __float2half_rn(w);
}

// ---------------------------------------------------------------------------
// mega_setup: prepack + x transpose (halo zero-fill) + zero h1/hA1/hB1/hA2/hB2
// ---------------------------------------------------------------------------
#define MS_P0 909312L
#define MS_P1 12746752L               // + xp items (11,837,440)
#define MS_P2 18665472L               // + h1 uint4 (5,918,720)
#define MS_P3 19257344L               // + hA1 uint4 (591,872)
#define MS_P4 19849216L               // + hB1
#define MS_P5 20441088L               // + hA2
#define MS_P6 21032960L               // + hB2

__global__ void mega_setup(const float* __restrict__ x,
                           const float* __restrict__ W1, const float* __restrict__ U1,
                           const float* __restrict__ W2, const float* __restrict__ U2,
                           __half* __restrict__ B1x, __half* __restrict__ B1h,
                           __half* __restrict__ B2x, __half* __restrict__ B2h,
                           unsigned* __restrict__ xp,
                           uint4* __restrict__ zh1,
                           uint4* __restrict__ zhA1, uint4* __restrict__ zhB1,
                           uint4* __restrict__ zhA2, uint4* __restrict__ zhB2)
{
    long stride = (long)gridDim.x * blockDim.x;
    for (long idx = blockIdx.x * (long)blockDim.x + threadIdx.x; idx < MS_P6;
         idx += stride) {
        if (idx < MS_P0) {
            long i = idx;
            if (i < 204800)       prepack_one(i,          W1, B1x, 32, NC1X, 0);
            else if (i < 614400)  prepack_one(i - 204800, U1, B1h, 64, NC1H, 1);
            else if (i < 761856)  prepack_one(i - 614400, W2, B2x, 64, NC2, 0);
            else                  prepack_one(i - 761856, U2, B2h, 64, NC2, 1);
        } else if (idx < MS_P1) {
            long i = idx - MS_P0;
            int plane = (int)(i % PLANE);
            long cb = i / PLANE;               // bt*32 + ch
            int ch = (int)(cb & 31);
            long bt = cb >> 5;
            int y = plane / HR, xx = plane - y * HR;
            unsigned v = 0u;
            if (y >= 2 && y < 66 && xx >= 2 && xx < 66) {
                float f = x[(bt * HWP + (y - 2) * 64 + (xx - 2)) * 32 + ch];
                v = pack_hl(f);
            }
            xp[cb * PLANE + plane] = v;
        } else if (idx < MS_P2) {
            zh1[idx - MS_P1] = make_uint4(0u, 0u, 0u, 0u);
        } else if (idx < MS_P3) {
            zhA1[idx - MS_P2] = make_uint4(0u, 0u, 0u, 0u);
        } else if (idx < MS_P4) {
            zhB1[idx - MS_P3] = make_uint4(0u, 0u, 0u, 0u);
        } else if (idx < MS_P5) {
            zhA2[idx - MS_P4] = make_uint4(0u, 0u, 0u, 0u);
        } else {
            zhB2[idx - MS_P5] = make_uint4(0u, 0u, 0u, 0u);
        }
    }
}

// ---------------------------------------------------------------------------
// Per-timestep input GEMM conv. 256 threads, occ 2, CTA 128m x 128n,
// grid (2, 256). fp16x2 split. Folds bias in. Source plane bt = b*TT + t.
// z row = b*zstrb + zoff + pix.
// ---------------------------------------------------------------------------
template<int CIN, int KH, int NCHUNKS>
__global__ void __launch_bounds__(256, 2)
conv_step(const unsigned* __restrict__ src,
          const __half* __restrict__ Bpack,
          const float* __restrict__ bias,
          float* __restrict__ zout, long zstrb, long zoff, int t)
{
    extern __shared__ char smem[];
    const unsigned sb = smem_u32(smem);
    const int tid = threadIdx.x;
    const int lane = tid & 31, wid = tid >> 5;
    const int n_blk = blockIdx.x;          // 0..1
    const int m0 = blockIdx.y * 128;
    const int b = m0 >> 12;
    const int bt = b * TT + t;
    const int y0 = (m0 & 4095) >> 6;
    constexpr int pad = KH >> 1;
    constexpr int HOFF = 2 - pad;

    const unsigned sA0 = sb, sB0 = sb + 32768;

    const int pix = tid & 127;
    const int g = tid >> 7;                // 0/1: channels g*16..g*16+15
    const int prow = (y0 + (pix >> 6)) * HR + (pix & 63);

    const int mw = wid & 3, nw = wid >> 2;
    int offA[2], offB[4];
#pragma unroll
    for (int mf = 0; mf < 2; mf++)
        offA[mf] = (mw * 32 + mf * 16 + (lane & 15)) * 128 + (lane >> 4) * 16;
#pragma unroll
    for (int nf2 = 0; nf2 < 4; nf2++)
        offB[nf2] = (nw * 64 + nf2 * 16 + (lane >> 4) * 8 + (lane & 7)) * 64
                  + ((lane >> 3) & 1) * 16;

    float acc[16][4];
#pragma unroll
    for (int i = 0; i < 16; i++)
#pragma unroll
        for (int j = 0; j < 4; j++) acc[i][j] = 0.f;

    unsigned a[16];

    auto prefA = [&](int kc) {
        int k0 = kc * 32;
        int pos = k0 / CIN;
        int cb = k0 - pos * CIN;
        int ky = pos / KH, kx = pos - ky * KH;
        const unsigned* s = src + ((long)bt * CIN + cb + g * 16) * PLANE
                          + prow + (ky + HOFF) * HR + kx + HOFF;
#pragma unroll
        for (int r = 0; r < 16; r++) a[r] = __ldg(s + (long)r * PLANE);
    };

    auto cpB = [&](int kc, int s) {
        const char* gsrc = (const char*)(Bpack + ((long)n_blk * NCHUNKS + kc) * 4096)
                         + tid * 16;
        unsigned dst = sB0 + s * 8192 + tid * 16;
        CP_ASYNC16(dst, gsrc);
        CP_ASYNC16(dst + 4096, gsrc + 4096);
    };

    auto stageA = [&](int s) {
        unsigned hw[8], lw[8];
#pragma unroll
        for (int j = 0; j < 8; j++) {
            hw[j] = __byte_perm(a[2 * j], a[2 * j + 1], 0x5410);
            lw[j] = __byte_perm(a[2 * j], a[2 * j + 1], 0x7632);
        }
        char* Ab = smem + s * 16384;
        int rb = pix * 128 + g * 32;
#pragma unroll
        for (int q = 0; q < 2; q++) {
            *(uint4*)(Ab + SWZ(rb + q * 16)) =
                make_uint4(hw[q * 4], hw[q * 4 + 1], hw[q * 4 + 2], hw[q * 4 + 3]);
            *(uint4*)(Ab + SWZ(rb + 64 + q * 16)) =
                make_uint4(lw[q * 4], lw[q * 4 + 1], lw[q * 4 + 2], lw[q * 4 + 3]);
        }
    };

    prefA(0);
    cpB(0, 0);
    CP_COMMIT();
    stageA(0);
    CP_WAIT0();
    __syncthreads();

    for (int kt = 0; kt < NCHUNKS; kt++) {
        const int cur = kt & 1;
        const bool more = (kt + 1 < NCHUNKS);
        if (more) {
            prefA(kt + 1);
            cpB(kt + 1, cur ^ 1);
            CP_COMMIT();
        }

        const unsigned a_base = sA0 + cur * 16384;
        const unsigned b_base = sB0 + cur * 8192;
#pragma unroll
        for (int ks = 0; ks < 2; ks++) {
            unsigned bf[4][4];
#pragma unroll
            for (int nf2 = 0; nf2 < 4; nf2++)
                ldsm4(bf[nf2], b_base + SWZ64(offB[nf2] + ks * 32));
#pragma unroll
            for (int term = 0; term < 2; term++) {
                unsigned af[2][4];
                ldsm4(af[0], a_base + SWZ(offA[0] + term * 64 + ks * 32));
                ldsm4(af[1], a_base + SWZ(offA[1] + term * 64 + ks * 32));
#pragma unroll
                for (int nf2 = 0; nf2 < 4; nf2++) {
                    mma_f16(acc[nf2 * 2 + 0],     af[0], bf[nf2][0], bf[nf2][1]);
                    mma_f16(acc[nf2 * 2 + 1],     af[0], bf[nf2][2], bf[nf2][3]);
                    mma_f16(acc[8 + nf2 * 2 + 0], af[1], bf[nf2][0], bf[nf2][1]);
                    mma_f16(acc[8 + nf2 * 2 + 1], af[1], bf[nf2][2], bf[nf2][3]);
                }
            }
        }

        if (more) {
            stageA(cur ^ 1);
            CP_WAIT0();
        }
        __syncthreads();
    }

    // epilogue: + bias (permuted cols), write zout
    const long coff = (long)n_blk * 128 + nw * 64 + (lane & 3) * 2;
    float bb0[8], bb1[8];
#pragma unroll
    for (int nf = 0; nf < 8; nf++) {
        int col = (int)coff + nf * 8;
        bb0[nf] = __ldg(bias + ((col & 3) << 6) + (col >> 2));
        bb1[nf] = __ldg(bias + (((col + 1) & 3) << 6) + ((col + 1) >> 2));
    }
    const long zrow0 = (long)b * zstrb + zoff + (m0 & 4095);
#pragma unroll
    for (int mf = 0; mf < 2; mf++) {
        int ml = mw * 32 + mf * 16 + (lane >> 2);
        float* zr = zout + (zrow0 + ml) * NCH + coff;
#pragma unroll
        for (int nf = 0; nf < 8; nf++) {
            *(float2*)(zr + nf * 8) = make_float2(
                acc[mf * 8 + nf][0] + bb0[nf], acc[mf * 8 + nf][1] + bb1[nf]);
            *(float2*)(zr + nf * 8 + 8 * NCH) = make_float2(
                acc[mf * 8 + nf][2] + bb0[nf], acc[mf * 8 + nf][3] + bb1[nf]);
        }
    }
}

// ---------------------------------------------------------------------------
// FUSED recurrent step: U*h conv + z-add + LSTM gates. 256 threads, occ 2,
// CTA 128m x 128n (grid (2, 256)). h ping-pongs across steps. Register-gate
// epilogue via shfl-xor (permuted-N). z-add row = b*zstrb + zoff + pix.
// t0: h_{t-1}==0 -> skip GEMM, treat c as 0.
// ---------------------------------------------------------------------------
template<int KH, int NCHUNKS, int LAYER>
__global__ void __launch_bounds__(256, 2)
conv_fused(const unsigned* __restrict__ hin,
           const __half* __restrict__ Bpack,
           const float* __restrict__ zx, long zstrb, long zoff,
           float* __restrict__ cst,
           unsigned* __restrict__ hout,
           unsigned* __restrict__ h1seq,
           float* __restrict__ outp, int t, int t0)
{
    extern __shared__ char smem[];
    const unsigned sb = smem_u32(smem);
    const int tid = threadIdx.x;
    const int lane = tid & 31, wid = tid >> 5;
    const int n_blk = blockIdx.x;          // 0..1
    const int m0 = blockIdx.y * 128;
    const int b = m0 >> 12;
    const int y0 = (m0 & 4095) >> 6;
    constexpr int CIN = 64;
    constexpr int pad = KH >> 1;
    constexpr int HOFF = 2 - pad;

    const unsigned sA0 = sb, sB0 = sb + 32768;

    const int mw = wid & 3, nw = wid >> 2;

    float acc[16][4];
#pragma unroll
    for (int i = 0; i < 16; i++)
#pragma unroll
        for (int j = 0; j < 4; j++) acc[i][j] = 0.f;

    if (!t0) {
        const int pix = tid & 127;
        const int g = tid >> 7;
        const int prow = (y0 + (pix >> 6)) * HR + (pix & 63);

        int offA[2], offB[4];
#pragma unroll
        for (int mf = 0; mf < 2; mf++)
            offA[mf] = (mw * 32 + mf * 16 + (lane & 15)) * 128 + (lane >> 4) * 16;
#pragma unroll
        for (int nf2 = 0; nf2 < 4; nf2++)
            offB[nf2] = (nw * 64 + nf2 * 16 + (lane >> 4) * 8 + (lane & 7)) * 64
                      + ((lane >> 3) & 1) * 16;

        unsigned a[16];

        auto prefA = [&](int kc) {
            int k0 = kc * 32;
            int pos = k0 / CIN;
            int cb = k0 - pos * CIN;
            int ky = pos / KH, kx = pos - ky * KH;
            const unsigned* s = hin + ((long)b * CIN + cb + g * 16) * PLANE
                              + prow + (ky + HOFF) * HR + kx + HOFF;
#pragma unroll
            for (int r = 0; r < 16; r++) a[r] = __ldg(s + (long)r * PLANE);
        };

        auto cpB = [&](int kc, int s) {
            const char* gsrc = (const char*)(Bpack + ((long)kc * 2 + n_blk) * 4096)
                             + tid * 16;
            unsigned dst = sB0 + s * 8192 + tid * 16;
            CP_ASYNC16(dst, gsrc);
            CP_ASYNC16(dst + 4096, gsrc + 4096);
        };

        auto stageA = [&](int s) {
            unsigned hw[8], lw[8];
#pragma unroll
            for (int j = 0; j < 8; j++) {
                hw[j] = __byte_perm(a[2 * j], a[2 * j + 1], 0x5410);
                lw[j] = __byte_perm(a[2 * j], a[2 * j + 1], 0x7632);
            }
            char* Ab = smem + s * 16384;
            int rb = pix * 128 + g * 32;
#pragma unroll
            for (int q = 0; q < 2; q++) {
                *(uint4*)(Ab + SWZ(rb + q * 16)) =
                    make_uint4(hw[q * 4], hw[q * 4 + 1], hw[q * 4 + 2], hw[q * 4 + 3]);
                *(uint4*)(Ab + SWZ(rb + 64 + q * 16)) =
                    make_uint4(lw[q * 4], lw[q * 4 + 1], lw[q * 4 + 2], lw[q * 4 + 3]);
            }
        };

        prefA(0);
        cpB(0, 0);
        CP_COMMIT();
        stageA(0);
        CP_WAIT0();
        __syncthreads();

        for (int kt = 0; kt < NCHUNKS; kt++) {
            const int cur = kt & 1;
            const bool more = (kt + 1 < NCHUNKS);
            if (more) {
                prefA(kt + 1);
                cpB(kt + 1, cur ^ 1);
                CP_COMMIT();
            }

            const unsigned a_base = sA0 + cur * 16384;
            const unsigned b_base = sB0 + cur * 8192;
#pragma unroll
            for (int ks = 0; ks < 2; ks++) {
                unsigned bf[4][4];
#pragma unroll
                for (int nf2 = 0; nf2 < 4; nf2++)
                    ldsm4(bf[nf2], b_base + SWZ64(offB[nf2] + ks * 32));
#pragma unroll
                for (int term = 0; term < 2; term++) {
                    unsigned af[2][4];
                    ldsm4(af[0], a_base + SWZ(offA[0] + term * 64 + ks * 32));
                    ldsm4(af[1], a_base + SWZ(offA[1] + term * 64 + ks * 32));
#pragma unroll
                    for (int nf2 = 0; nf2 < 4; nf2++) {
                        mma_f16(acc[nf2 * 2 + 0],     af[0], bf[nf2][0], bf[nf2][1]);
                        mma_f16(acc[nf2 * 2 + 1],     af[0], bf[nf2][2], bf[nf2][3]);
                        mma_f16(acc[8 + nf2 * 2 + 0], af[1], bf[nf2][0], bf[nf2][1]);
                        mma_f16(acc[8 + nf2 * 2 + 1], af[1], bf[nf2][2], bf[nf2][3]);
                    }
                }
            }

            if (more) {
                stageA(cur ^ 1);
                CP_WAIT0();
            }
            __syncthreads();
        }
    }

    // ================= register-gate epilogue =================
    const float* za = zx + ((long)b * zstrb + zoff + (m0 & 4095)) * NCH;
    float* hs = (float*)smem;              // LAYER 2: [128][33] relu(h) staging
    const int q = lane & 3;
    const int rq = lane >> 2;
    const bool odd = (q & 1);
#pragma unroll
    for (int mf = 0; mf < 2; mf++) {
        const int rloc = mw * 32 + mf * 16 + rq;
#pragma unroll
        for (int nf = 0; nf < 8; nf++) {
            int coll = nw * 64 + nf * 8 + q * 2;
            int col = n_blk * 128 + coll;
            float2 w0 = *(const float2*)(za + (long)rloc * NCH + col);
            float2 w1 = *(const float2*)(za + (long)(rloc + 8) * NCH + col);
            float z0 = acc[mf * 8 + nf][0] + w0.x;
            float z1 = acc[mf * 8 + nf][1] + w0.y;
            float z2 = acc[mf * 8 + nf][2] + w1.x;
            float z3 = acc[mf * 8 + nf][3] + w1.y;
            float e0 = __shfl_xor_sync(0xFFFFFFFFu, z0, 1);
            float e1 = __shfl_xor_sync(0xFFFFFFFFu, z1, 1);
            float e2 = __shfl_xor_sync(0xFFFFFFFFu, z2, 1);
            float e3 = __shfl_xor_sync(0xFFFFFFFFu, z3, 1);
            float zi = odd ? e2 : z0;
            float zf = odd ? e3 : z1;
            float zc = odd ? z2 : e0;
            float zo = odd ? z3 : e1;
            int pixl = rloc + (odd ? 8 : 0);
            int f = col >> 2;
            int pixg = (m0 & 4095) + pixl;
            long cidx = ((long)b * FF + f) * HWP + pixg;
            float cold = t0 ? 0.f : cst[cidx];
            float cn = hsig(zf) * cold + hsig(zi) * tanhf(zc);
            float hn = hsig(zo) * tanhf(cn);
            cst[cidx] = cn;
            int y = pixg >> 6, xx = pixg & 63;
            int hoffpix = (y + 2) * HR + xx + 2;
            hout[((long)b * FF + f) * PLANE + hoffpix] = pack_hl(hn);
            if (LAYER == 1)
                h1seq[((long)(b * TT + t) * FF + f) * PLANE + hoffpix] =
                    pack_hl(fmaxf(hn, 0.f));
            else
                hs[pixl * 33 + (coll >> 2)] = fmaxf(hn, 0.f);
        }
    }
    if (LAYER == 2) {
        __syncthreads();
        float* ob = outp + ((long)(b * TT + t) * HWP + (m0 & 4095)) * FF
                  + n_blk * 32;
#pragma unroll
        for (int i = 0; i < 16; i++) {
            int e = i * 256 + tid;
            int pixl = e >> 5, fl = e & 31;
            ob[(long)pixl * FF + fl] = hs[pixl * 33 + fl];
        }
    }
}

// ---------------------------------------------------------------------------
extern "C" void kernel_launch(void* const* d_in, const int* in_sizes, int n_in,
                              void* d_out, int out_size)
{
    const float* x   = (const float*)d_in[0];
    const float* Wk1 = (const float*)d_in[1];
    const float* Uk1 = (const float*)d_in[2];
    const float* b1  = (const float*)d_in[3];
    const float* Wk2 = (const float*)d_in[4];
    const float* Uk2 = (const float*)d_in[5];
    const float* b2  = (const float*)d_in[6];
    float* out = (float*)d_out;

    float *zx, *zx2, *c1, *c2;
    unsigned *xp, *h1, *hA1, *hB1, *hA2, *hB2;
    __half *B1x, *B1h, *B2x, *B2h;
    cudaGetSymbolAddress((void**)&zx,  g_zx);
    cudaGetSymbolAddress((void**)&zx2, g_zx2);
    cudaGetSymbolAddress((void**)&xp,  g_xp);
    cudaGetSymbolAddress((void**)&h1,  g_h1);
    cudaGetSymbolAddress((void**)&hA1, g_hA1);
    cudaGetSymbolAddress((void**)&hB1, g_hB1);
    cudaGetSymbolAddress((void**)&hA2, g_hA2);
    cudaGetSymbolAddress((void**)&hB2, g_hB2);
    cudaGetSymbolAddress((void**)&c1,  g_c1);
    cudaGetSymbolAddress((void**)&c2,  g_c2);
    cudaGetSymbolAddress((void**)&B1x, g_B1x);
    cudaGetSymbolAddress((void**)&B1h, g_B1h);
    cudaGetSymbolAddress((void**)&B2x, g_B2x);
    cudaGetSymbolAddress((void**)&B2h, g_B2h);

    static int inited = 0;
    static cudaStream_t s2, s3;
    static cudaEvent_t evSetup, evX[TT], evL1[TT], evJoin;
    if (!inited) {
        cudaFuncSetAttribute(conv_step<32, 5, NC1X>,
                             cudaFuncAttributeMaxDynamicSharedMemorySize, SM_BIG);
        cudaFuncSetAttribute(conv_step<64, 3, NC2>,
                             cudaFuncAttributeMaxDynamicSharedMemorySize, SM_BIG);
        cudaFuncSetAttribute(conv_fused<5, NC1H, 1>,
                             cudaFuncAttributeMaxDynamicSharedMemorySize, SM_BIG);
        cudaFuncSetAttribute(conv_fused<3, NC2, 2>,
                             cudaFuncAttributeMaxDynamicSharedMemorySize, SM_BIG);
        cudaStreamCreateWithFlags(&s2, cudaStreamNonBlocking);
        cudaStreamCreateWithFlags(&s3, cudaStreamNonBlocking);
        cudaEventCreateWithFlags(&evSetup, cudaEventDisableTiming);
        for (int i = 0; i < TT; i++) {
            cudaEventCreateWithFlags(&evX[i], cudaEventDisableTiming);
            cudaEventCreateWithFlags(&evL1[i], cudaEventDisableTiming);
        }
        cudaEventCreateWithFlags(&evJoin, cudaEventDisableTiming);
        inited = 1;
    }

    const dim3 gridRec(2, M_TOTAL / 128); // (2, 256)

    // Stream 0: setup + L1 recurrent chain. Stream s3: per-step W1*x_t slices
    // (run ahead, fill idle capacity). Stream s2: W2*h1_t + L2 step per t.
    mega_setup<<<2048, 256>>>(x, Wk1, Uk1, Wk2, Uk2,
                              B1x, B1h, B2x, B2h,
                              xp, (uint4*)h1,
                              (uint4*)hA1, (uint4*)hB1,
                              (uint4*)hA2, (uint4*)hB2);
    cudaEventRecord(evSetup, 0);

    cudaStreamWaitEvent(s3, evSetup, 0);
    for (int t = 0; t < TT; t++) {
        conv_step<32, 5, NC1X><<<gridRec, 256, SM_BIG, s3>>>(
            xp, B1x, b1, zx, (long)TT * HWP, (long)t * HWP, t);
        cudaEventRecord(evX[t], s3);
    }

    for (int t = 0; t < TT; t++) {
        unsigned* hin1  = (t & 1) ? hB1 : hA1;
        unsigned* hout1 = (t & 1) ? hA1 : hB1;
        cudaStreamWaitEvent(0, evX[t], 0);
        conv_fused<5, NC1H, 1><<<gridRec, 256, SM_BIG>>>(
            hin1, B1h, zx, (long)TT * HWP, (long)t * HWP,
            c1, hout1, h1, nullptr, t, t == 0);
        cudaEventRecord(evL1[t], 0);

        cudaStreamWaitEvent(s2, evL1[t], 0);
        conv_step<64, 3, NC2><<<gridRec, 256, SM_BIG, s2>>>(
            h1, B2x, b2, zx2, (long)HWP, 0L, t);
        unsigned* hin2  = (t & 1) ? hB2 : hA2;
        unsigned* hout2 = (t & 1) ? hA2 : hB2;
        conv_fused<3, NC2, 2><<<gridRec, 256, SM_BIG, s2>>>(
            hin2, B2h, zx2, (long)HWP, 0L,
            c2, hout2, nullptr, out, t, t == 0);
    }

    cudaEventRecord(evJoin, s2);
    cudaStreamWaitEvent(0, evJoin, 0);
}

// round 16
// speedup vs baseline: 1.9810x; 1.4648x over previous
#include <cuda_runtime.h>
#include <cuda_fp16.h>
#include <math.h>

// Problem constants
#define BB 8
#define TT 10
#define HH 64
#define WW 64
#define HWP 4096           // H*W
#define FF 64
#define NCH 256            // 4*F
#define M_TOTAL (BB*HWP)   // 32768

// Planar halo layout: 2-pixel border on each side
#define HR 68
#define PLANE (HR*HR)      // 4624 per channel plane

// K chunk = 32 fp32 channels -> 32 fp16 cols in A (ah), 32 fp16 in B (bh)
#define NC1X 25            // layer1 x-part:  K=800  (25 taps x 32ch) /32
#define NC1H 50            // layer1 h-part:  K=1600 (25 x 64) /32
#define NC2  18            // layer2 x/h:     K=576  (9 x 64) /32

#define SM_SZ 32768        // A[2][8K] + B[2][8K] (both GEMM kernels)

// N-column permutation: GEMM column n' carries f = n'>>2, gate = n'&3.

// Scratch (static device globals; no allocation allowed)
// Activation planes are packed u32 = fp16(hi) | fp16(lo)<<16 (hi consumed;
// lo retained for a cheap revert to the split scheme if precision demands).
__device__ float    g_zx[(long)BB * TT * HWP * NCH];    // L1: W1*x + b1 (all t)
__device__ float    g_zx2[(long)M_TOTAL * NCH];         // L2: W2*h1_t + b2 (per t)
__device__ unsigned g_xp[(long)BB * TT * 32 * PLANE];   // x planar+halo packed
__device__ unsigned g_h1[(long)BB * TT * FF * PLANE];   // relu(h) seq L1, packed
__device__ unsigned g_hA1[(long)BB * FF * PLANE];       // L1 hidden ping
__device__ unsigned g_hB1[(long)BB * FF * PLANE];       // L1 hidden pong
__device__ unsigned g_hA2[(long)BB * FF * PLANE];       // L2 hidden ping
__device__ unsigned g_hB2[(long)BB * FF * PLANE];       // L2 hidden pong
__device__ float    g_c1[(long)BB * FF * HWP];          // L1 cell state
__device__ float    g_c2[(long)BB * FF * HWP];          // L2 cell state
__device__ __half g_B1x[(long)2 * NC1X * 4096];         // per-step GEMM [nb][kc]
__device__ __half g_B1h[(long)2 * NC1H * 4096];         // fused tiles   [kc][nb]
__device__ __half g_B2x[(long)2 * NC2 * 4096];          // per-step GEMM [nb][kc]
__device__ __half g_B2h[(long)2 * NC2 * 4096];          // fused tiles   [kc][nb]

// ---------------------------------------------------------------------------
// Helpers (sm_80-baseline PTX only — harness targets family-generic sm_103)
// ---------------------------------------------------------------------------
__device__ __forceinline__ unsigned smem_u32(const void* p) {
    unsigned r;
    asm("{ .reg .u64 t; cvta.to.shared.u64 t, %1; cvt.u32.u64 %0, t; }"
        : "=r"(r) : "l"(p));
    return r;
}
__device__ __forceinline__ unsigned pack_hl(float f) {
    __half h = __float2half_rn(f);
    float r = f - __half2float(h);
    return (unsigned)__half_as_ushort(h)
         | ((unsigned)__half_as_ushort(__float2half_rn(r)) << 16);
}
__device__ __forceinline__ void ldsm4(unsigned* r, unsigned addr) {
    asm volatile("ldmatrix.sync.aligned.m8n8.x4.shared.b16 {%0,%1,%2,%3}, [%4];"
                 : "=r"(r[0]), "=r"(r[1]), "=r"(r[2]), "=r"(r[3]) : "r"(addr));
}
__device__ __forceinline__ void mma_f16(float* c, const unsigned* a,
                                        unsigned b0, unsigned b1) {
    asm volatile(
        "mma.sync.aligned.m16n8k16.row.col.f32.f16.f16.f32 "
        "{%0,%1,%2,%3}, {%4,%5,%6,%7}, {%8,%9}, {%0,%1,%2,%3};"
        : "+f"(c[0]), "+f"(c[1]), "+f"(c[2]), "+f"(c[3])
        : "r"(a[0]), "r"(a[1]), "r"(a[2]), "r"(a[3]), "r"(b0), "r"(b1));
}
#define CP_ASYNC16(dst, src) \
    asm volatile("cp.async.cg.shared.global [%0], [%1], 16;" \
                 :: "r"(dst), "l"(src))
#define CP_COMMIT() asm volatile("cp.async.commit_group;" ::: "memory")
#define CP_WAIT0()  asm volatile("cp.async.wait_group 0;" ::: "memory")

#define SWZ64(off) ((off) ^ (((off) >> 3) & 0x30))   // 64B-row swizzle (A & B)

__device__ __forceinline__ float hsig(float v)
{
    return fminf(fmaxf(0.2f * v + 0.5f, 0.f), 1.f);
}

// ---------------------------------------------------------------------------
// Prepack weights into permuted-N 8KB tiles (128 N-rows x 32 fp16, 64B rows,
// SWZ64). GEMM col n' reads original weight col (n'&3)*64 + (n'>>2).
// Tile order: per-step GEMM = [nb][kc]; fused = [kc][nb].
// ---------------------------------------------------------------------------
__device__ __forceinline__ void prepack_one(long idx, const float* __restrict__ W,
                                            __half* __restrict__ Bp, int Cin,
                                            int nch, int fused)
{
    int j = (int)(idx & 31);
    long r = idx >> 5;
    int nrow = (int)(r & 127);
    r >>= 7;
    int kc = (int)(r % nch);
    int nb = (int)(r / nch);
    int k = kc * 32 + j;
    int pos = k / Cin, c = k % Cin;
    int n = nb * 128 + nrow;                    // permuted column index
    int worig = ((n & 3) << 6) + (n >> 2);      // gate*64 + f
    float w = W[((long)pos * Cin + c) * NCH + worig];
    int inb = nrow * 64 + j * 2;
    int sw = SWZ64(inb);
    long tile = fused ? (long)(kc * 2 + nb) : (long)(nb * nch + kc);
    Bp[tile * 4096 + (sw >> 1)] = __float2half_rn(w);
}

// ---------------------------------------------------------------------------
// mega_setup: prepack + x transpose (halo zero-fill) + zero h1/hA1/hB1/hA2/hB2
// ---------------------------------------------------------------------------
#define MS_P0 909312L
#define MS_P1 12746752L               // + xp items (11,837,440)
#define MS_P2 18665472L               // + h1 uint4 (5,918,720)
#define MS_P3 19257344L               // + hA1 uint4 (591,872)
#define MS_P4 19849216L               // + hB1
#define MS_P5 20441088L               // + hA2
#define MS_P6 21032960L               // + hB2

__global__ void mega_setup(const float* __restrict__ x,
                           const float* __restrict__ W1, const float* __restrict__ U1,
                           const float* __restrict__ W2, const float* __restrict__ U2,
                           __half* __restrict__ B1x, __half* __restrict__ B1h,
                           __half* __restrict__ B2x, __half* __restrict__ B2h,
                           unsigned* __restrict__ xp,
                           uint4* __restrict__ zh1,
                           uint4* __restrict__ zhA1, uint4* __restrict__ zhB1,
                           uint4* __restrict__ zhA2, uint4* __restrict__ zhB2)
{
    long stride = (long)gridDim.x * blockDim.x;
    for (long idx = blockIdx.x * (long)blockDim.x + threadIdx.x; idx < MS_P6;
         idx += stride) {
        if (idx < MS_P0) {
            long i = idx;
            if (i < 204800)       prepack_one(i,          W1, B1x, 32, NC1X, 0);
            else if (i < 614400)  prepack_one(i - 204800, U1, B1h, 64, NC1H, 1);
            else if (i < 761856)  prepack_one(i - 614400, W2, B2x, 64, NC2, 0);
            else                  prepack_one(i - 761856, U2, B2h, 64, NC2, 1);
        } else if (idx < MS_P1) {
            long i = idx - MS_P0;
            int plane = (int)(i % PLANE);
            long cb = i / PLANE;               // bt*32 + ch
            int ch = (int)(cb & 31);
            long bt = cb >> 5;
            int y = plane / HR, xx = plane - y * HR;
            unsigned v = 0u;
            if (y >= 2 && y < 66 && xx >= 2 && xx < 66) {
                float f = x[(bt * HWP + (y - 2) * 64 + (xx - 2)) * 32 + ch];
                v = pack_hl(f);
            }
            xp[cb * PLANE + plane] = v;
        } else if (idx < MS_P2) {
            zh1[idx - MS_P1] = make_uint4(0u, 0u, 0u, 0u);
        } else if (idx < MS_P3) {
            zhA1[idx - MS_P2] = make_uint4(0u, 0u, 0u, 0u);
        } else if (idx < MS_P4) {
            zhB1[idx - MS_P3] = make_uint4(0u, 0u, 0u, 0u);
        } else if (idx < MS_P5) {
            zhA2[idx - MS_P4] = make_uint4(0u, 0u, 0u, 0u);
        } else {
            zhB2[idx - MS_P5] = make_uint4(0u, 0u, 0u, 0u);
        }
    }
}

// ---------------------------------------------------------------------------
// Per-timestep input GEMM conv. 256 threads, occ 2, CTA 128m x 128n,
// grid (2, 256). fp16-single (ah*bh). Folds bias in. Source bt = b*TT + t.
// z row = b*zstrb + zoff + pix.
// A smem tile: 128 pix x 32 fp16 (64B rows, SWZ64), 8KB per stage.
// ---------------------------------------------------------------------------
template<int CIN, int KH, int NCHUNKS>
__global__ void __launch_bounds__(256, 2)
conv_step(const unsigned* __restrict__ src,
          const __half* __restrict__ Bpack,
          const float* __restrict__ bias,
          float* __restrict__ zout, long zstrb, long zoff, int t)
{
    extern __shared__ char smem[];
    const unsigned sb = smem_u32(smem);
    const int tid = threadIdx.x;
    const int lane = tid & 31, wid = tid >> 5;
    const int n_blk = blockIdx.x;          // 0..1
    const int m0 = blockIdx.y * 128;
    const int b = m0 >> 12;
    const int bt = b * TT + t;
    const int y0 = (m0 & 4095) >> 6;
    constexpr int pad = KH >> 1;
    constexpr int HOFF = 2 - pad;

    const unsigned sA0 = sb, sB0 = sb + 16384;

    const int pix = tid & 127;
    const int g = tid >> 7;                // 0/1: channels g*16..g*16+15
    const int prow = (y0 + (pix >> 6)) * HR + (pix & 63);

    const int mw = wid & 3, nw = wid >> 2;
    int offA[2], offB[4];
#pragma unroll
    for (int mf = 0; mf < 2; mf++)
        offA[mf] = (mw * 32 + mf * 16 + (lane & 15)) * 64 + (lane >> 4) * 16;
#pragma unroll
    for (int nf2 = 0; nf2 < 4; nf2++)
        offB[nf2] = (nw * 64 + nf2 * 16 + (lane >> 4) * 8 + (lane & 7)) * 64
                  + ((lane >> 3) & 1) * 16;

    float acc[16][4];
#pragma unroll
    for (int i = 0; i < 16; i++)
#pragma unroll
        for (int j = 0; j < 4; j++) acc[i][j] = 0.f;

    unsigned a[16];

    auto prefA = [&](int kc) {
        int k0 = kc * 32;
        int pos = k0 / CIN;
        int cb = k0 - pos * CIN;
        int ky = pos / KH, kx = pos - ky * KH;
        const unsigned* s = src + ((long)bt * CIN + cb + g * 16) * PLANE
                          + prow + (ky + HOFF) * HR + kx + HOFF;
#pragma unroll
        for (int r = 0; r < 16; r++) a[r] = __ldg(s + (long)r * PLANE);
    };

    auto cpB = [&](int kc, int s) {
        const char* gsrc = (const char*)(Bpack + ((long)n_blk * NCHUNKS + kc) * 4096)
                         + tid * 16;
        unsigned dst = sB0 + s * 8192 + tid * 16;
        CP_ASYNC16(dst, gsrc);
        CP_ASYNC16(dst + 4096, gsrc + 4096);
    };

    auto stageA = [&](int s) {
        unsigned hw[8];
#pragma unroll
        for (int j = 0; j < 8; j++)
            hw[j] = __byte_perm(a[2 * j], a[2 * j + 1], 0x5410);
        char* Ab = smem + s * 8192;
        int rb = pix * 64 + g * 32;
        *(uint4*)(Ab + SWZ64(rb)) =
            make_uint4(hw[0], hw[1], hw[2], hw[3]);
        *(uint4*)(Ab + SWZ64(rb + 16)) =
            make_uint4(hw[4], hw[5], hw[6], hw[7]);
    };

    prefA(0);
    cpB(0, 0);
    CP_COMMIT();
    stageA(0);
    CP_WAIT0();
    __syncthreads();

    for (int kt = 0; kt < NCHUNKS; kt++) {
        const int cur = kt & 1;
        const bool more = (kt + 1 < NCHUNKS);
        if (more) {
            prefA(kt + 1);
            cpB(kt + 1, cur ^ 1);
            CP_COMMIT();
        }

        const unsigned a_base = sA0 + cur * 8192;
        const unsigned b_base = sB0 + cur * 8192;
#pragma unroll
        for (int ks = 0; ks < 2; ks++) {
            unsigned bf[4][4];
#pragma unroll
            for (int nf2 = 0; nf2 < 4; nf2++)
                ldsm4(bf[nf2], b_base + SWZ64(offB[nf2] + ks * 32));
            unsigned af[2][4];
            ldsm4(af[0], a_base + SWZ64(offA[0] + ks * 32));
            ldsm4(af[1], a_base + SWZ64(offA[1] + ks * 32));
#pragma unroll
            for (int nf2 = 0; nf2 < 4; nf2++) {
                mma_f16(acc[nf2 * 2 + 0],     af[0], bf[nf2][0], bf[nf2][1]);
                mma_f16(acc[nf2 * 2 + 1],     af[0], bf[nf2][2], bf[nf2][3]);
                mma_f16(acc[8 + nf2 * 2 + 0], af[1], bf[nf2][0], bf[nf2][1]);
                mma_f16(acc[8 + nf2 * 2 + 1], af[1], bf[nf2][2], bf[nf2][3]);
            }
        }

        if (more) {
            stageA(cur ^ 1);
            CP_WAIT0();
        }
        __syncthreads();
    }

    // epilogue: + bias (permuted cols), write zout
    const long coff = (long)n_blk * 128 + nw * 64 + (lane & 3) * 2;
    float bb0[8], bb1[8];
#pragma unroll
    for (int nf = 0; nf < 8; nf++) {
        int col = (int)coff + nf * 8;
        bb0[nf] = __ldg(bias + ((col & 3) << 6) + (col >> 2));
        bb1[nf] = __ldg(bias + (((col + 1) & 3) << 6) + ((col + 1) >> 2));
    }
    const long zrow0 = (long)b * zstrb + zoff + (m0 & 4095);
#pragma unroll
    for (int mf = 0; mf < 2; mf++) {
        int ml = mw * 32 + mf * 16 + (lane >> 2);
        float* zr = zout + (zrow0 + ml) * NCH + coff;
#pragma unroll
        for (int nf = 0; nf < 8; nf++) {
            *(float2*)(zr + nf * 8) = make_float2(
                acc[mf * 8 + nf][0] + bb0[nf], acc[mf * 8 + nf][1] + bb1[nf]);
            *(float2*)(zr + nf * 8 + 8 * NCH) = make_float2(
                acc[mf * 8 + nf][2] + bb0[nf], acc[mf * 8 + nf][3] + bb1[nf]);
        }
    }
}

// ---------------------------------------------------------------------------
// FUSED recurrent step: U*h conv + z-add + LSTM gates. 256 threads, occ 2,
// CTA 128m x 128n (grid (2, 256)). h ping-pongs across steps. Register-gate
// epilogue via shfl-xor (permuted-N). z-add row = b*zstrb + zoff + pix.
// t0: h_{t-1}==0 -> skip GEMM, treat c as 0. fp16-single A.
// ---------------------------------------------------------------------------
template<int KH, int NCHUNKS, int LAYER>
__global__ void __launch_bounds__(256, 2)
conv_fused(const unsigned* __restrict__ hin,
           const __half* __restrict__ Bpack,
           const float* __restrict__ zx, long zstrb, long zoff,
           float* __restrict__ cst,
           unsigned* __restrict__ hout,
           unsigned* __restrict__ h1seq,
           float* __restrict__ outp, int t, int t0)
{
    extern __shared__ char smem[];
    const unsigned sb = smem_u32(smem);
    const int tid = threadIdx.x;
    const int lane = tid & 31, wid = tid >> 5;
    const int n_blk = blockIdx.x;          // 0..1
    const int m0 = blockIdx.y * 128;
    const int b = m0 >> 12;
    const int y0 = (m0 & 4095) >> 6;
    constexpr int CIN = 64;
    constexpr int pad = KH >> 1;
    constexpr int HOFF = 2 - pad;

    const unsigned sA0 = sb, sB0 = sb + 16384;

    const int mw = wid & 3, nw = wid >> 2;

    float acc[16][4];
#pragma unroll
    for (int i = 0; i < 16; i++)
#pragma unroll
        for (int j = 0; j < 4; j++) acc[i][j] = 0.f;

    if (!t0) {
        const int pix = tid & 127;
        const int g = tid >> 7;
        const int prow = (y0 + (pix >> 6)) * HR + (pix & 63);

        int offA[2], offB[4];
#pragma unroll
        for (int mf = 0; mf < 2; mf++)
            offA[mf] = (mw * 32 + mf * 16 + (lane & 15)) * 64 + (lane >> 4) * 16;
#pragma unroll
        for (int nf2 = 0; nf2 < 4; nf2++)
            offB[nf2] = (nw * 64 + nf2 * 16 + (lane >> 4) * 8 + (lane & 7)) * 64
                      + ((lane >> 3) & 1) * 16;

        unsigned a[16];

        auto prefA = [&](int kc) {
            int k0 = kc * 32;
            int pos = k0 / CIN;
            int cb = k0 - pos * CIN;
            int ky = pos / KH, kx = pos - ky * KH;
            const unsigned* s = hin + ((long)b * CIN + cb + g * 16) * PLANE
                              + prow + (ky + HOFF) * HR + kx + HOFF;
#pragma unroll
            for (int r = 0; r < 16; r++) a[r] = __ldg(s + (long)r * PLANE);
        };

        auto cpB = [&](int kc, int s) {
            const char* gsrc = (const char*)(Bpack + ((long)kc * 2 + n_blk) * 4096)
                             + tid * 16;
            unsigned dst = sB0 + s * 8192 + tid * 16;
            CP_ASYNC16(dst, gsrc);
            CP_ASYNC16(dst + 4096, gsrc + 4096);
        };

        auto stageA = [&](int s) {
            unsigned hw[8];
#pragma unroll
            for (int j = 0; j < 8; j++)
                hw[j] = __byte_perm(a[2 * j], a[2 * j + 1], 0x5410);
            char* Ab = smem + s * 8192;
            int rb = pix * 64 + g * 32;
            *(uint4*)(Ab + SWZ64(rb)) =
                make_uint4(hw[0], hw[1], hw[2], hw[3]);
            *(uint4*)(Ab + SWZ64(rb + 16)) =
                make_uint4(hw[4], hw[5], hw[6], hw[7]);
        };

        prefA(0);
        cpB(0, 0);
        CP_COMMIT();
        stageA(0);
        CP_WAIT0();
        __syncthreads();

        for (int kt = 0; kt < NCHUNKS; kt++) {
            const int cur = kt & 1;
            const bool more = (kt + 1 < NCHUNKS);
            if (more) {
                prefA(kt + 1);
                cpB(kt + 1, cur ^ 1);
                CP_COMMIT();
            }

            const unsigned a_base = sA0 + cur * 8192;
            const unsigned b_base = sB0 + cur * 8192;
#pragma unroll
            for (int ks = 0; ks < 2; ks++) {
                unsigned bf[4][4];
#pragma unroll
                for (int nf2 = 0; nf2 < 4; nf2++)
                    ldsm4(bf[nf2], b_base + SWZ64(offB[nf2] + ks * 32));
                unsigned af[2][4];
                ldsm4(af[0], a_base + SWZ64(offA[0] + ks * 32));
                ldsm4(af[1], a_base + SWZ64(offA[1] + ks * 32));
#pragma unroll
                for (int nf2 = 0; nf2 < 4; nf2++) {
                    mma_f16(acc[nf2 * 2 + 0],     af[0], bf[nf2][0], bf[nf2][1]);
                    mma_f16(acc[nf2 * 2 + 1],     af[0], bf[nf2][2], bf[nf2][3]);
                    mma_f16(acc[8 + nf2 * 2 + 0], af[1], bf[nf2][0], bf[nf2][1]);
                    mma_f16(acc[8 + nf2 * 2 + 1], af[1], bf[nf2][2], bf[nf2][3]);
                }
            }

            if (more) {
                stageA(cur ^ 1);
                CP_WAIT0();
            }
            __syncthreads();
        }
    }

    // ================= register-gate epilogue =================
    const float* za = zx + ((long)b * zstrb + zoff + (m0 & 4095)) * NCH;
    float* hs = (float*)smem;              // LAYER 2: [128][33] relu(h) staging
    const int q = lane & 3;
    const int rq = lane >> 2;
    const bool odd = (q & 1);
#pragma unroll
    for (int mf = 0; mf < 2; mf++) {
        const int rloc = mw * 32 + mf * 16 + rq;
#pragma unroll
        for (int nf = 0; nf < 8; nf++) {
            int coll = nw * 64 + nf * 8 + q * 2;
            int col = n_blk * 128 + coll;
            float2 w0 = *(const float2*)(za + (long)rloc * NCH + col);
            float2 w1 = *(const float2*)(za + (long)(rloc + 8) * NCH + col);
            float z0 = acc[mf * 8 + nf][0] + w0.x;
            float z1 = acc[mf * 8 + nf][1] + w0.y;
            float z2 = acc[mf * 8 + nf][2] + w1.x;
            float z3 = acc[mf * 8 + nf][3] + w1.y;
            float e0 = __shfl_xor_sync(0xFFFFFFFFu, z0, 1);
            float e1 = __shfl_xor_sync(0xFFFFFFFFu, z1, 1);
            float e2 = __shfl_xor_sync(0xFFFFFFFFu, z2, 1);
            float e3 = __shfl_xor_sync(0xFFFFFFFFu, z3, 1);
            float zi = odd ? e2 : z0;
            float zf = odd ? e3 : z1;
            float zc = odd ? z2 : e0;
            float zo = odd ? z3 : e1;
            int pixl = rloc + (odd ? 8 : 0);
            int f = col >> 2;
            int pixg = (m0 & 4095) + pixl;
            long cidx = ((long)b * FF + f) * HWP + pixg;
            float cold = t0 ? 0.f : cst[cidx];
            float cn = hsig(zf) * cold + hsig(zi) * tanhf(zc);
            float hn = hsig(zo) * tanhf(cn);
            cst[cidx] = cn;
            int y = pixg >> 6, xx = pixg & 63;
            int hoffpix = (y + 2) * HR + xx + 2;
            hout[((long)b * FF + f) * PLANE + hoffpix] = pack_hl(hn);
            if (LAYER == 1)
                h1seq[((long)(b * TT + t) * FF + f) * PLANE + hoffpix] =
                    pack_hl(fmaxf(hn, 0.f));
            else
                hs[pixl * 33 + (coll >> 2)] = fmaxf(hn, 0.f);
        }
    }
    if (LAYER == 2) {
        __syncthreads();
        float* ob = outp + ((long)(b * TT + t) * HWP + (m0 & 4095)) * FF
                  + n_blk * 32;
#pragma unroll
        for (int i = 0; i < 16; i++) {
            int e = i * 256 + tid;
            int pixl = e >> 5, fl = e & 31;
            ob[(long)pixl * FF + fl] = hs[pixl * 33 + fl];
        }
    }
}

// ---------------------------------------------------------------------------
extern "C" void kernel_launch(void* const* d_in, const int* in_sizes, int n_in,
                              void* d_out, int out_size)
{
    const float* x   = (const float*)d_in[0];
    const float* Wk1 = (const float*)d_in[1];
    const float* Uk1 = (const float*)d_in[2];
    const float* b1  = (const float*)d_in[3];
    const float* Wk2 = (const float*)d_in[4];
    const float* Uk2 = (const float*)d_in[5];
    const float* b2  = (const float*)d_in[6];
    float* out = (float*)d_out;

    float *zx, *zx2, *c1, *c2;
    unsigned *xp, *h1, *hA1, *hB1, *hA2, *hB2;
    __half *B1x, *B1h, *B2x, *B2h;
    cudaGetSymbolAddress((void**)&zx,  g_zx);
    cudaGetSymbolAddress((void**)&zx2, g_zx2);
    cudaGetSymbolAddress((void**)&xp,  g_xp);
    cudaGetSymbolAddress((void**)&h1,  g_h1);
    cudaGetSymbolAddress((void**)&hA1, g_hA1);
    cudaGetSymbolAddress((void**)&hB1, g_hB1);
    cudaGetSymbolAddress((void**)&hA2, g_hA2);
    cudaGetSymbolAddress((void**)&hB2, g_hB2);
    cudaGetSymbolAddress((void**)&c1,  g_c1);
    cudaGetSymbolAddress((void**)&c2,  g_c2);
    cudaGetSymbolAddress((void**)&B1x, g_B1x);
    cudaGetSymbolAddress((void**)&B1h, g_B1h);
    cudaGetSymbolAddress((void**)&B2x, g_B2x);
    cudaGetSymbolAddress((void**)&B2h, g_B2h);

    static int inited = 0;
    static cudaStream_t s2, s3;
    static cudaEvent_t evSetup, evX[TT], evL1[TT], evJoin;
    if (!inited) {
        cudaFuncSetAttribute(conv_step<32, 5, NC1X>,
                             cudaFuncAttributeMaxDynamicSharedMemorySize, SM_SZ);
        cudaFuncSetAttribute(conv_step<64, 3, NC2>,
                             cudaFuncAttributeMaxDynamicSharedMemorySize, SM_SZ);
        cudaFuncSetAttribute(conv_fused<5, NC1H, 1>,
                             cudaFuncAttributeMaxDynamicSharedMemorySize, SM_SZ);
        cudaFuncSetAttribute(conv_fused<3, NC2, 2>,
                             cudaFuncAttributeMaxDynamicSharedMemorySize, SM_SZ);
        cudaStreamCreateWithFlags(&s2, cudaStreamNonBlocking);
        cudaStreamCreateWithFlags(&s3, cudaStreamNonBlocking);
        cudaEventCreateWithFlags(&evSetup, cudaEventDisableTiming);
        for (int i = 0; i < TT; i++) {
            cudaEventCreateWithFlags(&evX[i], cudaEventDisableTiming);
            cudaEventCreateWithFlags(&evL1[i], cudaEventDisableTiming);
        }
        cudaEventCreateWithFlags(&evJoin, cudaEventDisableTiming);
        inited = 1;
    }

    const dim3 gridRec(2, M_TOTAL / 128); // (2, 256)

    // Stream 0: setup + L1 recurrent chain. Stream s3: per-step W1*x_t slices
    // (run ahead, fill idle capacity). Stream s2: W2*h1_t + L2 step per t.
    mega_setup<<<2048, 256>>>(x, Wk1, Uk1, Wk2, Uk2,
                              B1x, B1h, B2x, B2h,
                              xp, (uint4*)h1,
                              (uint4*)hA1, (uint4*)hB1,
                              (uint4*)hA2, (uint4*)hB2);
    cudaEventRecord(evSetup, 0);

    cudaStreamWaitEvent(s3, evSetup, 0);
    for (int t = 0; t < TT; t++) {
        conv_step<32, 5, NC1X><<<gridRec, 256, SM_SZ, s3>>>(
            xp, B1x, b1, zx, (long)TT * HWP, (long)t * HWP, t);
        cudaEventRecord(evX[t], s3);
    }

    for (int t = 0; t < TT; t++) {
        unsigned* hin1  = (t & 1) ? hB1 : hA1;
        unsigned* hout1 = (t & 1) ? hA1 : hB1;
        cudaStreamWaitEvent(0, evX[t], 0);
        conv_fused<5, NC1H, 1><<<gridRec, 256, SM_SZ>>>(
            hin1, B1h, zx, (long)TT * HWP, (long)t * HWP,
            c1, hout1, h1, nullptr, t, t == 0);
        cudaEventRecord(evL1[t], 0);

        cudaStreamWaitEvent(s2, evL1[t], 0);
        conv_step<64, 3, NC2><<<gridRec, 256, SM_SZ, s2>>>(
            h1, B2x, b2, zx2, (long)HWP, 0L, t);
        unsigned* hin2  = (t & 1) ? hB2 : hA2;
        unsigned* hout2 = (t & 1) ? hA2 : hB2;
        conv_fused<3, NC2, 2><<<gridRec, 256, SM_SZ, s2>>>(
            hin2, B2h, zx2, (long)HWP, 0L,
            c2, hout2, nullptr, out, t, t == 0);
    }

    cudaEventRecord(evJoin, s2);
    cudaStreamWaitEvent(0, evJoin, 0);
}

// round 17
// speedup vs baseline: 2.0959x; 1.0580x over previous
#include <cuda_runtime.h>
#include <cuda_fp16.h>
#include <math.h>

// Problem constants
#define BB 8
#define TT 10
#define HH 64
#define WW 64
#define HWP 4096           // H*W
#define FF 64
#define NCH 256            // 4*F
#define M_TOTAL (BB*HWP)   // 32768

// Planar halo layout: 2-pixel border on each side
#define HR 68
#define PLANE (HR*HR)      // 4624 per channel plane

// K chunk = 32 fp32 channels -> 32 fp16 cols in A (ah), 32 fp16 in B (bh)
#define NC1X 25            // layer1 x-part:  K=800  (25 taps x 32ch) /32
#define NC1H 50            // layer1 h-part:  K=1600 (25 x 64) /32
#define NC2  18            // layer2 x/h:     K=576  (9 x 64) /32

#define SM_SZ 32768        // A[2][8K] + B[2][8K]

// N-column permutation: GEMM column n' carries f = n'>>2, gate = n'&3.

// Scratch (static device globals; no allocation allowed)
// Activation planes are packed u32 = fp16(hi) | fp16(lo)<<16 (hi consumed).
__device__ float    g_zx[(long)BB * TT * HWP * NCH];    // L1: W1*x + b1 (all t)
__device__ unsigned g_xp[(long)BB * TT * 32 * PLANE];   // x planar+halo packed
__device__ unsigned g_h1[(long)BB * TT * FF * PLANE];   // relu(h) seq L1, packed
__device__ unsigned g_hA1[(long)BB * FF * PLANE];       // L1 hidden ping
__device__ unsigned g_hB1[(long)BB * FF * PLANE];       // L1 hidden pong
__device__ unsigned g_hA2[(long)BB * FF * PLANE];       // L2 hidden ping
__device__ unsigned g_hB2[(long)BB * FF * PLANE];       // L2 hidden pong
__device__ float    g_c1[(long)BB * FF * HWP];          // L1 cell state
__device__ float    g_c2[(long)BB * FF * HWP];          // L2 cell state
__device__ __half g_B1x[(long)2 * NC1X * 4096];         // per-step GEMM [nb][kc]
__device__ __half g_B1h[(long)2 * NC1H * 4096];         // fused tiles   [kc][nb]
__device__ __half g_B2x[(long)2 * NC2 * 4096];          // fused tiles   [kc][nb]
__device__ __half g_B2h[(long)2 * NC2 * 4096];          // fused tiles   [kc][nb]

// ---------------------------------------------------------------------------
// Helpers (sm_80-baseline PTX only — harness targets family-generic sm_103)
// ---------------------------------------------------------------------------
__device__ __forceinline__ unsigned smem_u32(const void* p) {
    unsigned r;
    asm("{ .reg .u64 t; cvta.to.shared.u64 t, %1; cvt.u32.u64 %0, t; }"
        : "=r"(r) : "l"(p));
    return r;
}
__device__ __forceinline__ unsigned pack_hl(float f) {
    __half h = __float2half_rn(f);
    float r = f - __half2float(h);
    return (unsigned)__half_as_ushort(h)
         | ((unsigned)__half_as_ushort(__float2half_rn(r)) << 16);
}
__device__ __forceinline__ void ldsm4(unsigned* r, unsigned addr) {
    asm volatile("ldmatrix.sync.aligned.m8n8.x4.shared.b16 {%0,%1,%2,%3}, [%4];"
                 : "=r"(r[0]), "=r"(r[1]), "=r"(r[2]), "=r"(r[3]) : "r"(addr));
}
__device__ __forceinline__ void mma_f16(float* c, const unsigned* a,
                                        unsigned b0, unsigned b1) {
    asm volatile(
        "mma.sync.aligned.m16n8k16.row.col.f32.f16.f16.f32 "
        "{%0,%1,%2,%3}, {%4,%5,%6,%7}, {%8,%9}, {%0,%1,%2,%3};"
        : "+f"(c[0]), "+f"(c[1]), "+f"(c[2]), "+f"(c[3])
        : "r"(a[0]), "r"(a[1]), "r"(a[2]), "r"(a[3]), "r"(b0), "r"(b1));
}
#define CP_ASYNC16(dst, src) \
    asm volatile("cp.async.cg.shared.global [%0], [%1], 16;" \
                 :: "r"(dst), "l"(src))
#define CP_COMMIT() asm volatile("cp.async.commit_group;" ::: "memory")
#define CP_WAIT0()  asm volatile("cp.async.wait_group 0;" ::: "memory")

#define SWZ64(off) ((off) ^ (((off) >> 3) & 0x30))   // 64B-row swizzle (A & B)

__device__ __forceinline__ float hsig(float v)
{
    return fminf(fmaxf(0.2f * v + 0.5f, 0.f), 1.f);
}

// ---------------------------------------------------------------------------
// Prepack weights into permuted-N 8KB tiles (128 N-rows x 32 fp16, 64B rows,
// SWZ64). GEMM col n' reads original weight col (n'&3)*64 + (n'>>2).
// Tile order: per-step L1x GEMM = [nb][kc]; all fused uses = [kc][nb].
// ---------------------------------------------------------------------------
__device__ __forceinline__ void prepack_one(long idx, const float* __restrict__ W,
                                            __half* __restrict__ Bp, int Cin,
                                            int nch, int fused)
{
    int j = (int)(idx & 31);
    long r = idx >> 5;
    int nrow = (int)(r & 127);
    r >>= 7;
    int kc = (int)(r % nch);
    int nb = (int)(r / nch);
    int k = kc * 32 + j;
    int pos = k / Cin, c = k % Cin;
    int n = nb * 128 + nrow;                    // permuted column index
    int worig = ((n & 3) << 6) + (n >> 2);      // gate*64 + f
    float w = W[((long)pos * Cin + c) * NCH + worig];
    int inb = nrow * 64 + j * 2;
    int sw = SWZ64(inb);
    long tile = fused ? (long)(kc * 2 + nb) : (long)(nb * nch + kc);
    Bp[tile * 4096 + (sw >> 1)] = __float2half_rn(w);
}

// ---------------------------------------------------------------------------
// mega_setup: prepack + x transpose (halo zero-fill) + zero h1/hA1/hB1/hA2/hB2
// ---------------------------------------------------------------------------
#define MS_P0 909312L
#define MS_P1 12746752L               // + xp items (11,837,440)
#define MS_P2 18665472L               // + h1 uint4 (5,918,720)
#define MS_P3 19257344L               // + hA1 uint4 (591,872)
#define MS_P4 19849216L               // + hB1
#define MS_P5 20441088L               // + hA2
#define MS_P6 21032960L               // + hB2

__global__ void mega_setup(const float* __restrict__ x,
                           const float* __restrict__ W1, const float* __restrict__ U1,
                           const float* __restrict__ W2, const float* __restrict__ U2,
                           __half* __restrict__ B1x, __half* __restrict__ B1h,
                           __half* __restrict__ B2x, __half* __restrict__ B2h,
                           unsigned* __restrict__ xp,
                           uint4* __restrict__ zh1,
                           uint4* __restrict__ zhA1, uint4* __restrict__ zhB1,
                           uint4* __restrict__ zhA2, uint4* __restrict__ zhB2)
{
    long stride = (long)gridDim.x * blockDim.x;
    for (long idx = blockIdx.x * (long)blockDim.x + threadIdx.x; idx < MS_P6;
         idx += stride) {
        if (idx < MS_P0) {
            long i = idx;
            if (i < 204800)       prepack_one(i,          W1, B1x, 32, NC1X, 0);
            else if (i < 614400)  prepack_one(i - 204800, U1, B1h, 64, NC1H, 1);
            else if (i < 761856)  prepack_one(i - 614400, W2, B2x, 64, NC2, 1);
            else                  prepack_one(i - 761856, U2, B2h, 64, NC2, 1);
        } else if (idx < MS_P1) {
            long i = idx - MS_P0;
            int plane = (int)(i % PLANE);
            long cb = i / PLANE;               // bt*32 + ch
            int ch = (int)(cb & 31);
            long bt = cb >> 5;
            int y = plane / HR, xx = plane - y * HR;
            unsigned v = 0u;
            if (y >= 2 && y < 66 && xx >= 2 && xx < 66) {
                float f = x[(bt * HWP + (y - 2) * 64 + (xx - 2)) * 32 + ch];
                v = pack_hl(f);
            }
            xp[cb * PLANE + plane] = v;
        } else if (idx < MS_P2) {
            zh1[idx - MS_P1] = make_uint4(0u, 0u, 0u, 0u);
        } else if (idx < MS_P3) {
            zhA1[idx - MS_P2] = make_uint4(0u, 0u, 0u, 0u);
        } else if (idx < MS_P4) {
            zhB1[idx - MS_P3] = make_uint4(0u, 0u, 0u, 0u);
        } else if (idx < MS_P5) {
            zhA2[idx - MS_P4] = make_uint4(0u, 0u, 0u, 0u);
        } else {
            zhB2[idx - MS_P5] = make_uint4(0u, 0u, 0u, 0u);
        }
    }
}

// ---------------------------------------------------------------------------
// Per-timestep L1 input GEMM. 256 threads, occ 2, CTA 128m x 128n,
// grid (2, 256). fp16-single (ah*bh). Folds bias in. Source bt = b*TT + t.
// ---------------------------------------------------------------------------
template<int CIN, int KH, int NCHUNKS>
__global__ void __launch_bounds__(256, 2)
conv_step(const unsigned* __restrict__ src,
          const __half* __restrict__ Bpack,
          const float* __restrict__ bias,
          float* __restrict__ zout, long zstrb, long zoff, int t)
{
    extern __shared__ char smem[];
    const unsigned sb = smem_u32(smem);
    const int tid = threadIdx.x;
    const int lane = tid & 31, wid = tid >> 5;
    const int n_blk = blockIdx.x;          // 0..1
    const int m0 = blockIdx.y * 128;
    const int b = m0 >> 12;
    const int bt = b * TT + t;
    const int y0 = (m0 & 4095) >> 6;
    constexpr int pad = KH >> 1;
    constexpr int HOFF = 2 - pad;

    const unsigned sA0 = sb, sB0 = sb + 16384;

    const int pix = tid & 127;
    const int g = tid >> 7;                // 0/1: channels g*16..g*16+15
    const int prow = (y0 + (pix >> 6)) * HR + (pix & 63);

    const int mw = wid & 3, nw = wid >> 2;
    int offA[2], offB[4];
#pragma unroll
    for (int mf = 0; mf < 2; mf++)
        offA[mf] = (mw * 32 + mf * 16 + (lane & 15)) * 64 + (lane >> 4) * 16;
#pragma unroll
    for (int nf2 = 0; nf2 < 4; nf2++)
        offB[nf2] = (nw * 64 + nf2 * 16 + (lane >> 4) * 8 + (lane & 7)) * 64
                  + ((lane >> 3) & 1) * 16;

    float acc[16][4];
#pragma unroll
    for (int i = 0; i < 16; i++)
#pragma unroll
        for (int j = 0; j < 4; j++) acc[i][j] = 0.f;

    unsigned a[16];

    auto prefA = [&](int kc) {
        int k0 = kc * 32;
        int pos = k0 / CIN;
        int cb = k0 - pos * CIN;
        int ky = pos / KH, kx = pos - ky * KH;
        const unsigned* s = src + ((long)bt * CIN + cb + g * 16) * PLANE
                          + prow + (ky + HOFF) * HR + kx + HOFF;
#pragma unroll
        for (int r = 0; r < 16; r++) a[r] = __ldg(s + (long)r * PLANE);
    };

    auto cpB = [&](int kc, int s) {
        const char* gsrc = (const char*)(Bpack + ((long)n_blk * NCHUNKS + kc) * 4096)
                         + tid * 16;
        unsigned dst = sB0 + s * 8192 + tid * 16;
        CP_ASYNC16(dst, gsrc);
        CP_ASYNC16(dst + 4096, gsrc + 4096);
    };

    auto stageA = [&](int s) {
        unsigned hw[8];
#pragma unroll
        for (int j = 0; j < 8; j++)
            hw[j] = __byte_perm(a[2 * j], a[2 * j + 1], 0x5410);
        char* Ab = smem + s * 8192;
        int rb = pix * 64 + g * 32;
        *(uint4*)(Ab + SWZ64(rb)) = make_uint4(hw[0], hw[1], hw[2], hw[3]);
        *(uint4*)(Ab + SWZ64(rb + 16)) = make_uint4(hw[4], hw[5], hw[6], hw[7]);
    };

    prefA(0);
    cpB(0, 0);
    CP_COMMIT();
    stageA(0);
    CP_WAIT0();
    __syncthreads();

    for (int kt = 0; kt < NCHUNKS; kt++) {
        const int cur = kt & 1;
        const bool more = (kt + 1 < NCHUNKS);
        if (more) {
            prefA(kt + 1);
            cpB(kt + 1, cur ^ 1);
            CP_COMMIT();
        }

        const unsigned a_base = sA0 + cur * 8192;
        const unsigned b_base = sB0 + cur * 8192;
#pragma unroll
        for (int ks = 0; ks < 2; ks++) {
            unsigned bf[4][4];
#pragma unroll
            for (int nf2 = 0; nf2 < 4; nf2++)
                ldsm4(bf[nf2], b_base + SWZ64(offB[nf2] + ks * 32));
            unsigned af[2][4];
            ldsm4(af[0], a_base + SWZ64(offA[0] + ks * 32));
            ldsm4(af[1], a_base + SWZ64(offA[1] + ks * 32));
#pragma unroll
            for (int nf2 = 0; nf2 < 4; nf2++) {
                mma_f16(acc[nf2 * 2 + 0],     af[0], bf[nf2][0], bf[nf2][1]);
                mma_f16(acc[nf2 * 2 + 1],     af[0], bf[nf2][2], bf[nf2][3]);
                mma_f16(acc[8 + nf2 * 2 + 0], af[1], bf[nf2][0], bf[nf2][1]);
                mma_f16(acc[8 + nf2 * 2 + 1], af[1], bf[nf2][2], bf[nf2][3]);
            }
        }

        if (more) {
            stageA(cur ^ 1);
            CP_WAIT0();
        }
        __syncthreads();
    }

    // epilogue: + bias (permuted cols), write zout
    const long coff = (long)n_blk * 128 + nw * 64 + (lane & 3) * 2;
    float bb0[8], bb1[8];
#pragma unroll
    for (int nf = 0; nf < 8; nf++) {
        int col = (int)coff + nf * 8;
        bb0[nf] = __ldg(bias + ((col & 3) << 6) + (col >> 2));
        bb1[nf] = __ldg(bias + (((col + 1) & 3) << 6) + ((col + 1) >> 2));
    }
    const long zrow0 = (long)b * zstrb + zoff + (m0 & 4095);
#pragma unroll
    for (int mf = 0; mf < 2; mf++) {
        int ml = mw * 32 + mf * 16 + (lane >> 2);
        float* zr = zout + (zrow0 + ml) * NCH + coff;
#pragma unroll
        for (int nf = 0; nf < 8; nf++) {
            *(float2*)(zr + nf * 8) = make_float2(
                acc[mf * 8 + nf][0] + bb0[nf], acc[mf * 8 + nf][1] + bb1[nf]);
            *(float2*)(zr + nf * 8 + 8 * NCH) = make_float2(
                acc[mf * 8 + nf][2] + bb0[nf], acc[mf * 8 + nf][3] + bb1[nf]);
        }
    }
}

// ---------------------------------------------------------------------------
// L1 FUSED recurrent step: U1*h conv + zx-add + LSTM gates. 256 threads,
// occ 2, CTA 128m x 128n (grid (2, 256)). Register-gate epilogue (shfl-xor).
// t0: skip GEMM, c=0.
// ---------------------------------------------------------------------------
template<int KH, int NCHUNKS>
__global__ void __launch_bounds__(256, 2)
conv_fused1(const unsigned* __restrict__ hin,
            const __half* __restrict__ Bpack,
            const float* __restrict__ zx,
            float* __restrict__ cst,
            unsigned* __restrict__ hout,
            unsigned* __restrict__ h1seq, int t, int t0)
{
    extern __shared__ char smem[];
    const unsigned sb = smem_u32(smem);
    const int tid = threadIdx.x;
    const int lane = tid & 31, wid = tid >> 5;
    const int n_blk = blockIdx.x;
    const int m0 = blockIdx.y * 128;
    const int b = m0 >> 12;
    const int y0 = (m0 & 4095) >> 6;
    constexpr int CIN = 64;
    constexpr int pad = KH >> 1;
    constexpr int HOFF = 2 - pad;

    const unsigned sA0 = sb, sB0 = sb + 16384;
    const int mw = wid & 3, nw = wid >> 2;

    float acc[16][4];
#pragma unroll
    for (int i = 0; i < 16; i++)
#pragma unroll
        for (int j = 0; j < 4; j++) acc[i][j] = 0.f;

    if (!t0) {
        const int pix = tid & 127;
        const int g = tid >> 7;
        const int prow = (y0 + (pix >> 6)) * HR + (pix & 63);

        int offA[2], offB[4];
#pragma unroll
        for (int mf = 0; mf < 2; mf++)
            offA[mf] = (mw * 32 + mf * 16 + (lane & 15)) * 64 + (lane >> 4) * 16;
#pragma unroll
        for (int nf2 = 0; nf2 < 4; nf2++)
            offB[nf2] = (nw * 64 + nf2 * 16 + (lane >> 4) * 8 + (lane & 7)) * 64
                      + ((lane >> 3) & 1) * 16;

        unsigned a[16];

        auto prefA = [&](int kc) {
            int k0 = kc * 32;
            int pos = k0 / CIN;
            int cb = k0 - pos * CIN;
            int ky = pos / KH, kx = pos - ky * KH;
            const unsigned* s = hin + ((long)b * CIN + cb + g * 16) * PLANE
                              + prow + (ky + HOFF) * HR + kx + HOFF;
#pragma unroll
            for (int r = 0; r < 16; r++) a[r] = __ldg(s + (long)r * PLANE);
        };

        auto cpB = [&](int kc, int s) {
            const char* gsrc = (const char*)(Bpack + ((long)kc * 2 + n_blk) * 4096)
                             + tid * 16;
            unsigned dst = sB0 + s * 8192 + tid * 16;
            CP_ASYNC16(dst, gsrc);
            CP_ASYNC16(dst + 4096, gsrc + 4096);
        };

        auto stageA = [&](int s) {
            unsigned hw[8];
#pragma unroll
            for (int j = 0; j < 8; j++)
                hw[j] = __byte_perm(a[2 * j], a[2 * j + 1], 0x5410);
            char* Ab = smem + s * 8192;
            int rb = pix * 64 + g * 32;
            *(uint4*)(Ab + SWZ64(rb)) = make_uint4(hw[0], hw[1], hw[2], hw[3]);
            *(uint4*)(Ab + SWZ64(rb + 16)) = make_uint4(hw[4], hw[5], hw[6], hw[7]);
        };

        prefA(0);
        cpB(0, 0);
        CP_COMMIT();
        stageA(0);
        CP_WAIT0();
        __syncthreads();

        for (int kt = 0; kt < NCHUNKS; kt++) {
            const int cur = kt & 1;
            const bool more = (kt + 1 < NCHUNKS);
            if (more) {
                prefA(kt + 1);
                cpB(kt + 1, cur ^ 1);
                CP_COMMIT();
            }

            const unsigned a_base = sA0 + cur * 8192;
            const unsigned b_base = sB0 + cur * 8192;
#pragma unroll
            for (int ks = 0; ks < 2; ks++) {
                unsigned bf[4][4];
#pragma unroll
                for (int nf2 = 0; nf2 < 4; nf2++)
                    ldsm4(bf[nf2], b_base + SWZ64(offB[nf2] + ks * 32));
                unsigned af[2][4];
                ldsm4(af[0], a_base + SWZ64(offA[0] + ks * 32));
                ldsm4(af[1], a_base + SWZ64(offA[1] + ks * 32));
#pragma unroll
                for (int nf2 = 0; nf2 < 4; nf2++) {
                    mma_f16(acc[nf2 * 2 + 0],     af[0], bf[nf2][0], bf[nf2][1]);
                    mma_f16(acc[nf2 * 2 + 1],     af[0], bf[nf2][2], bf[nf2][3]);
                    mma_f16(acc[8 + nf2 * 2 + 0], af[1], bf[nf2][0], bf[nf2][1]);
                    mma_f16(acc[8 + nf2 * 2 + 1], af[1], bf[nf2][2], bf[nf2][3]);
                }
            }

            if (more) {
                stageA(cur ^ 1);
                CP_WAIT0();
            }
            __syncthreads();
        }
    }

    // register-gate epilogue (adds zx tile)
    const float* za = zx + ((long)(b * TT + t) * HWP + (m0 & 4095)) * NCH;
    const int q = lane & 3;
    const int rq = lane >> 2;
    const bool odd = (q & 1);
#pragma unroll
    for (int mf = 0; mf < 2; mf++) {
        const int rloc = mw * 32 + mf * 16 + rq;
#pragma unroll
        for (int nf = 0; nf < 8; nf++) {
            int col = n_blk * 128 + nw * 64 + nf * 8 + q * 2;
            float2 w0 = *(const float2*)(za + (long)rloc * NCH + col);
            float2 w1 = *(const float2*)(za + (long)(rloc + 8) * NCH + col);
            float z0 = acc[mf * 8 + nf][0] + w0.x;
            float z1 = acc[mf * 8 + nf][1] + w0.y;
            float z2 = acc[mf * 8 + nf][2] + w1.x;
            float z3 = acc[mf * 8 + nf][3] + w1.y;
            float e0 = __shfl_xor_sync(0xFFFFFFFFu, z0, 1);
            float e1 = __shfl_xor_sync(0xFFFFFFFFu, z1, 1);
            float e2 = __shfl_xor_sync(0xFFFFFFFFu, z2, 1);
            float e3 = __shfl_xor_sync(0xFFFFFFFFu, z3, 1);
            float zi = odd ? e2 : z0;
            float zf = odd ? e3 : z1;
            float zc = odd ? z2 : e0;
            float zo = odd ? z3 : e1;
            int pixl = rloc + (odd ? 8 : 0);
            int f = col >> 2;
            int pixg = (m0 & 4095) + pixl;
            long cidx = ((long)b * FF + f) * HWP + pixg;
            float cold = t0 ? 0.f : cst[cidx];
            float cn = hsig(zf) * cold + hsig(zi) * tanhf(zc);
            float hn = hsig(zo) * tanhf(cn);
            cst[cidx] = cn;
            int y = pixg >> 6, xx = pixg & 63;
            int hoffpix = (y + 2) * HR + xx + 2;
            hout[((long)b * FF + f) * PLANE + hoffpix] = pack_hl(hn);
            h1seq[((long)(b * TT + t) * FF + f) * PLANE + hoffpix] =
                pack_hl(fmaxf(hn, 0.f));
        }
    }
}

// ---------------------------------------------------------------------------
// L2 MERGED step: (W2*h1_t + U2*h2 + b2) conv + LSTM gates + NHWC out, one
// kernel. Dual-source mainloop: chunks [0,NCX) read h1_t planes w/ Bx tiles;
// chunks [NCX, NCX+NCHH) read h2 w/ Bh tiles. t0: only the x-half, c=0.
// ---------------------------------------------------------------------------
template<int KH, int NCX, int NCHH>
__global__ void __launch_bounds__(256, 2)
conv_fused2(const unsigned* __restrict__ xsrc,   // h1 seq planes
            const unsigned* __restrict__ hin,    // h2 prev
            const __half* __restrict__ Bx,
            const __half* __restrict__ Bh,
            const float* __restrict__ bias,
            float* __restrict__ cst,
            unsigned* __restrict__ hout,
            float* __restrict__ outp, int t, int t0)
{
    extern __shared__ char smem[];
    const unsigned sb = smem_u32(smem);
    const int tid = threadIdx.x;
    const int lane = tid & 31, wid = tid >> 5;
    const int n_blk = blockIdx.x;
    const int m0 = blockIdx.y * 128;
    const int b = m0 >> 12;
    const int y0 = (m0 & 4095) >> 6;
    constexpr int CIN = 64;
    constexpr int pad = KH >> 1;
    constexpr int HOFF = 2 - pad;

    const unsigned sA0 = sb, sB0 = sb + 16384;
    const int mw = wid & 3, nw = wid >> 2;

    const int pix = tid & 127;
    const int g = tid >> 7;
    const int prow = (y0 + (pix >> 6)) * HR + (pix & 63);
    const unsigned* xbase = xsrc + (long)(b * TT + t) * CIN * PLANE;
    const unsigned* hbase = hin + (long)b * CIN * PLANE;

    int offA[2], offB[4];
#pragma unroll
    for (int mf = 0; mf < 2; mf++)
        offA[mf] = (mw * 32 + mf * 16 + (lane & 15)) * 64 + (lane >> 4) * 16;
#pragma unroll
    for (int nf2 = 0; nf2 < 4; nf2++)
        offB[nf2] = (nw * 64 + nf2 * 16 + (lane >> 4) * 8 + (lane & 7)) * 64
                  + ((lane >> 3) & 1) * 16;

    float acc[16][4];
#pragma unroll
    for (int i = 0; i < 16; i++)
#pragma unroll
        for (int j = 0; j < 4; j++) acc[i][j] = 0.f;

    unsigned a[16];
    const int NCT = t0 ? NCX : (NCX + NCHH);

    auto prefA = [&](int kt) {
        const unsigned* base = (kt < NCX) ? xbase : hbase;
        int kc = (kt < NCX) ? kt : (kt - NCX);
        int k0 = kc * 32;
        int pos = k0 / CIN;
        int cb = k0 - pos * CIN;
        int ky = pos / KH, kx = pos - ky * KH;
        const unsigned* s = base + (long)(cb + g * 16) * PLANE
                          + prow + (ky + HOFF) * HR + kx + HOFF;
#pragma unroll
        for (int r = 0; r < 16; r++) a[r] = __ldg(s + (long)r * PLANE);
    };

    auto cpB = [&](int kt, int s) {
        const __half* Bp = (kt < NCX) ? Bx : Bh;
        int kc = (kt < NCX) ? kt : (kt - NCX);
        const char* gsrc = (const char*)(Bp + ((long)kc * 2 + n_blk) * 4096)
                         + tid * 16;
        unsigned dst = sB0 + s * 8192 + tid * 16;
        CP_ASYNC16(dst, gsrc);
        CP_ASYNC16(dst + 4096, gsrc + 4096);
    };

    auto stageA = [&](int s) {
        unsigned hw[8];
#pragma unroll
        for (int j = 0; j < 8; j++)
            hw[j] = __byte_perm(a[2 * j], a[2 * j + 1], 0x5410);
        char* Ab = smem + s * 8192;
        int rb = pix * 64 + g * 32;
        *(uint4*)(Ab + SWZ64(rb)) = make_uint4(hw[0], hw[1], hw[2], hw[3]);
        *(uint4*)(Ab + SWZ64(rb + 16)) = make_uint4(hw[4], hw[5], hw[6], hw[7]);
    };

    prefA(0);
    cpB(0, 0);
    CP_COMMIT();
    stageA(0);
    CP_WAIT0();
    __syncthreads();

    for (int kt = 0; kt < NCT; kt++) {
        const int cur = kt & 1;
        const bool more = (kt + 1 < NCT);
        if (more) {
            prefA(kt + 1);
            cpB(kt + 1, cur ^ 1);
            CP_COMMIT();
        }

        const unsigned a_base = sA0 + cur * 8192;
        const unsigned b_base = sB0 + cur * 8192;
#pragma unroll
        for (int ks = 0; ks < 2; ks++) {
            unsigned bf[4][4];
#pragma unroll
            for (int nf2 = 0; nf2 < 4; nf2++)
                ldsm4(bf[nf2], b_base + SWZ64(offB[nf2] + ks * 32));
            unsigned af[2][4];
            ldsm4(af[0], a_base + SWZ64(offA[0] + ks * 32));
            ldsm4(af[1], a_base + SWZ64(offA[1] + ks * 32));
#pragma unroll
            for (int nf2 = 0; nf2 < 4; nf2++) {
                mma_f16(acc[nf2 * 2 + 0],     af[0], bf[nf2][0], bf[nf2][1]);
                mma_f16(acc[nf2 * 2 + 1],     af[0], bf[nf2][2], bf[nf2][3]);
                mma_f16(acc[8 + nf2 * 2 + 0], af[1], bf[nf2][0], bf[nf2][1]);
                mma_f16(acc[8 + nf2 * 2 + 1], af[1], bf[nf2][2], bf[nf2][3]);
            }
        }

        if (more) {
            stageA(cur ^ 1);
            CP_WAIT0();
        }
        __syncthreads();
    }

    // register-gate epilogue (adds bias only; no z buffer)
    float* hs = (float*)smem;              // [128][33] relu(h) staging
    const int q = lane & 3;
    const int rq = lane >> 2;
    const bool odd = (q & 1);
#pragma unroll
    for (int mf = 0; mf < 2; mf++) {
        const int rloc = mw * 32 + mf * 16 + rq;
#pragma unroll
        for (int nf = 0; nf < 8; nf++) {
            int coll = nw * 64 + nf * 8 + q * 2;
            int col = n_blk * 128 + coll;
            float bb0 = __ldg(bias + ((col & 3) << 6) + (col >> 2));
            float bb1 = __ldg(bias + (((col + 1) & 3) << 6) + ((col + 1) >> 2));
            float z0 = acc[mf * 8 + nf][0] + bb0;
            float z1 = acc[mf * 8 + nf][1] + bb1;
            float z2 = acc[mf * 8 + nf][2] + bb0;
            float z3 = acc[mf * 8 + nf][3] + bb1;
            float e0 = __shfl_xor_sync(0xFFFFFFFFu, z0, 1);
            float e1 = __shfl_xor_sync(0xFFFFFFFFu, z1, 1);
            float e2 = __shfl_xor_sync(0xFFFFFFFFu, z2, 1);
            float e3 = __shfl_xor_sync(0xFFFFFFFFu, z3, 1);
            float zi = odd ? e2 : z0;
            float zf = odd ? e3 : z1;
            float zc = odd ? z2 : e0;
            float zo = odd ? z3 : e1;
            int pixl = rloc + (odd ? 8 : 0);
            int f = col >> 2;
            int pixg = (m0 & 4095) + pixl;
            long cidx = ((long)b * FF + f) * HWP + pixg;
            float cold = t0 ? 0.f : cst[cidx];
            float cn = hsig(zf) * cold + hsig(zi) * tanhf(zc);
            float hn = hsig(zo) * tanhf(cn);
            cst[cidx] = cn;
            int y = pixg >> 6, xx = pixg & 63;
            int hoffpix = (y + 2) * HR + xx + 2;
            hout[((long)b * FF + f) * PLANE + hoffpix] = pack_hl(hn);
            hs[pixl * 33 + (coll >> 2)] = fmaxf(hn, 0.f);
        }
    }
    __syncthreads();
    float* ob = outp + ((long)(b * TT + t) * HWP + (m0 & 4095)) * FF + n_blk * 32;
#pragma unroll
    for (int i = 0; i < 16; i++) {
        int e = i * 256 + tid;
        int pixl = e >> 5, fl = e & 31;
        ob[(long)pixl * FF + fl] = hs[pixl * 33 + fl];
    }
}

// ---------------------------------------------------------------------------
extern "C" void kernel_launch(void* const* d_in, const int* in_sizes, int n_in,
                              void* d_out, int out_size)
{
    const float* x   = (const float*)d_in[0];
    const float* Wk1 = (const float*)d_in[1];
    const float* Uk1 = (const float*)d_in[2];
    const float* b1  = (const float*)d_in[3];
    const float* Wk2 = (const float*)d_in[4];
    const float* Uk2 = (const float*)d_in[5];
    const float* b2  = (const float*)d_in[6];
    float* out = (float*)d_out;

    float *zx, *c1, *c2;
    unsigned *xp, *h1, *hA1, *hB1, *hA2, *hB2;
    __half *B1x, *B1h, *B2x, *B2h;
    cudaGetSymbolAddress((void**)&zx,  g_zx);
    cudaGetSymbolAddress((void**)&xp,  g_xp);
    cudaGetSymbolAddress((void**)&h1,  g_h1);
    cudaGetSymbolAddress((void**)&hA1, g_hA1);
    cudaGetSymbolAddress((void**)&hB1, g_hB1);
    cudaGetSymbolAddress((void**)&hA2, g_hA2);
    cudaGetSymbolAddress((void**)&hB2, g_hB2);
    cudaGetSymbolAddress((void**)&c1,  g_c1);
    cudaGetSymbolAddress((void**)&c2,  g_c2);
    cudaGetSymbolAddress((void**)&B1x, g_B1x);
    cudaGetSymbolAddress((void**)&B1h, g_B1h);
    cudaGetSymbolAddress((void**)&B2x, g_B2x);
    cudaGetSymbolAddress((void**)&B2h, g_B2h);

    static int inited = 0;
    static cudaStream_t s1, s2, s3;   // s1 = high-priority chain stream
    static cudaEvent_t evSetup, evX[TT], evL1[TT], evJoin;
    if (!inited) {
        cudaFuncSetAttribute(conv_step<32, 5, NC1X>,
                             cudaFuncAttributeMaxDynamicSharedMemorySize, SM_SZ);
        cudaFuncSetAttribute(conv_fused1<5, NC1H>,
                             cudaFuncAttributeMaxDynamicSharedMemorySize, SM_SZ);
        cudaFuncSetAttribute(conv_fused2<3, NC2, NC2>,
                             cudaFuncAttributeMaxDynamicSharedMemorySize, SM_SZ);
        int loPri, hiPri;
        cudaDeviceGetStreamPriorityRange(&loPri, &hiPri);
        cudaStreamCreateWithPriority(&s1, cudaStreamNonBlocking, hiPri);
        cudaStreamCreateWithPriority(&s2, cudaStreamNonBlocking, loPri);
        cudaStreamCreateWithPriority(&s3, cudaStreamNonBlocking, loPri);
        cudaEventCreateWithFlags(&evSetup, cudaEventDisableTiming);
        for (int i = 0; i < TT; i++) {
            cudaEventCreateWithFlags(&evX[i], cudaEventDisableTiming);
            cudaEventCreateWithFlags(&evL1[i], cudaEventDisableTiming);
        }
        cudaEventCreateWithFlags(&evJoin, cudaEventDisableTiming);
        inited = 1;
    }

    const dim3 gridRec(2, M_TOTAL / 128); // (2, 256)

    // Stream s1 (high pri): L1 recurrent chain. s3 (low): W1*x_t slices.
    // s2 (low): merged L2 step (W2*h1_t + U2*h2 + gates + output).
    mega_setup<<<2048, 256>>>(x, Wk1, Uk1, Wk2, Uk2,
                              B1x, B1h, B2x, B2h,
                              xp, (uint4*)h1,
                              (uint4*)hA1, (uint4*)hB1,
                              (uint4*)hA2, (uint4*)hB2);
    cudaEventRecord(evSetup, 0);

    cudaStreamWaitEvent(s3, evSetup, 0);
    for (int t = 0; t < TT; t++) {
        conv_step<32, 5, NC1X><<<gridRec, 256, SM_SZ, s3>>>(
            xp, B1x, b1, zx, (long)TT * HWP, (long)t * HWP, t);
        cudaEventRecord(evX[t], s3);
    }

    cudaStreamWaitEvent(s1, evSetup, 0);
    for (int t = 0; t < TT; t++) {
        unsigned* hin1  = (t & 1) ? hB1 : hA1;
        unsigned* hout1 = (t & 1) ? hA1 : hB1;
        cudaStreamWaitEvent(s1, evX[t], 0);
        conv_fused1<5, NC1H><<<gridRec, 256, SM_SZ, s1>>>(
            hin1, B1h, zx, c1, hout1, h1, t, t == 0);
        cudaEventRecord(evL1[t], s1);

        cudaStreamWaitEvent(s2, evL1[t], 0);
        unsigned* hin2  = (t & 1) ? hB2 : hA2;
        unsigned* hout2 = (t & 1) ? hA2 : hB2;
        conv_fused2<3, NC2, NC2><<<gridRec, 256, SM_SZ, s2>>>(
            h1, hin2, B2x, B2h, b2, c2, hout2, out, t, t == 0);
    }

    cudaEventRecord(evJoin, s2);
    cudaStreamWaitEvent(0, evJoin, 0);
}